// round 8
// baseline (speedup 1.0000x reference)
#include <cuda_runtime.h>
#include <cuda_bf16.h>
#include <cstdint>
#include <cfloat>

#define NU 100000
#define NI 50000
#define DIM 128
#define EU 400000
#define EI 200000
#define BATCH 4096

#define NBI_G ((NI + 127) / 128)       // 391 gemm blocks (item)
#define NBU_G ((NU + 127) / 128)       // 782 gemm blocks (user)
#define NBI_SC ((NI + 1023) / 1024)    // 49 scan blocks (item)
#define NBU_SC ((NU + 1023) / 1024)    // 98 scan blocks (user)
#define AB2_I ((NI + 3) / 4)           // agg blocks (item), 4 dst/block
#define AB2_U ((NU + 3) / 4)           // agg blocks (user)

// ---------------- scratch (static device memory) ------------------------------
__device__ float g_h_u[NU * DIM];
__device__ float g_h_i[NI * DIM];
__device__ float g_out1_u[NU * DIM];
__device__ float g_out1_i[NI * DIM];
__device__ float g_uout2[NU * DIM];
__device__ float g_iout2[NI * DIM];
__device__ float g_ssrc_u[NU], g_sdst_u[NU];
__device__ float g_ssrc_i[NI], g_sdst_i[NI];
__device__ uint32_t g_wp_hi[4][DIM * 64];   // W^T [n][k-pair] bf16x2, hi part
__device__ uint32_t g_wp_lo[4][DIM * 64];   // residual lo part
// CSR (both graphs persist)
__device__ int   g_cnt_u[NU + 1], g_cnt_i[NI + 1];
__device__ int   g_off_u[NU + 1], g_off_i[NI + 1];
__device__ int   g_btot_u[NBU_SC], g_btot_i[NBI_SC];
__device__ int   g_work_u[NU], g_work_i[NI];
__device__ int2  g_ced_u[EU], g_ced_i[EI];  // packed (src, ev bits)

// ---------------- helpers ------------------------------------------------------
__device__ __forceinline__ float elu_f(float x) { return x > 0.f ? x : expm1f(x); }

__device__ __forceinline__ uint32_t pack_bf2(__nv_bfloat16 a, __nv_bfloat16 b) {
    return ((uint32_t)__bfloat16_as_ushort(b) << 16) | (uint32_t)__bfloat16_as_ushort(a);
}
__device__ __forceinline__ void mma_bf16(float* d, const uint32_t* a, const uint32_t* b) {
    asm volatile(
        "mma.sync.aligned.m16n8k16.row.col.f32.bf16.bf16.f32 "
        "{%0,%1,%2,%3}, {%4,%5,%6,%7}, {%8,%9}, {%0,%1,%2,%3};"
        : "+f"(d[0]), "+f"(d[1]), "+f"(d[2]), "+f"(d[3])
        : "r"(a[0]), "r"(a[1]), "r"(a[2]), "r"(a[3]), "r"(b[0]), "r"(b[1]));
}
__device__ __forceinline__ void ldsm_x4(uint32_t* r, uint32_t addr) {
    asm volatile("ldmatrix.sync.aligned.m8n8.x4.shared.b16 {%0,%1,%2,%3}, [%4];"
                 : "=r"(r[0]), "=r"(r[1]), "=r"(r[2]), "=r"(r[3]) : "r"(addr));
}
__device__ __forceinline__ void ldsm_x2(uint32_t* r, uint32_t addr) {
    asm volatile("ldmatrix.sync.aligned.m8n8.x2.shared.b16 {%0,%1}, [%2];"
                 : "=r"(r[0]), "=r"(r[1]) : "r"(addr));
}
__device__ __forceinline__ uint32_t smem_u32(const void* p) {
    return (uint32_t)__cvta_generic_to_shared(p);
}

// ---------------- W^T hi/lo prep (bf16 split, packed pairs) --------------------
__global__ void prep_w_kernel(const float* __restrict__ w0, const float* __restrict__ w1,
                              const float* __restrict__ w2, const float* __restrict__ w3) {
    int i = blockIdx.x * blockDim.x + threadIdx.x;     // 4*128*64
    int l = i >> 13;
    int j = i & 8191;
    int n = j >> 6, kk = j & 63;
    const float* W = (l == 0) ? w0 : (l == 1) ? w1 : (l == 2) ? w2 : w3;
    float a = W[(2 * kk) * DIM + n];
    float b = W[(2 * kk + 1) * DIM + n];
    __nv_bfloat16 ha = __float2bfloat16(a);
    __nv_bfloat16 hb = __float2bfloat16(b);
    __nv_bfloat16 la = __float2bfloat16(a - __bfloat162float(ha));
    __nv_bfloat16 lb = __float2bfloat16(b - __bfloat162float(hb));
    g_wp_hi[l][n * 64 + kk] = pack_bf2(ha, hb);
    g_wp_lo[l][n * 64 + kk] = pack_bf2(la, lb);
}

// ---------------- merged CSR build (both graphs per launch) --------------------
__global__ void zero_cnt_kernel() {
    int i = blockIdx.x * blockDim.x + threadIdx.x;
    if (i <= NU) g_cnt_u[i] = 0;
    if (i <= NI) g_cnt_i[i] = 0;
}
__global__ void count_kernel(const int* __restrict__ udst, const int* __restrict__ idst) {
    int e = blockIdx.x * blockDim.x + threadIdx.x;
    if (e < EU) atomicAdd(&g_cnt_u[udst[e]], 1);
    if (e < EI) atomicAdd(&g_cnt_i[idst[e]], 1);
}
__global__ void __launch_bounds__(1024) scan_a_kernel() {
    __shared__ int sm[1024];
    int t = threadIdx.x;
    int b = blockIdx.x;
    const int* cnt;  int* offs;  int* btot;  int N;  int lb;
    if (b < NBI_SC) { cnt = g_cnt_i; offs = g_off_i; btot = g_btot_i; N = NI; lb = b; }
    else            { cnt = g_cnt_u; offs = g_off_u; btot = g_btot_u; N = NU; lb = b - NBI_SC; }
    int i = lb * 1024 + t;
    int v = (i < N) ? cnt[i] : 0;
    sm[t] = v;
    __syncthreads();
#pragma unroll
    for (int s = 1; s < 1024; s <<= 1) {
        int u = (t >= s) ? sm[t - s] : 0;
        __syncthreads();
        sm[t] += u;
        __syncthreads();
    }
    if (i < N) offs[i] = sm[t] - v;
    if (t == 1023) btot[lb] = sm[1023];
}
__global__ void scan_b_kernel() {
    if (threadIdx.x == 0) {
        int run = 0;
        for (int b = 0; b < NBI_SC; ++b) { int t = g_btot_i[b]; g_btot_i[b] = run; run += t; }
        run = 0;
        for (int b = 0; b < NBU_SC; ++b) { int t = g_btot_u[b]; g_btot_u[b] = run; run += t; }
    }
}
__global__ void scan_c_kernel() {
    int i = blockIdx.x * blockDim.x + threadIdx.x;
    if (i < NI) {
        int o = g_off_i[i] + g_btot_i[i >> 10];
        g_off_i[i] = o;  g_work_i[i] = o;
    }
    if (i < NU) {
        int o = g_off_u[i] + g_btot_u[i >> 10];
        g_off_u[i] = o;  g_work_u[i] = o;
    }
    if (i == 0) { g_off_i[NI] = EI; g_off_u[NU] = EU; }
}
__global__ void scatter_kernel(const int* __restrict__ uedg, const float* __restrict__ uev,
                               const int* __restrict__ iedg, const float* __restrict__ iev) {
    int e = blockIdx.x * blockDim.x + threadIdx.x;
    if (e < EU) {
        int p = atomicAdd(&g_work_u[uedg[EU + e]], 1);
        g_ced_u[p] = make_int2(uedg[e], __float_as_int(uev[e]));
    }
    if (e < EI) {
        int p = atomicAdd(&g_work_i[iedg[EI + e]], 1);
        g_ced_i[p] = make_int2(iedg[e], __float_as_int(iev[e]));
    }
}

// ---------------- merged BF16 3-term HMMA GEMM + attention scalars -------------
struct GemmArgs {
    const float* x;
    const uint32_t *wh, *wl;
    const float *as, *ad;
    float *h, *ssrc, *sdst;
    int N;
};

// smem (bytes): B hi/lo [128n][68 u32], A hi/lo [128r][68 u32], red buf
#define SB_BH   0
#define SB_BL   34816
#define SB_AH   69632
#define SB_AL   104448
#define SB_RED  139264
#define SMEM_TOT 143360

template <int ACT>
__global__ void __launch_bounds__(256, 1) gemm_mma_kernel(GemmArgs gi, GemmArgs gu)
{
    extern __shared__ char smem[];
    uint32_t* Bh = (uint32_t*)(smem + SB_BH);
    uint32_t* Bl = (uint32_t*)(smem + SB_BL);
    uint32_t* Ah = (uint32_t*)(smem + SB_AH);
    uint32_t* Al = (uint32_t*)(smem + SB_AL);
    float* red_s = (float*)(smem + SB_RED);
    float* red_d = red_s + 128 * 4;

    const GemmArgs& g = (blockIdx.x < NBI_G) ? gi : gu;
    const int blk = (blockIdx.x < NBI_G) ? blockIdx.x : (blockIdx.x - NBI_G);
    const float* __restrict__ x = g.x;
    const int N = g.N;

    const int tid = threadIdx.x;
    const int lane = tid & 31;
    const int wid = tid >> 5;
    const int wm = wid & 1;
    const int wn = wid >> 1;
    const int r0 = blk * 128;

    // stage B (both hi and lo), uint4 copies into stride-68 layout
    for (int i = tid; i < 2048; i += 256) {
        int n = i >> 4, k4 = (i & 15) * 4;
        *(uint4*)&Bh[n * 68 + k4] = *(const uint4*)&g.wh[n * 64 + k4];
        *(uint4*)&Bl[n * 68 + k4] = *(const uint4*)&g.wl[n * 64 + k4];
    }

    // stage full A tile (128 rows x 128 k) with ELU + bf16 hi/lo split
    {
        const int r = tid >> 1;
        const int half = tid & 1;
        const bool ok = (r0 + r < N);
        const float* xr = x + (size_t)(r0 + r) * DIM + half * 64;
#pragma unroll
        for (int q = 0; q < 16; ++q) {
            float4 v = ok ? *(const float4*)(xr + q * 4) : make_float4(0.f, 0.f, 0.f, 0.f);
            if (ACT) { v.x = elu_f(v.x); v.y = elu_f(v.y); v.z = elu_f(v.z); v.w = elu_f(v.w); }
            __nv_bfloat16 hx = __float2bfloat16(v.x), hy = __float2bfloat16(v.y);
            __nv_bfloat16 hz = __float2bfloat16(v.z), hw = __float2bfloat16(v.w);
            __nv_bfloat16 lx = __float2bfloat16(v.x - __bfloat162float(hx));
            __nv_bfloat16 ly = __float2bfloat16(v.y - __bfloat162float(hy));
            __nv_bfloat16 lz = __float2bfloat16(v.z - __bfloat162float(hz));
            __nv_bfloat16 lw = __float2bfloat16(v.w - __bfloat162float(hw));
            int o = r * 68 + half * 32 + q * 2;
            Ah[o] = pack_bf2(hx, hy);  Ah[o + 1] = pack_bf2(hz, hw);
            Al[o] = pack_bf2(lx, ly);  Al[o + 1] = pack_bf2(lz, lw);
        }
    }
    __syncthreads();

    float acc[4][4][4];
#pragma unroll
    for (int mt = 0; mt < 4; ++mt)
#pragma unroll
        for (int nt = 0; nt < 4; ++nt)
#pragma unroll
            for (int q = 0; q < 4; ++q) acc[mt][nt][q] = 0.f;

    // ldmatrix per-lane address components (byte offsets within stride-68 u32 rows)
    const int selA = lane >> 3;                       // 0..3  -> (row+8?, khi?)
    const int rowA = (lane & 7) + (selA & 1) * 8;
    const int colA = (selA >> 1) * 4;                 // u32 words
    const int lane16 = lane & 15;
    const int rowB = lane16 & 7;
    const int colB = (lane16 >> 3) * 4;

    const uint32_t sAh = smem_u32(Ah), sAl = smem_u32(Al);
    const uint32_t sBh = smem_u32(Bh), sBl = smem_u32(Bl);

    uint32_t aoffm[4], boffn[4];
#pragma unroll
    for (int mt = 0; mt < 4; ++mt)
        aoffm[mt] = ((wm * 64 + mt * 16 + rowA) * 68 + colA) * 4;
#pragma unroll
    for (int nt = 0; nt < 4; ++nt)
        boffn[nt] = ((wn * 32 + nt * 8 + rowB) * 68 + colB) * 4;

#pragma unroll
    for (int ks = 0; ks < 8; ++ks) {
        const uint32_t ko = ks * 32;                  // 8 u32 words = 32 bytes
        uint32_t bh[4][2], bl[4][2];
#pragma unroll
        for (int nt = 0; nt < 4; ++nt) {
            ldsm_x2(bh[nt], sBh + boffn[nt] + ko);
            ldsm_x2(bl[nt], sBl + boffn[nt] + ko);
        }
        uint32_t ah[4][4], al[4][4];
#pragma unroll
        for (int mt = 0; mt < 4; ++mt) {
            ldsm_x4(ah[mt], sAh + aoffm[mt] + ko);
            ldsm_x4(al[mt], sAl + aoffm[mt] + ko);
        }
#pragma unroll
        for (int mt = 0; mt < 4; ++mt)
#pragma unroll
            for (int nt = 0; nt < 4; ++nt) {
                mma_bf16(acc[mt][nt], ah[mt], bh[nt]);
                mma_bf16(acc[mt][nt], ah[mt], bl[nt]);
                mma_bf16(acc[mt][nt], al[mt], bh[nt]);
            }
    }

    // ---------------- epilogue: store h + attention scalar dots ----------------
    float asv[4][2], adv[4][2];
#pragma unroll
    for (int nt = 0; nt < 4; ++nt) {
        int c0 = wn * 32 + nt * 8 + 2 * (lane & 3);
        asv[nt][0] = g.as[c0];   asv[nt][1] = g.as[c0 + 1];
        adv[nt][0] = g.ad[c0];   adv[nt][1] = g.ad[c0 + 1];
    }

    float ps[8], pd[8];
#pragma unroll
    for (int q = 0; q < 8; ++q) { ps[q] = 0.f; pd[q] = 0.f; }

    float* __restrict__ h = g.h;
#pragma unroll
    for (int mt = 0; mt < 4; ++mt) {
        int ar = r0 + wm * 64 + mt * 16 + (lane >> 2);
#pragma unroll
        for (int nt = 0; nt < 4; ++nt) {
            int c0 = wn * 32 + nt * 8 + 2 * (lane & 3);
            if (ar < N)
                *(float2*)(h + (size_t)ar * DIM + c0) = make_float2(acc[mt][nt][0], acc[mt][nt][1]);
            if (ar + 8 < N)
                *(float2*)(h + (size_t)(ar + 8) * DIM + c0) = make_float2(acc[mt][nt][2], acc[mt][nt][3]);
            ps[mt * 2 + 0] += acc[mt][nt][0] * asv[nt][0] + acc[mt][nt][1] * asv[nt][1];
            ps[mt * 2 + 1] += acc[mt][nt][2] * asv[nt][0] + acc[mt][nt][3] * asv[nt][1];
            pd[mt * 2 + 0] += acc[mt][nt][0] * adv[nt][0] + acc[mt][nt][1] * adv[nt][1];
            pd[mt * 2 + 1] += acc[mt][nt][2] * adv[nt][0] + acc[mt][nt][3] * adv[nt][1];
        }
    }
#pragma unroll
    for (int q = 0; q < 8; ++q) {
        ps[q] += __shfl_xor_sync(0xFFFFFFFF, ps[q], 1);
        ps[q] += __shfl_xor_sync(0xFFFFFFFF, ps[q], 2);
        pd[q] += __shfl_xor_sync(0xFFFFFFFF, pd[q], 1);
        pd[q] += __shfl_xor_sync(0xFFFFFFFF, pd[q], 2);
    }
    __syncthreads();
    if ((lane & 3) == 0) {
#pragma unroll
        for (int mt = 0; mt < 4; ++mt) {
            int rl0 = wm * 64 + mt * 16 + (lane >> 2);
            red_s[rl0 * 4 + wn] = ps[mt * 2 + 0];
            red_s[(rl0 + 8) * 4 + wn] = ps[mt * 2 + 1];
            red_d[rl0 * 4 + wn] = pd[mt * 2 + 0];
            red_d[(rl0 + 8) * 4 + wn] = pd[mt * 2 + 1];
        }
    }
    __syncthreads();
    if (tid < 128) {
        int row = r0 + tid;
        if (row < N) {
            float s = red_s[tid * 4] + red_s[tid * 4 + 1] + red_s[tid * 4 + 2] + red_s[tid * 4 + 3];
            float d = red_d[tid * 4] + red_d[tid * 4 + 1] + red_d[tid * 4 + 2] + red_d[tid * 4 + 3];
            g.ssrc[row] = s;
            g.sdst[row] = d;
        }
    }
}

// ---------------- merged CSR aggregate: 2 warps per dst (edge parity split) ----
struct AggArgs {
    const int* off;
    const int2* ced;
    const float *ssrc, *sdst, *h;
    float* out;
    int N;
};

__global__ void __launch_bounds__(256) agg_csr_kernel(AggArgs ai, AggArgs au)
{
    __shared__ float4 sacc[8][32];
    __shared__ float sden[8];
    const AggArgs& a = (blockIdx.x < AB2_I) ? ai : au;
    const int blk = (blockIdx.x < AB2_I) ? blockIdx.x : (blockIdx.x - AB2_I);
    const int tid = threadIdx.x;
    const int wid = tid >> 5, lane = tid & 31;
    const int slot = wid >> 1, half = wid & 1;
    const int d = blk * 4 + slot;

    float4 acc = make_float4(0.f, 0.f, 0.f, 0.f);
    float denom = 0.f;

    if (d < a.N) {
        const int o0 = a.off[d], o1 = a.off[d + 1];
        const float sd = a.sdst[d];
        const int deg = o1 - o0;
        const int cntw = (deg - half + 1) >> 1;       // this warp's edges: o0+half+2j
        const float* __restrict__ h = a.h;

        for (int base = 0; base < cntw; base += 32) {
            int j = base + lane;
            float e = 0.f;
            int s = 0;
            if (j < cntw) {
                int2 se = a.ced[o0 + half + 2 * j];
                s = se.x;
                float l = a.ssrc[s] + sd;
                l = l > 0.f ? l : 0.2f * l;
                e = __expf(l) * __int_as_float(se.y);
            }
            float es = e;
#pragma unroll
            for (int m = 16; m; m >>= 1) es += __shfl_xor_sync(0xFFFFFFFF, es, m);
            denom += es;

            int cnt = min(32, cntw - base);
            for (int k = 0; k < cnt; ++k) {
                float coef = __shfl_sync(0xFFFFFFFF, e, k);
                int sk = __shfl_sync(0xFFFFFFFF, s, k);
                float4 v = *(const float4*)(h + (size_t)sk * DIM + lane * 4);
                acc.x += coef * v.x; acc.y += coef * v.y;
                acc.z += coef * v.z; acc.w += coef * v.w;
            }
        }
    }
    sacc[wid][lane] = acc;
    if (lane == 0) sden[wid] = denom;
    __syncthreads();
    if (half == 0 && d < a.N) {
        float4 o = sacc[wid ^ 1][lane];
        float dn = denom + sden[wid ^ 1];
        acc.x += o.x; acc.y += o.y; acc.z += o.z; acc.w += o.w;
        float inv = 1.f / (dn + 1e-16f);
        acc.x *= inv; acc.y *= inv; acc.z *= inv; acc.w *= inv;
        *(float4*)(a.out + (size_t)d * DIM + lane * 4) = acc;
    }
}

// ---------------- final gather (deferred elu applied here) ----------------------
__global__ void gather_kernel(const float* __restrict__ uo, const float* __restrict__ io,
                              const int* __restrict__ uid, const int* __restrict__ iid,
                              float* __restrict__ out)
{
    int t = blockIdx.x * blockDim.x + threadIdx.x;
    int b = t >> 7, c = t & 127;
    if (b < BATCH)          out[t] = elu_f(uo[(size_t)uid[b] * DIM + c]);
    else if (b < 2 * BATCH) out[t] = elu_f(io[(size_t)iid[b - BATCH] * DIM + c]);
}

// ---------------- host orchestration -------------------------------------------
extern "C" void kernel_launch(void* const* d_in, const int* in_sizes, int n_in,
                              void* d_out, int out_size)
{
    const int*   uedg = (const int*)d_in[0];
    const int*   iedg = (const int*)d_in[1];
    const int*   user_id = (const int*)d_in[2];
    const int*   item_id = (const int*)d_in[3];
    const float* uval = (const float*)d_in[4];
    const float* ival = (const float*)d_in[5];
    const float* umat = (const float*)d_in[6];
    const float* imat = (const float*)d_in[7];
    const float* W_u1 = (const float*)d_in[8];
    const float* as_u1 = (const float*)d_in[9];
    const float* ad_u1 = (const float*)d_in[10];
    const float* W_u2 = (const float*)d_in[11];
    const float* as_u2 = (const float*)d_in[12];
    const float* ad_u2 = (const float*)d_in[13];
    const float* W_i1 = (const float*)d_in[14];
    const float* as_i1 = (const float*)d_in[15];
    const float* ad_i1 = (const float*)d_in[16];
    const float* W_i2 = (const float*)d_in[17];
    const float* as_i2 = (const float*)d_in[18];
    const float* ad_i2 = (const float*)d_in[19];

    float *h_u, *h_i, *out1_u, *out1_i, *uout2, *iout2;
    float *ssrc_u, *sdst_u, *ssrc_i, *sdst_i;
    uint32_t *wph, *wpl;
    int *off_u, *off_i;
    int2 *ced_u, *ced_i;
    cudaGetSymbolAddress((void**)&h_u, g_h_u);
    cudaGetSymbolAddress((void**)&h_i, g_h_i);
    cudaGetSymbolAddress((void**)&out1_u, g_out1_u);
    cudaGetSymbolAddress((void**)&out1_i, g_out1_i);
    cudaGetSymbolAddress((void**)&uout2, g_uout2);
    cudaGetSymbolAddress((void**)&iout2, g_iout2);
    cudaGetSymbolAddress((void**)&ssrc_u, g_ssrc_u);
    cudaGetSymbolAddress((void**)&sdst_u, g_sdst_u);
    cudaGetSymbolAddress((void**)&ssrc_i, g_ssrc_i);
    cudaGetSymbolAddress((void**)&sdst_i, g_sdst_i);
    cudaGetSymbolAddress((void**)&wph, g_wp_hi);
    cudaGetSymbolAddress((void**)&wpl, g_wp_lo);
    cudaGetSymbolAddress((void**)&off_u, g_off_u);
    cudaGetSymbolAddress((void**)&off_i, g_off_i);
    cudaGetSymbolAddress((void**)&ced_u, g_ced_u);
    cudaGetSymbolAddress((void**)&ced_i, g_ced_i);

    cudaFuncSetAttribute(gemm_mma_kernel<0>, cudaFuncAttributeMaxDynamicSharedMemorySize, SMEM_TOT);
    cudaFuncSetAttribute(gemm_mma_kernel<1>, cudaFuncAttributeMaxDynamicSharedMemorySize, SMEM_TOT);

    // one-time side-stream + events (resources only; work per call is identical)
    static cudaStream_t s2 = nullptr;
    static cudaEvent_t evF = nullptr, evC = nullptr;
    if (!s2) {
        cudaStreamCreateWithFlags(&s2, cudaStreamNonBlocking);
        cudaEventCreateWithFlags(&evF, cudaEventDisableTiming);
        cudaEventCreateWithFlags(&evC, cudaEventDisableTiming);
    }

    const int TB = 256;
    const int WSTRIDE = DIM * 64;

    // fork: CSR build on side stream, overlapped with prep + GEMM1
    cudaEventRecord(evF, 0);
    cudaStreamWaitEvent(s2, evF, 0);

    zero_cnt_kernel<<<(NU + TB) / TB, TB, 0, s2>>>();
    count_kernel<<<(EU + TB - 1) / TB, TB, 0, s2>>>(uedg + EU, iedg + EI);
    scan_a_kernel<<<NBI_SC + NBU_SC, 1024, 0, s2>>>();
    scan_b_kernel<<<1, 32, 0, s2>>>();
    scan_c_kernel<<<(NU + TB - 1) / TB, TB, 0, s2>>>();
    scatter_kernel<<<(EU + TB - 1) / TB, TB, 0, s2>>>(uedg, uval, iedg, ival);
    cudaEventRecord(evC, s2);

    // main stream: weight prep + layer-1 GEMM (independent of CSR)
    prep_w_kernel<<<4 * DIM * 64 / TB, TB>>>(W_i1, W_i2, W_u1, W_u2);

    GemmArgs gi1 = { imat, wph + 0 * WSTRIDE, wpl + 0 * WSTRIDE, as_i1, ad_i1,
                     h_i, ssrc_i, sdst_i, NI };
    GemmArgs gu1 = { umat, wph + 2 * WSTRIDE, wpl + 2 * WSTRIDE, as_u1, ad_u1,
                     h_u, ssrc_u, sdst_u, NU };
    gemm_mma_kernel<0><<<NBI_G + NBU_G, 256, SMEM_TOT>>>(gi1, gu1);

    // join: agg needs the CSR
    cudaStreamWaitEvent(0, evC, 0);

    AggArgs ai1 = { off_i, ced_i, ssrc_i, sdst_i, h_i, out1_i, NI };
    AggArgs au1 = { off_u, ced_u, ssrc_u, sdst_u, h_u, out1_u, NU };
    agg_csr_kernel<<<AB2_I + AB2_U, 256>>>(ai1, au1);

    // ---- layer 2 (both graphs merged) ----
    GemmArgs gi2 = { out1_i, wph + 1 * WSTRIDE, wpl + 1 * WSTRIDE, as_i2, ad_i2,
                     h_i, ssrc_i, sdst_i, NI };
    GemmArgs gu2 = { out1_u, wph + 3 * WSTRIDE, wpl + 3 * WSTRIDE, as_u2, ad_u2,
                     h_u, ssrc_u, sdst_u, NU };
    gemm_mma_kernel<1><<<NBI_G + NBU_G, 256, SMEM_TOT>>>(gi2, gu2);

    AggArgs ai2 = { off_i, ced_i, ssrc_i, sdst_i, h_i, iout2, NI };
    AggArgs au2 = { off_u, ced_u, ssrc_u, sdst_u, h_u, uout2, NU };
    agg_csr_kernel<<<AB2_I + AB2_U, 256>>>(ai2, au2);

    gather_kernel<<<(2 * BATCH * DIM) / TB, TB>>>(uout2, iout2, user_id, item_id, (float*)d_out);
}

// round 9
// speedup vs baseline: 1.2306x; 1.2306x over previous
#include <cuda_runtime.h>
#include <cuda_bf16.h>
#include <cstdint>
#include <cfloat>

#define NU 100000
#define NI 50000
#define DIM 128
#define EU 400000
#define EI 200000
#define BATCH 4096

#define NBI_G ((NI + 127) / 128)       // 391 gemm blocks (item)
#define NBU_G ((NU + 127) / 128)       // 782 gemm blocks (user)
#define NBI_SC ((NI + 1023) / 1024)    // 49 scan blocks (item)
#define NBU_SC ((NU + 1023) / 1024)    // 98 scan blocks (user)
#define AB_I ((NI + 7) / 8)            // agg blocks (item)
#define AB_U ((NU + 7) / 8)            // agg blocks (user)

// ---------------- scratch (static device memory) ------------------------------
__device__ float g_h_u[NU * DIM];
__device__ float g_h_i[NI * DIM];
__device__ float g_out1_u[NU * DIM];
__device__ float g_out1_i[NI * DIM];
__device__ float g_uout2[NU * DIM];
__device__ float g_iout2[NI * DIM];
__device__ float g_ssrc_u[NU], g_sdst_u[NU];
__device__ float g_ssrc_i[NI], g_sdst_i[NI];
__device__ uint32_t g_wp_hi[4][DIM * 64];   // W^T [n][k-pair] bf16x2, hi part
__device__ uint32_t g_wp_lo[4][DIM * 64];   // residual lo part
// CSR (both graphs persist)
__device__ int   g_cnt_u[NU + 1], g_cnt_i[NI + 1];
__device__ int   g_off_u[NU + 1], g_off_i[NI + 1];
__device__ int   g_btot_u[NBU_SC], g_btot_i[NBI_SC];
__device__ int   g_work_u[NU], g_work_i[NI];
__device__ int   g_csrc_u[EU], g_csrc_i[EI];
__device__ float g_cev_u[EU],  g_cev_i[EI];

// ---------------- helpers ------------------------------------------------------
__device__ __forceinline__ float elu_f(float x) {
    return x > 0.f ? x : __expf(x) - 1.f;
}
__device__ __forceinline__ uint32_t pack_bf2(__nv_bfloat16 a, __nv_bfloat16 b) {
    return ((uint32_t)__bfloat16_as_ushort(b) << 16) | (uint32_t)__bfloat16_as_ushort(a);
}
__device__ __forceinline__ uint32_t cvt_bf2(float lo0, float lo1) {
    uint32_t r;                       // lower half = lo0, upper = lo1
    asm("cvt.rn.bf16x2.f32 %0, %1, %2;" : "=r"(r) : "f"(lo1), "f"(lo0));
    return r;
}
__device__ __forceinline__ void mma_bf16(float* d, const uint32_t* a, const uint32_t* b) {
    asm volatile(
        "mma.sync.aligned.m16n8k16.row.col.f32.bf16.bf16.f32 "
        "{%0,%1,%2,%3}, {%4,%5,%6,%7}, {%8,%9}, {%0,%1,%2,%3};"
        : "+f"(d[0]), "+f"(d[1]), "+f"(d[2]), "+f"(d[3])
        : "r"(a[0]), "r"(a[1]), "r"(a[2]), "r"(a[3]), "r"(b[0]), "r"(b[1]));
}

// ---------------- W^T hi/lo prep (bf16 split, packed pairs) --------------------
__global__ void prep_w_kernel(const float* __restrict__ w0, const float* __restrict__ w1,
                              const float* __restrict__ w2, const float* __restrict__ w3) {
    int i = blockIdx.x * blockDim.x + threadIdx.x;     // 4*128*64
    int l = i >> 13;
    int j = i & 8191;
    int n = j >> 6, kk = j & 63;
    const float* W = (l == 0) ? w0 : (l == 1) ? w1 : (l == 2) ? w2 : w3;
    float a = W[(2 * kk) * DIM + n];
    float b = W[(2 * kk + 1) * DIM + n];
    __nv_bfloat16 ha = __float2bfloat16(a);
    __nv_bfloat16 hb = __float2bfloat16(b);
    __nv_bfloat16 la = __float2bfloat16(a - __bfloat162float(ha));
    __nv_bfloat16 lb = __float2bfloat16(b - __bfloat162float(hb));
    g_wp_hi[l][n * 64 + kk] = pack_bf2(ha, hb);
    g_wp_lo[l][n * 64 + kk] = pack_bf2(la, lb);
}

// ---------------- merged CSR build (both graphs per launch) --------------------
__global__ void zero_cnt_kernel() {
    int i = blockIdx.x * blockDim.x + threadIdx.x;
    if (i <= NU) g_cnt_u[i] = 0;
    if (i <= NI) g_cnt_i[i] = 0;
}
__global__ void count_kernel(const int* __restrict__ udst, const int* __restrict__ idst) {
    int e = blockIdx.x * blockDim.x + threadIdx.x;
    if (e < EU) atomicAdd(&g_cnt_u[udst[e]], 1);
    if (e < EI) atomicAdd(&g_cnt_i[idst[e]], 1);
}
__global__ void __launch_bounds__(1024) scan_a_kernel() {
    __shared__ int sm[1024];
    int t = threadIdx.x;
    int b = blockIdx.x;
    const int* cnt;  int* offs;  int* btot;  int N;  int lb;
    if (b < NBI_SC) { cnt = g_cnt_i; offs = g_off_i; btot = g_btot_i; N = NI; lb = b; }
    else            { cnt = g_cnt_u; offs = g_off_u; btot = g_btot_u; N = NU; lb = b - NBI_SC; }
    int i = lb * 1024 + t;
    int v = (i < N) ? cnt[i] : 0;
    sm[t] = v;
    __syncthreads();
#pragma unroll
    for (int s = 1; s < 1024; s <<= 1) {
        int u = (t >= s) ? sm[t - s] : 0;
        __syncthreads();
        sm[t] += u;
        __syncthreads();
    }
    if (i < N) offs[i] = sm[t] - v;
    if (t == 1023) btot[lb] = sm[1023];
}
// parallel block-total scan: one 128-thread block scans both btot arrays
__global__ void __launch_bounds__(128) scan_b_kernel() {
    __shared__ int sm[128];
    int t = threadIdx.x;
    // item
    int v = (t < NBI_SC) ? g_btot_i[t] : 0;
    sm[t] = v;
    __syncthreads();
#pragma unroll
    for (int s = 1; s < 128; s <<= 1) {
        int u = (t >= s) ? sm[t - s] : 0;
        __syncthreads();
        sm[t] += u;
        __syncthreads();
    }
    if (t < NBI_SC) g_btot_i[t] = sm[t] - v;
    __syncthreads();
    // user
    v = (t < NBU_SC) ? g_btot_u[t] : 0;
    sm[t] = v;
    __syncthreads();
#pragma unroll
    for (int s = 1; s < 128; s <<= 1) {
        int u = (t >= s) ? sm[t - s] : 0;
        __syncthreads();
        sm[t] += u;
        __syncthreads();
    }
    if (t < NBU_SC) g_btot_u[t] = sm[t] - v;
}
__global__ void scan_c_kernel() {
    int i = blockIdx.x * blockDim.x + threadIdx.x;
    if (i < NI) {
        int o = g_off_i[i] + g_btot_i[i >> 10];
        g_off_i[i] = o;  g_work_i[i] = o;
    }
    if (i < NU) {
        int o = g_off_u[i] + g_btot_u[i >> 10];
        g_off_u[i] = o;  g_work_u[i] = o;
    }
    if (i == 0) { g_off_i[NI] = EI; g_off_u[NU] = EU; }
}
__global__ void scatter_kernel(const int* __restrict__ uedg, const float* __restrict__ uev,
                               const int* __restrict__ iedg, const float* __restrict__ iev) {
    int e = blockIdx.x * blockDim.x + threadIdx.x;
    if (e < EU) {
        int p = atomicAdd(&g_work_u[uedg[EU + e]], 1);
        g_csrc_u[p] = uedg[e];
        g_cev_u[p] = uev[e];
    }
    if (e < EI) {
        int p = atomicAdd(&g_work_i[iedg[EI + e]], 1);
        g_csrc_i[p] = iedg[e];
        g_cev_i[p] = iev[e];
    }
}

// ---------------- merged BF16 3-term HMMA GEMM + attention scalars -------------
struct GemmArgs {
    const float* x;
    const uint32_t *wh, *wl;
    const float *as, *ad;
    float *h, *ssrc, *sdst;
    int N;
};

// smem (bytes): B hi/lo [128n][68 u32], A hi/lo [128r][68 u32], red buf
#define SB_BH   0
#define SB_BL   34816
#define SB_AH   69632
#define SB_AL   104448
#define SB_RED  139264
#define SMEM_TOT 143360

template <int ACT>
__global__ void __launch_bounds__(256, 1) gemm_mma_kernel(GemmArgs gi, GemmArgs gu)
{
    extern __shared__ char smem[];
    uint32_t* Bh = (uint32_t*)(smem + SB_BH);
    uint32_t* Bl = (uint32_t*)(smem + SB_BL);
    uint32_t* Ah = (uint32_t*)(smem + SB_AH);
    uint32_t* Al = (uint32_t*)(smem + SB_AL);
    float* red_s = (float*)(smem + SB_RED);
    float* red_d = red_s + 128 * 4;

    const GemmArgs& g = (blockIdx.x < NBI_G) ? gi : gu;
    const int blk = (blockIdx.x < NBI_G) ? blockIdx.x : (blockIdx.x - NBI_G);
    const float* __restrict__ x = g.x;
    const int N = g.N;

    const int tid = threadIdx.x;
    const int lane = tid & 31;
    const int wid = tid >> 5;
    const int wm = wid & 1;
    const int wn = wid >> 1;
    const int r0 = blk * 128;

    // stage B (both hi and lo), uint4 copies into stride-68 layout
    for (int i = tid; i < 2048; i += 256) {
        int n = i >> 4, k4 = (i & 15) * 4;
        *(uint4*)&Bh[n * 68 + k4] = *(const uint4*)&g.wh[n * 64 + k4];
        *(uint4*)&Bl[n * 68 + k4] = *(const uint4*)&g.wl[n * 64 + k4];
    }

    // stage full A tile (128 rows x 128 k): ELU + cheap truncation-based bf16 split
    {
        const int r = tid >> 1;
        const int half = tid & 1;
        const bool ok = (r0 + r < N);
        const float* xr = x + (size_t)(r0 + r) * DIM + half * 64;
#pragma unroll
        for (int q = 0; q < 16; ++q) {
            float4 v = ok ? *(const float4*)(xr + q * 4) : make_float4(0.f, 0.f, 0.f, 0.f);
            if (ACT) { v.x = elu_f(v.x); v.y = elu_f(v.y); v.z = elu_f(v.z); v.w = elu_f(v.w); }
            uint32_t ix = __float_as_uint(v.x), iy = __float_as_uint(v.y);
            uint32_t iz = __float_as_uint(v.z), iw = __float_as_uint(v.w);
            // hi = truncate-to-bf16; pack two hi halves with one byte_perm
            uint32_t hi01 = __byte_perm(ix, iy, 0x7632);
            uint32_t hi23 = __byte_perm(iz, iw, 0x7632);
            // lo = x - hi (exact), then round pair to bf16x2
            float l0 = v.x - __uint_as_float(ix & 0xFFFF0000u);
            float l1 = v.y - __uint_as_float(iy & 0xFFFF0000u);
            float l2 = v.z - __uint_as_float(iz & 0xFFFF0000u);
            float l3 = v.w - __uint_as_float(iw & 0xFFFF0000u);
            int o = r * 68 + half * 32 + q * 2;
            Ah[o] = hi01;  Ah[o + 1] = hi23;
            Al[o] = cvt_bf2(l0, l1);  Al[o + 1] = cvt_bf2(l2, l3);
        }
    }
    __syncthreads();

    float acc[4][4][4];
#pragma unroll
    for (int mt = 0; mt < 4; ++mt)
#pragma unroll
        for (int nt = 0; nt < 4; ++nt)
#pragma unroll
            for (int q = 0; q < 4; ++q) acc[mt][nt][q] = 0.f;

#pragma unroll
    for (int ks = 0; ks < 8; ++ks) {
        const int kk0 = ks * 8;
        uint32_t bh[4][2], bl[4][2];
#pragma unroll
        for (int nt = 0; nt < 4; ++nt) {
            int bn = wn * 32 + nt * 8 + (lane >> 2);
            bh[nt][0] = Bh[bn * 68 + kk0 + (lane & 3)];
            bh[nt][1] = Bh[bn * 68 + kk0 + 4 + (lane & 3)];
            bl[nt][0] = Bl[bn * 68 + kk0 + (lane & 3)];
            bl[nt][1] = Bl[bn * 68 + kk0 + 4 + (lane & 3)];
        }
        uint32_t ah[4][4], al[4][4];
#pragma unroll
        for (int mt = 0; mt < 4; ++mt) {
            int ar = wm * 64 + mt * 16 + (lane >> 2);
            ah[mt][0] = Ah[ar * 68 + kk0 + (lane & 3)];
            ah[mt][1] = Ah[(ar + 8) * 68 + kk0 + (lane & 3)];
            ah[mt][2] = Ah[ar * 68 + kk0 + 4 + (lane & 3)];
            ah[mt][3] = Ah[(ar + 8) * 68 + kk0 + 4 + (lane & 3)];
            al[mt][0] = Al[ar * 68 + kk0 + (lane & 3)];
            al[mt][1] = Al[(ar + 8) * 68 + kk0 + (lane & 3)];
            al[mt][2] = Al[ar * 68 + kk0 + 4 + (lane & 3)];
            al[mt][3] = Al[(ar + 8) * 68 + kk0 + 4 + (lane & 3)];
        }
#pragma unroll
        for (int mt = 0; mt < 4; ++mt)
#pragma unroll
            for (int nt = 0; nt < 4; ++nt) {
                mma_bf16(acc[mt][nt], ah[mt], bh[nt]);
                mma_bf16(acc[mt][nt], ah[mt], bl[nt]);
                mma_bf16(acc[mt][nt], al[mt], bh[nt]);
            }
    }

    // ---------------- epilogue: store h + attention scalar dots ----------------
    float asv[4][2], adv[4][2];
#pragma unroll
    for (int nt = 0; nt < 4; ++nt) {
        int c0 = wn * 32 + nt * 8 + 2 * (lane & 3);
        asv[nt][0] = g.as[c0];   asv[nt][1] = g.as[c0 + 1];
        adv[nt][0] = g.ad[c0];   adv[nt][1] = g.ad[c0 + 1];
    }

    float ps[8], pd[8];
#pragma unroll
    for (int q = 0; q < 8; ++q) { ps[q] = 0.f; pd[q] = 0.f; }

    float* __restrict__ h = g.h;
#pragma unroll
    for (int mt = 0; mt < 4; ++mt) {
        int ar = r0 + wm * 64 + mt * 16 + (lane >> 2);
#pragma unroll
        for (int nt = 0; nt < 4; ++nt) {
            int c0 = wn * 32 + nt * 8 + 2 * (lane & 3);
            if (ar < N)
                *(float2*)(h + (size_t)ar * DIM + c0) = make_float2(acc[mt][nt][0], acc[mt][nt][1]);
            if (ar + 8 < N)
                *(float2*)(h + (size_t)(ar + 8) * DIM + c0) = make_float2(acc[mt][nt][2], acc[mt][nt][3]);
            ps[mt * 2 + 0] += acc[mt][nt][0] * asv[nt][0] + acc[mt][nt][1] * asv[nt][1];
            ps[mt * 2 + 1] += acc[mt][nt][2] * asv[nt][0] + acc[mt][nt][3] * asv[nt][1];
            pd[mt * 2 + 0] += acc[mt][nt][0] * adv[nt][0] + acc[mt][nt][1] * adv[nt][1];
            pd[mt * 2 + 1] += acc[mt][nt][2] * adv[nt][0] + acc[mt][nt][3] * adv[nt][1];
        }
    }
#pragma unroll
    for (int q = 0; q < 8; ++q) {
        ps[q] += __shfl_xor_sync(0xFFFFFFFF, ps[q], 1);
        ps[q] += __shfl_xor_sync(0xFFFFFFFF, ps[q], 2);
        pd[q] += __shfl_xor_sync(0xFFFFFFFF, pd[q], 1);
        pd[q] += __shfl_xor_sync(0xFFFFFFFF, pd[q], 2);
    }
    __syncthreads();
    if ((lane & 3) == 0) {
#pragma unroll
        for (int mt = 0; mt < 4; ++mt) {
            int rl0 = wm * 64 + mt * 16 + (lane >> 2);
            red_s[rl0 * 4 + wn] = ps[mt * 2 + 0];
            red_s[(rl0 + 8) * 4 + wn] = ps[mt * 2 + 1];
            red_d[rl0 * 4 + wn] = pd[mt * 2 + 0];
            red_d[(rl0 + 8) * 4 + wn] = pd[mt * 2 + 1];
        }
    }
    __syncthreads();
    if (tid < 128) {
        int row = r0 + tid;
        if (row < N) {
            float s = red_s[tid * 4] + red_s[tid * 4 + 1] + red_s[tid * 4 + 2] + red_s[tid * 4 + 3];
            float d = red_d[tid * 4] + red_d[tid * 4 + 1] + red_d[tid * 4 + 2] + red_d[tid * 4 + 3];
            g.ssrc[row] = s;
            g.sdst[row] = d;
        }
    }
}

// ---------------- merged CSR aggregate (both graphs per launch) ----------------
struct AggArgs {
    const int* off;
    const int* csrc;
    const float* cev;
    const float *ssrc, *sdst, *h;
    float* out;
    int N;
};

__global__ void agg_csr_kernel(AggArgs ai, AggArgs au)
{
    const AggArgs& a = (blockIdx.x < AB_I) ? ai : au;
    const int blk = (blockIdx.x < AB_I) ? blockIdx.x : (blockIdx.x - AB_I);
    int lane = threadIdx.x & 31;
    int d = blk * 8 + (threadIdx.x >> 5);
    if (d >= a.N) return;
    const int o0 = a.off[d], o1 = a.off[d + 1];
    const float sd = a.sdst[d];
    const float* __restrict__ h = a.h;

    float4 acc = make_float4(0.f, 0.f, 0.f, 0.f);
    float denom = 0.f;

    for (int base = o0; base < o1; base += 32) {
        int idx = base + lane;
        float e = 0.f;
        int s = 0;
        if (idx < o1) {
            s = a.csrc[idx];
            float l = a.ssrc[s] + sd;
            l = l > 0.f ? l : 0.2f * l;
            e = __expf(l) * a.cev[idx];
        }
        float esum = e;
#pragma unroll
        for (int m = 16; m; m >>= 1) esum += __shfl_xor_sync(0xFFFFFFFF, esum, m);
        denom += esum;

        int cnt = min(32, o1 - base);
        for (int k = 0; k < cnt; ++k) {
            float coef = __shfl_sync(0xFFFFFFFF, e, k);
            int sk = __shfl_sync(0xFFFFFFFF, s, k);
            float4 v = *(const float4*)(h + (size_t)sk * DIM + lane * 4);
            acc.x += coef * v.x; acc.y += coef * v.y;
            acc.z += coef * v.z; acc.w += coef * v.w;
        }
    }
    float inv = 1.f / (denom + 1e-16f);
    acc.x *= inv; acc.y *= inv; acc.z *= inv; acc.w *= inv;
    *(float4*)(a.out + (size_t)d * DIM + lane * 4) = acc;
}

// ---------------- final gather (deferred elu applied here) ----------------------
__global__ void gather_kernel(const float* __restrict__ uo, const float* __restrict__ io,
                              const int* __restrict__ uid, const int* __restrict__ iid,
                              float* __restrict__ out)
{
    int t = blockIdx.x * blockDim.x + threadIdx.x;
    int b = t >> 7, c = t & 127;
    if (b < BATCH)          out[t] = elu_f(uo[(size_t)uid[b] * DIM + c]);
    else if (b < 2 * BATCH) out[t] = elu_f(io[(size_t)iid[b - BATCH] * DIM + c]);
}

// ---------------- host orchestration -------------------------------------------
extern "C" void kernel_launch(void* const* d_in, const int* in_sizes, int n_in,
                              void* d_out, int out_size)
{
    const int*   uedg = (const int*)d_in[0];
    const int*   iedg = (const int*)d_in[1];
    const int*   user_id = (const int*)d_in[2];
    const int*   item_id = (const int*)d_in[3];
    const float* uval = (const float*)d_in[4];
    const float* ival = (const float*)d_in[5];
    const float* umat = (const float*)d_in[6];
    const float* imat = (const float*)d_in[7];
    const float* W_u1 = (const float*)d_in[8];
    const float* as_u1 = (const float*)d_in[9];
    const float* ad_u1 = (const float*)d_in[10];
    const float* W_u2 = (const float*)d_in[11];
    const float* as_u2 = (const float*)d_in[12];
    const float* ad_u2 = (const float*)d_in[13];
    const float* W_i1 = (const float*)d_in[14];
    const float* as_i1 = (const float*)d_in[15];
    const float* ad_i1 = (const float*)d_in[16];
    const float* W_i2 = (const float*)d_in[17];
    const float* as_i2 = (const float*)d_in[18];
    const float* ad_i2 = (const float*)d_in[19];

    float *h_u, *h_i, *out1_u, *out1_i, *uout2, *iout2;
    float *ssrc_u, *sdst_u, *ssrc_i, *sdst_i, *cev_u, *cev_i;
    uint32_t *wph, *wpl;
    int *off_u, *off_i, *csrc_u, *csrc_i;
    cudaGetSymbolAddress((void**)&h_u, g_h_u);
    cudaGetSymbolAddress((void**)&h_i, g_h_i);
    cudaGetSymbolAddress((void**)&out1_u, g_out1_u);
    cudaGetSymbolAddress((void**)&out1_i, g_out1_i);
    cudaGetSymbolAddress((void**)&uout2, g_uout2);
    cudaGetSymbolAddress((void**)&iout2, g_iout2);
    cudaGetSymbolAddress((void**)&ssrc_u, g_ssrc_u);
    cudaGetSymbolAddress((void**)&sdst_u, g_sdst_u);
    cudaGetSymbolAddress((void**)&ssrc_i, g_ssrc_i);
    cudaGetSymbolAddress((void**)&sdst_i, g_sdst_i);
    cudaGetSymbolAddress((void**)&wph, g_wp_hi);
    cudaGetSymbolAddress((void**)&wpl, g_wp_lo);
    cudaGetSymbolAddress((void**)&off_u, g_off_u);
    cudaGetSymbolAddress((void**)&off_i, g_off_i);
    cudaGetSymbolAddress((void**)&csrc_u, g_csrc_u);
    cudaGetSymbolAddress((void**)&csrc_i, g_csrc_i);
    cudaGetSymbolAddress((void**)&cev_u, g_cev_u);
    cudaGetSymbolAddress((void**)&cev_i, g_cev_i);

    cudaFuncSetAttribute(gemm_mma_kernel<0>, cudaFuncAttributeMaxDynamicSharedMemorySize, SMEM_TOT);
    cudaFuncSetAttribute(gemm_mma_kernel<1>, cudaFuncAttributeMaxDynamicSharedMemorySize, SMEM_TOT);

    const int TB = 256;
    const int WSTRIDE = DIM * 64;

    // weight prep (layer order: 0=i1, 1=i2, 2=u1, 3=u2)
    prep_w_kernel<<<4 * DIM * 64 / TB, TB>>>(W_i1, W_i2, W_u1, W_u2);

    // merged CSR build for both graphs
    zero_cnt_kernel<<<(NU + TB) / TB, TB>>>();
    count_kernel<<<(EU + TB - 1) / TB, TB>>>(uedg + EU, iedg + EI);
    scan_a_kernel<<<NBI_SC + NBU_SC, 1024>>>();
    scan_b_kernel<<<1, 128>>>();
    scan_c_kernel<<<(NU + TB - 1) / TB, TB>>>();
    scatter_kernel<<<(EU + TB - 1) / TB, TB>>>(uedg, uval, iedg, ival);

    // ---- layer 1 (both graphs merged) ----
    GemmArgs gi1 = { imat, wph + 0 * WSTRIDE, wpl + 0 * WSTRIDE, as_i1, ad_i1,
                     h_i, ssrc_i, sdst_i, NI };
    GemmArgs gu1 = { umat, wph + 2 * WSTRIDE, wpl + 2 * WSTRIDE, as_u1, ad_u1,
                     h_u, ssrc_u, sdst_u, NU };
    gemm_mma_kernel<0><<<NBI_G + NBU_G, 256, SMEM_TOT>>>(gi1, gu1);

    AggArgs ai1 = { off_i, csrc_i, cev_i, ssrc_i, sdst_i, h_i, out1_i, NI };
    AggArgs au1 = { off_u, csrc_u, cev_u, ssrc_u, sdst_u, h_u, out1_u, NU };
    agg_csr_kernel<<<AB_I + AB_U, 256>>>(ai1, au1);

    // ---- layer 2 (both graphs merged) ----
    GemmArgs gi2 = { out1_i, wph + 1 * WSTRIDE, wpl + 1 * WSTRIDE, as_i2, ad_i2,
                     h_i, ssrc_i, sdst_i, NI };
    GemmArgs gu2 = { out1_u, wph + 3 * WSTRIDE, wpl + 3 * WSTRIDE, as_u2, ad_u2,
                     h_u, ssrc_u, sdst_u, NU };
    gemm_mma_kernel<1><<<NBI_G + NBU_G, 256, SMEM_TOT>>>(gi2, gu2);

    AggArgs ai2 = { off_i, csrc_i, cev_i, ssrc_i, sdst_i, h_i, iout2, NI };
    AggArgs au2 = { off_u, csrc_u, cev_u, ssrc_u, sdst_u, h_u, uout2, NU };
    agg_csr_kernel<<<AB_I + AB_U, 256>>>(ai2, au2);

    gather_kernel<<<(2 * BATCH * DIM) / TB, TB>>>(uout2, iout2, user_id, item_id, (float*)d_out);
}

// round 10
// speedup vs baseline: 1.3192x; 1.0720x over previous
#include <cuda_runtime.h>
#include <cuda_bf16.h>
#include <cstdint>
#include <cfloat>

#define NU 100000
#define NI 50000
#define DIM 128
#define EU 400000
#define EI 200000
#define BATCH 4096

#define NBI_G ((NI + 127) / 128)       // 391 gemm blocks (item)
#define NBU_G ((NU + 127) / 128)       // 782 gemm blocks (user)
#define NBI_SC ((NI + 1023) / 1024)    // 49 scan blocks (item)
#define NBU_SC ((NU + 1023) / 1024)    // 98 scan blocks (user)
#define AB_I ((NI + 7) / 8)            // agg blocks (item)
#define AB_U ((NU + 7) / 8)            // agg blocks (user)

// ---------------- scratch (static device memory) ------------------------------
__device__ float g_h_u[NU * DIM];
__device__ float g_h_i[NI * DIM];
__device__ float g_out1_u[NU * DIM];
__device__ float g_out1_i[NI * DIM];
__device__ float g_uout2[NU * DIM];
__device__ float g_iout2[NI * DIM];
__device__ float g_ssrc_u[NU], g_sdst_u[NU];
__device__ float g_ssrc_i[NI], g_sdst_i[NI];
__device__ uint32_t g_wp_hi[4][DIM * 64];   // W^T [n][k-pair] bf16x2, hi part
__device__ uint32_t g_wp_lo[4][DIM * 64];   // residual lo part
// CSR (both graphs persist)
__device__ int   g_cnt_u[NU + 1], g_cnt_i[NI + 1];
__device__ int   g_off_u[NU + 1], g_off_i[NI + 1];
__device__ int   g_btot_u[NBU_SC], g_btot_i[NBI_SC];
__device__ int   g_work_u[NU], g_work_i[NI];
__device__ int   g_csrc_u[EU], g_csrc_i[EI];
__device__ float g_cev_u[EU],  g_cev_i[EI];

// ---------------- helpers ------------------------------------------------------
__device__ __forceinline__ float elu_f(float x) {
    return x > 0.f ? x : __expf(x) - 1.f;
}
__device__ __forceinline__ uint32_t pack_bf2(__nv_bfloat16 a, __nv_bfloat16 b) {
    return ((uint32_t)__bfloat16_as_ushort(b) << 16) | (uint32_t)__bfloat16_as_ushort(a);
}
__device__ __forceinline__ uint32_t cvt_bf2(float lo0, float lo1) {
    uint32_t r;                       // lower half = lo0, upper = lo1
    asm("cvt.rn.bf16x2.f32 %0, %1, %2;" : "=r"(r) : "f"(lo1), "f"(lo0));
    return r;
}
__device__ __forceinline__ void mma_bf16(float* d, const uint32_t* a, const uint32_t* b) {
    asm volatile(
        "mma.sync.aligned.m16n8k16.row.col.f32.bf16.bf16.f32 "
        "{%0,%1,%2,%3}, {%4,%5,%6,%7}, {%8,%9}, {%0,%1,%2,%3};"
        : "+f"(d[0]), "+f"(d[1]), "+f"(d[2]), "+f"(d[3])
        : "r"(a[0]), "r"(a[1]), "r"(a[2]), "r"(a[3]), "r"(b[0]), "r"(b[1]));
}

// ---------------- W^T hi/lo prep (bf16 split, packed pairs) --------------------
__global__ void prep_w_kernel(const float* __restrict__ w0, const float* __restrict__ w1,
                              const float* __restrict__ w2, const float* __restrict__ w3) {
    int i = blockIdx.x * blockDim.x + threadIdx.x;     // 4*128*64
    int l = i >> 13;
    int j = i & 8191;
    int n = j >> 6, kk = j & 63;
    const float* W = (l == 0) ? w0 : (l == 1) ? w1 : (l == 2) ? w2 : w3;
    float a = W[(2 * kk) * DIM + n];
    float b = W[(2 * kk + 1) * DIM + n];
    __nv_bfloat16 ha = __float2bfloat16(a);
    __nv_bfloat16 hb = __float2bfloat16(b);
    __nv_bfloat16 la = __float2bfloat16(a - __bfloat162float(ha));
    __nv_bfloat16 lb = __float2bfloat16(b - __bfloat162float(hb));
    g_wp_hi[l][n * 64 + kk] = pack_bf2(ha, hb);
    g_wp_lo[l][n * 64 + kk] = pack_bf2(la, lb);
}

// ---------------- merged CSR build (both graphs per launch) --------------------
__global__ void zero_cnt_kernel() {
    int i = blockIdx.x * blockDim.x + threadIdx.x;
    if (i <= NU) g_cnt_u[i] = 0;
    if (i <= NI) g_cnt_i[i] = 0;
}
__global__ void count_kernel(const int* __restrict__ udst, const int* __restrict__ idst) {
    int e = blockIdx.x * blockDim.x + threadIdx.x;
    if (e < EU) atomicAdd(&g_cnt_u[udst[e]], 1);
    if (e < EI) atomicAdd(&g_cnt_i[idst[e]], 1);
}
__global__ void __launch_bounds__(1024) scan_a_kernel() {
    __shared__ int sm[1024];
    int t = threadIdx.x;
    int b = blockIdx.x;
    const int* cnt;  int* offs;  int* btot;  int N;  int lb;
    if (b < NBI_SC) { cnt = g_cnt_i; offs = g_off_i; btot = g_btot_i; N = NI; lb = b; }
    else            { cnt = g_cnt_u; offs = g_off_u; btot = g_btot_u; N = NU; lb = b - NBI_SC; }
    int i = lb * 1024 + t;
    int v = (i < N) ? cnt[i] : 0;
    sm[t] = v;
    __syncthreads();
#pragma unroll
    for (int s = 1; s < 1024; s <<= 1) {
        int u = (t >= s) ? sm[t - s] : 0;
        __syncthreads();
        sm[t] += u;
        __syncthreads();
    }
    if (i < N) offs[i] = sm[t] - v;
    if (t == 1023) btot[lb] = sm[1023];
}
// parallel block-total scan: one 128-thread block scans both btot arrays
__global__ void __launch_bounds__(128) scan_b_kernel() {
    __shared__ int sm[128];
    int t = threadIdx.x;
    int v = (t < NBI_SC) ? g_btot_i[t] : 0;
    sm[t] = v;
    __syncthreads();
#pragma unroll
    for (int s = 1; s < 128; s <<= 1) {
        int u = (t >= s) ? sm[t - s] : 0;
        __syncthreads();
        sm[t] += u;
        __syncthreads();
    }
    if (t < NBI_SC) g_btot_i[t] = sm[t] - v;
    __syncthreads();
    v = (t < NBU_SC) ? g_btot_u[t] : 0;
    sm[t] = v;
    __syncthreads();
#pragma unroll
    for (int s = 1; s < 128; s <<= 1) {
        int u = (t >= s) ? sm[t - s] : 0;
        __syncthreads();
        sm[t] += u;
        __syncthreads();
    }
    if (t < NBU_SC) g_btot_u[t] = sm[t] - v;
}
__global__ void scan_c_kernel() {
    int i = blockIdx.x * blockDim.x + threadIdx.x;
    if (i < NI) {
        int o = g_off_i[i] + g_btot_i[i >> 10];
        g_off_i[i] = o;  g_work_i[i] = o;
    }
    if (i < NU) {
        int o = g_off_u[i] + g_btot_u[i >> 10];
        g_off_u[i] = o;  g_work_u[i] = o;
    }
    if (i == 0) { g_off_i[NI] = EI; g_off_u[NU] = EU; }
}
__global__ void scatter_kernel(const int* __restrict__ uedg, const float* __restrict__ uev,
                               const int* __restrict__ iedg, const float* __restrict__ iev) {
    int e = blockIdx.x * blockDim.x + threadIdx.x;
    if (e < EU) {
        int p = atomicAdd(&g_work_u[uedg[EU + e]], 1);
        g_csrc_u[p] = uedg[e];
        g_cev_u[p] = uev[e];
    }
    if (e < EI) {
        int p = atomicAdd(&g_work_i[iedg[EI + e]], 1);
        g_csrc_i[p] = iedg[e];
        g_cev_i[p] = iev[e];
    }
}

// ---------------- merged BF16 3-term HMMA GEMM + attention scalars -------------
struct GemmArgs {
    const float* x;
    const uint32_t *wh, *wl;
    const float *as, *ad;
    float *h, *ssrc, *sdst;
    int N;
};

// smem (bytes): B hi/lo [128n][68 u32], A hi/lo [128r][68 u32], red buf
#define SB_BH   0
#define SB_BL   34816
#define SB_AH   69632
#define SB_AL   104448
#define SB_RED  139264
#define SMEM_TOT 143360

template <int ACT>
__global__ void __launch_bounds__(256, 1) gemm_mma_kernel(GemmArgs gi, GemmArgs gu)
{
    extern __shared__ char smem[];
    uint32_t* Bh = (uint32_t*)(smem + SB_BH);
    uint32_t* Bl = (uint32_t*)(smem + SB_BL);
    uint32_t* Ah = (uint32_t*)(smem + SB_AH);
    uint32_t* Al = (uint32_t*)(smem + SB_AL);
    float* red_s = (float*)(smem + SB_RED);
    float* red_d = red_s + 128 * 4;

    const GemmArgs& g = (blockIdx.x < NBI_G) ? gi : gu;
    const int blk = (blockIdx.x < NBI_G) ? blockIdx.x : (blockIdx.x - NBI_G);
    const float* __restrict__ x = g.x;
    const int N = g.N;

    const int tid = threadIdx.x;
    const int lane = tid & 31;
    const int wid = tid >> 5;
    const int wm = wid & 1;
    const int wn = wid >> 1;
    const int r0 = blk * 128;

    // stage B (both hi and lo), uint4 copies into stride-68 layout
    for (int i = tid; i < 2048; i += 256) {
        int n = i >> 4, k4 = (i & 15) * 4;
        *(uint4*)&Bh[n * 68 + k4] = *(const uint4*)&g.wh[n * 64 + k4];
        *(uint4*)&Bl[n * 68 + k4] = *(const uint4*)&g.wl[n * 64 + k4];
    }

    // stage full A tile (128 rows x 128 k): ELU + cheap truncation-based bf16 split
    {
        const int r = tid >> 1;
        const int half = tid & 1;
        const bool ok = (r0 + r < N);
        const float* xr = x + (size_t)(r0 + r) * DIM + half * 64;
#pragma unroll
        for (int q = 0; q < 16; ++q) {
            float4 v = ok ? *(const float4*)(xr + q * 4) : make_float4(0.f, 0.f, 0.f, 0.f);
            if (ACT) { v.x = elu_f(v.x); v.y = elu_f(v.y); v.z = elu_f(v.z); v.w = elu_f(v.w); }
            uint32_t ix = __float_as_uint(v.x), iy = __float_as_uint(v.y);
            uint32_t iz = __float_as_uint(v.z), iw = __float_as_uint(v.w);
            uint32_t hi01 = __byte_perm(ix, iy, 0x7632);
            uint32_t hi23 = __byte_perm(iz, iw, 0x7632);
            float l0 = v.x - __uint_as_float(ix & 0xFFFF0000u);
            float l1 = v.y - __uint_as_float(iy & 0xFFFF0000u);
            float l2 = v.z - __uint_as_float(iz & 0xFFFF0000u);
            float l3 = v.w - __uint_as_float(iw & 0xFFFF0000u);
            int o = r * 68 + half * 32 + q * 2;
            Ah[o] = hi01;  Ah[o + 1] = hi23;
            Al[o] = cvt_bf2(l0, l1);  Al[o + 1] = cvt_bf2(l2, l3);
        }
    }
    __syncthreads();

    float acc[4][4][4];
#pragma unroll
    for (int mt = 0; mt < 4; ++mt)
#pragma unroll
        for (int nt = 0; nt < 4; ++nt)
#pragma unroll
            for (int q = 0; q < 4; ++q) acc[mt][nt][q] = 0.f;

#pragma unroll
    for (int ks = 0; ks < 8; ++ks) {
        const int kk0 = ks * 8;
        uint32_t bh[4][2], bl[4][2];
#pragma unroll
        for (int nt = 0; nt < 4; ++nt) {
            int bn = wn * 32 + nt * 8 + (lane >> 2);
            bh[nt][0] = Bh[bn * 68 + kk0 + (lane & 3)];
            bh[nt][1] = Bh[bn * 68 + kk0 + 4 + (lane & 3)];
            bl[nt][0] = Bl[bn * 68 + kk0 + (lane & 3)];
            bl[nt][1] = Bl[bn * 68 + kk0 + 4 + (lane & 3)];
        }
        uint32_t ah[4][4], al[4][4];
#pragma unroll
        for (int mt = 0; mt < 4; ++mt) {
            int ar = wm * 64 + mt * 16 + (lane >> 2);
            ah[mt][0] = Ah[ar * 68 + kk0 + (lane & 3)];
            ah[mt][1] = Ah[(ar + 8) * 68 + kk0 + (lane & 3)];
            ah[mt][2] = Ah[ar * 68 + kk0 + 4 + (lane & 3)];
            ah[mt][3] = Ah[(ar + 8) * 68 + kk0 + 4 + (lane & 3)];
            al[mt][0] = Al[ar * 68 + kk0 + (lane & 3)];
            al[mt][1] = Al[(ar + 8) * 68 + kk0 + (lane & 3)];
            al[mt][2] = Al[ar * 68 + kk0 + 4 + (lane & 3)];
            al[mt][3] = Al[(ar + 8) * 68 + kk0 + 4 + (lane & 3)];
        }
#pragma unroll
        for (int mt = 0; mt < 4; ++mt)
#pragma unroll
            for (int nt = 0; nt < 4; ++nt) {
                mma_bf16(acc[mt][nt], ah[mt], bh[nt]);
                mma_bf16(acc[mt][nt], ah[mt], bl[nt]);
                mma_bf16(acc[mt][nt], al[mt], bh[nt]);
            }
    }

    // ---------------- epilogue: store h + attention scalar dots ----------------
    float asv[4][2], adv[4][2];
#pragma unroll
    for (int nt = 0; nt < 4; ++nt) {
        int c0 = wn * 32 + nt * 8 + 2 * (lane & 3);
        asv[nt][0] = g.as[c0];   asv[nt][1] = g.as[c0 + 1];
        adv[nt][0] = g.ad[c0];   adv[nt][1] = g.ad[c0 + 1];
    }

    float ps[8], pd[8];
#pragma unroll
    for (int q = 0; q < 8; ++q) { ps[q] = 0.f; pd[q] = 0.f; }

    float* __restrict__ h = g.h;
#pragma unroll
    for (int mt = 0; mt < 4; ++mt) {
        int ar = r0 + wm * 64 + mt * 16 + (lane >> 2);
#pragma unroll
        for (int nt = 0; nt < 4; ++nt) {
            int c0 = wn * 32 + nt * 8 + 2 * (lane & 3);
            if (ar < N)
                *(float2*)(h + (size_t)ar * DIM + c0) = make_float2(acc[mt][nt][0], acc[mt][nt][1]);
            if (ar + 8 < N)
                *(float2*)(h + (size_t)(ar + 8) * DIM + c0) = make_float2(acc[mt][nt][2], acc[mt][nt][3]);
            ps[mt * 2 + 0] += acc[mt][nt][0] * asv[nt][0] + acc[mt][nt][1] * asv[nt][1];
            ps[mt * 2 + 1] += acc[mt][nt][2] * asv[nt][0] + acc[mt][nt][3] * asv[nt][1];
            pd[mt * 2 + 0] += acc[mt][nt][0] * adv[nt][0] + acc[mt][nt][1] * adv[nt][1];
            pd[mt * 2 + 1] += acc[mt][nt][2] * adv[nt][0] + acc[mt][nt][3] * adv[nt][1];
        }
    }
#pragma unroll
    for (int q = 0; q < 8; ++q) {
        ps[q] += __shfl_xor_sync(0xFFFFFFFF, ps[q], 1);
        ps[q] += __shfl_xor_sync(0xFFFFFFFF, ps[q], 2);
        pd[q] += __shfl_xor_sync(0xFFFFFFFF, pd[q], 1);
        pd[q] += __shfl_xor_sync(0xFFFFFFFF, pd[q], 2);
    }
    __syncthreads();
    if ((lane & 3) == 0) {
#pragma unroll
        for (int mt = 0; mt < 4; ++mt) {
            int rl0 = wm * 64 + mt * 16 + (lane >> 2);
            red_s[rl0 * 4 + wn] = ps[mt * 2 + 0];
            red_s[(rl0 + 8) * 4 + wn] = ps[mt * 2 + 1];
            red_d[rl0 * 4 + wn] = pd[mt * 2 + 0];
            red_d[(rl0 + 8) * 4 + wn] = pd[mt * 2 + 1];
        }
    }
    __syncthreads();
    if (tid < 128) {
        int row = r0 + tid;
        if (row < N) {
            float s = red_s[tid * 4] + red_s[tid * 4 + 1] + red_s[tid * 4 + 2] + red_s[tid * 4 + 3];
            float d = red_d[tid * 4] + red_d[tid * 4 + 1] + red_d[tid * 4 + 2] + red_d[tid * 4 + 3];
            g.ssrc[row] = s;
            g.sdst[row] = d;
        }
    }
}

// ---------------- merged CSR aggregate (both graphs per launch) ----------------
struct AggArgs {
    const int* off;
    const int* csrc;
    const float* cev;
    const float *ssrc, *sdst, *h;
    float* out;
    int N;
};

__global__ void agg_csr_kernel(AggArgs ai, AggArgs au)
{
    const AggArgs& a = (blockIdx.x < AB_I) ? ai : au;
    const int blk = (blockIdx.x < AB_I) ? blockIdx.x : (blockIdx.x - AB_I);
    int lane = threadIdx.x & 31;
    int d = blk * 8 + (threadIdx.x >> 5);
    if (d >= a.N) return;
    const int o0 = a.off[d], o1 = a.off[d + 1];
    const float sd = a.sdst[d];
    const float* __restrict__ h = a.h;

    float4 acc = make_float4(0.f, 0.f, 0.f, 0.f);
    float denom = 0.f;

    for (int base = o0; base < o1; base += 32) {
        int idx = base + lane;
        float e = 0.f;
        int s = 0;
        if (idx < o1) {
            s = a.csrc[idx];
            float l = a.ssrc[s] + sd;
            l = l > 0.f ? l : 0.2f * l;
            e = __expf(l) * a.cev[idx];
        }
        float esum = e;
#pragma unroll
        for (int m = 16; m; m >>= 1) esum += __shfl_xor_sync(0xFFFFFFFF, esum, m);
        denom += esum;

        int cnt = min(32, o1 - base);
        int k = 0;
        // MLP batch of 4: issue 4 independent row loads before accumulating
        for (; k + 4 <= cnt; k += 4) {
            float c0 = __shfl_sync(0xFFFFFFFF, e, k);
            float c1 = __shfl_sync(0xFFFFFFFF, e, k + 1);
            float c2 = __shfl_sync(0xFFFFFFFF, e, k + 2);
            float c3 = __shfl_sync(0xFFFFFFFF, e, k + 3);
            int s0 = __shfl_sync(0xFFFFFFFF, s, k);
            int s1 = __shfl_sync(0xFFFFFFFF, s, k + 1);
            int s2 = __shfl_sync(0xFFFFFFFF, s, k + 2);
            int s3 = __shfl_sync(0xFFFFFFFF, s, k + 3);
            float4 v0 = *(const float4*)(h + (size_t)s0 * DIM + lane * 4);
            float4 v1 = *(const float4*)(h + (size_t)s1 * DIM + lane * 4);
            float4 v2 = *(const float4*)(h + (size_t)s2 * DIM + lane * 4);
            float4 v3 = *(const float4*)(h + (size_t)s3 * DIM + lane * 4);
            acc.x += c0 * v0.x + c1 * v1.x + c2 * v2.x + c3 * v3.x;
            acc.y += c0 * v0.y + c1 * v1.y + c2 * v2.y + c3 * v3.y;
            acc.z += c0 * v0.z + c1 * v1.z + c2 * v2.z + c3 * v3.z;
            acc.w += c0 * v0.w + c1 * v1.w + c2 * v2.w + c3 * v3.w;
        }
        for (; k < cnt; ++k) {
            float coef = __shfl_sync(0xFFFFFFFF, e, k);
            int sk = __shfl_sync(0xFFFFFFFF, s, k);
            float4 v = *(const float4*)(h + (size_t)sk * DIM + lane * 4);
            acc.x += coef * v.x; acc.y += coef * v.y;
            acc.z += coef * v.z; acc.w += coef * v.w;
        }
    }
    float inv = 1.f / (denom + 1e-16f);
    acc.x *= inv; acc.y *= inv; acc.z *= inv; acc.w *= inv;
    *(float4*)(a.out + (size_t)d * DIM + lane * 4) = acc;
}

// ---------------- final gather (deferred elu applied here) ----------------------
__global__ void gather_kernel(const float* __restrict__ uo, const float* __restrict__ io,
                              const int* __restrict__ uid, const int* __restrict__ iid,
                              float* __restrict__ out)
{
    int t = blockIdx.x * blockDim.x + threadIdx.x;
    int b = t >> 7, c = t & 127;
    if (b < BATCH)          out[t] = elu_f(uo[(size_t)uid[b] * DIM + c]);
    else if (b < 2 * BATCH) out[t] = elu_f(io[(size_t)iid[b - BATCH] * DIM + c]);
}

// ---------------- host orchestration -------------------------------------------
extern "C" void kernel_launch(void* const* d_in, const int* in_sizes, int n_in,
                              void* d_out, int out_size)
{
    const int*   uedg = (const int*)d_in[0];
    const int*   iedg = (const int*)d_in[1];
    const int*   user_id = (const int*)d_in[2];
    const int*   item_id = (const int*)d_in[3];
    const float* uval = (const float*)d_in[4];
    const float* ival = (const float*)d_in[5];
    const float* umat = (const float*)d_in[6];
    const float* imat = (const float*)d_in[7];
    const float* W_u1 = (const float*)d_in[8];
    const float* as_u1 = (const float*)d_in[9];
    const float* ad_u1 = (const float*)d_in[10];
    const float* W_u2 = (const float*)d_in[11];
    const float* as_u2 = (const float*)d_in[12];
    const float* ad_u2 = (const float*)d_in[13];
    const float* W_i1 = (const float*)d_in[14];
    const float* as_i1 = (const float*)d_in[15];
    const float* ad_i1 = (const float*)d_in[16];
    const float* W_i2 = (const float*)d_in[17];
    const float* as_i2 = (const float*)d_in[18];
    const float* ad_i2 = (const float*)d_in[19];

    float *h_u, *h_i, *out1_u, *out1_i, *uout2, *iout2;
    float *ssrc_u, *sdst_u, *ssrc_i, *sdst_i, *cev_u, *cev_i;
    uint32_t *wph, *wpl;
    int *off_u, *off_i, *csrc_u, *csrc_i;
    cudaGetSymbolAddress((void**)&h_u, g_h_u);
    cudaGetSymbolAddress((void**)&h_i, g_h_i);
    cudaGetSymbolAddress((void**)&out1_u, g_out1_u);
    cudaGetSymbolAddress((void**)&out1_i, g_out1_i);
    cudaGetSymbolAddress((void**)&uout2, g_uout2);
    cudaGetSymbolAddress((void**)&iout2, g_iout2);
    cudaGetSymbolAddress((void**)&ssrc_u, g_ssrc_u);
    cudaGetSymbolAddress((void**)&sdst_u, g_sdst_u);
    cudaGetSymbolAddress((void**)&ssrc_i, g_ssrc_i);
    cudaGetSymbolAddress((void**)&sdst_i, g_sdst_i);
    cudaGetSymbolAddress((void**)&wph, g_wp_hi);
    cudaGetSymbolAddress((void**)&wpl, g_wp_lo);
    cudaGetSymbolAddress((void**)&off_u, g_off_u);
    cudaGetSymbolAddress((void**)&off_i, g_off_i);
    cudaGetSymbolAddress((void**)&csrc_u, g_csrc_u);
    cudaGetSymbolAddress((void**)&csrc_i, g_csrc_i);
    cudaGetSymbolAddress((void**)&cev_u, g_cev_u);
    cudaGetSymbolAddress((void**)&cev_i, g_cev_i);

    cudaFuncSetAttribute(gemm_mma_kernel<0>, cudaFuncAttributeMaxDynamicSharedMemorySize, SMEM_TOT);
    cudaFuncSetAttribute(gemm_mma_kernel<1>, cudaFuncAttributeMaxDynamicSharedMemorySize, SMEM_TOT);

    // one-time side-stream + events (resources only; per-call work is identical)
    static cudaStream_t s2 = nullptr;
    static cudaEvent_t evF = nullptr, evC = nullptr;
    if (!s2) {
        cudaStreamCreateWithFlags(&s2, cudaStreamNonBlocking);
        cudaEventCreateWithFlags(&evF, cudaEventDisableTiming);
        cudaEventCreateWithFlags(&evC, cudaEventDisableTiming);
    }

    const int TB = 256;
    const int WSTRIDE = DIM * 64;

    // fork: CSR build on side stream, overlapped with prep + GEMM1
    cudaEventRecord(evF, 0);
    cudaStreamWaitEvent(s2, evF, 0);

    zero_cnt_kernel<<<(NU + TB) / TB, TB, 0, s2>>>();
    count_kernel<<<(EU + TB - 1) / TB, TB, 0, s2>>>(uedg + EU, iedg + EI);
    scan_a_kernel<<<NBI_SC + NBU_SC, 1024, 0, s2>>>();
    scan_b_kernel<<<1, 128, 0, s2>>>();
    scan_c_kernel<<<(NU + TB - 1) / TB, TB, 0, s2>>>();
    scatter_kernel<<<(EU + TB - 1) / TB, TB, 0, s2>>>(uedg, uval, iedg, ival);
    cudaEventRecord(evC, s2);

    // main stream: weight prep + layer-1 GEMM (independent of CSR)
    prep_w_kernel<<<4 * DIM * 64 / TB, TB>>>(W_i1, W_i2, W_u1, W_u2);

    GemmArgs gi1 = { imat, wph + 0 * WSTRIDE, wpl + 0 * WSTRIDE, as_i1, ad_i1,
                     h_i, ssrc_i, sdst_i, NI };
    GemmArgs gu1 = { umat, wph + 2 * WSTRIDE, wpl + 2 * WSTRIDE, as_u1, ad_u1,
                     h_u, ssrc_u, sdst_u, NU };
    gemm_mma_kernel<0><<<NBI_G + NBU_G, 256, SMEM_TOT>>>(gi1, gu1);

    // join: agg needs the CSR
    cudaStreamWaitEvent(0, evC, 0);

    AggArgs ai1 = { off_i, csrc_i, cev_i, ssrc_i, sdst_i, h_i, out1_i, NI };
    AggArgs au1 = { off_u, csrc_u, cev_u, ssrc_u, sdst_u, h_u, out1_u, NU };
    agg_csr_kernel<<<AB_I + AB_U, 256>>>(ai1, au1);

    // ---- layer 2 (both graphs merged) ----
    GemmArgs gi2 = { out1_i, wph + 1 * WSTRIDE, wpl + 1 * WSTRIDE, as_i2, ad_i2,
                     h_i, ssrc_i, sdst_i, NI };
    GemmArgs gu2 = { out1_u, wph + 3 * WSTRIDE, wpl + 3 * WSTRIDE, as_u2, ad_u2,
                     h_u, ssrc_u, sdst_u, NU };
    gemm_mma_kernel<1><<<NBI_G + NBU_G, 256, SMEM_TOT>>>(gi2, gu2);

    AggArgs ai2 = { off_i, csrc_i, cev_i, ssrc_i, sdst_i, h_i, iout2, NI };
    AggArgs au2 = { off_u, csrc_u, cev_u, ssrc_u, sdst_u, h_u, uout2, NU };
    agg_csr_kernel<<<AB_I + AB_U, 256>>>(ai2, au2);

    gather_kernel<<<(2 * BATCH * DIM) / TB, TB>>>(uout2, iout2, user_id, item_id, (float*)d_out);
}

// round 11
// speedup vs baseline: 1.4945x; 1.1329x over previous
#include <cuda_runtime.h>
#include <cuda_bf16.h>
#include <cuda_fp16.h>
#include <cstdint>
#include <cfloat>

#define NU 100000
#define NI 50000
#define DIM 128
#define EU 400000
#define EI 200000
#define BATCH 4096

#define NBI_G ((NI + 127) / 128)       // 391 gemm blocks (item)
#define NBU_G ((NU + 127) / 128)       // 782 gemm blocks (user)
#define NBI_SC ((NI + 1023) / 1024)    // 49 scan blocks (item)
#define NBU_SC ((NU + 1023) / 1024)    // 98 scan blocks (user)
#define AB_I ((NI + 7) / 8)            // agg blocks (item)
#define AB_U ((NU + 7) / 8)            // agg blocks (user)

// ---------------- scratch (static device memory) ------------------------------
__device__ __half g_h_u[NU * DIM];          // h stored fp16 (agg is sole consumer)
__device__ __half g_h_i[NI * DIM];
__device__ float g_out1_u[NU * DIM];
__device__ float g_out1_i[NI * DIM];
__device__ float g_uout2[NU * DIM];
__device__ float g_iout2[NI * DIM];
__device__ float g_ssrc_u[NU], g_sdst_u[NU];
__device__ float g_ssrc_i[NI], g_sdst_i[NI];
__device__ uint32_t g_wp_hi[4][DIM * 64];   // W^T [n][k-pair] bf16x2, hi part
__device__ uint32_t g_wp_lo[4][DIM * 64];   // residual lo part
// CSR (both graphs persist)
__device__ int   g_cnt_u[NU + 1], g_cnt_i[NI + 1];
__device__ int   g_off_u[NU + 1], g_off_i[NI + 1];
__device__ int   g_btot_u[NBU_SC], g_btot_i[NBI_SC];
__device__ int   g_work_u[NU], g_work_i[NI];
__device__ int2  g_ced_u[EU], g_ced_i[EI];  // packed (src, ev bits)

// ---------------- helpers ------------------------------------------------------
__device__ __forceinline__ float elu_f(float x) {
    return x > 0.f ? x : __expf(x) - 1.f;
}
__device__ __forceinline__ uint32_t pack_bf2(__nv_bfloat16 a, __nv_bfloat16 b) {
    return ((uint32_t)__bfloat16_as_ushort(b) << 16) | (uint32_t)__bfloat16_as_ushort(a);
}
__device__ __forceinline__ uint32_t cvt_bf2(float lo0, float lo1) {
    uint32_t r;                       // lower half = lo0, upper = lo1
    asm("cvt.rn.bf16x2.f32 %0, %1, %2;" : "=r"(r) : "f"(lo1), "f"(lo0));
    return r;
}
__device__ __forceinline__ void mma_bf16(float* d, const uint32_t* a, const uint32_t* b) {
    asm volatile(
        "mma.sync.aligned.m16n8k16.row.col.f32.bf16.bf16.f32 "
        "{%0,%1,%2,%3}, {%4,%5,%6,%7}, {%8,%9}, {%0,%1,%2,%3};"
        : "+f"(d[0]), "+f"(d[1]), "+f"(d[2]), "+f"(d[3])
        : "r"(a[0]), "r"(a[1]), "r"(a[2]), "r"(a[3]), "r"(b[0]), "r"(b[1]));
}
// load 4 fp16 h values (8B) and convert to float4
__device__ __forceinline__ float4 load_h4(const __half* p) {
    uint2 raw = *(const uint2*)p;
    float2 f0 = __half22float2(*(__half2*)&raw.x);
    float2 f1 = __half22float2(*(__half2*)&raw.y);
    return make_float4(f0.x, f0.y, f1.x, f1.y);
}

// ---------------- W^T hi/lo prep (bf16 split, packed pairs) --------------------
__global__ void prep_w_kernel(const float* __restrict__ w0, const float* __restrict__ w1,
                              const float* __restrict__ w2, const float* __restrict__ w3) {
    int i = blockIdx.x * blockDim.x + threadIdx.x;     // 4*128*64
    int l = i >> 13;
    int j = i & 8191;
    int n = j >> 6, kk = j & 63;
    const float* W = (l == 0) ? w0 : (l == 1) ? w1 : (l == 2) ? w2 : w3;
    float a = W[(2 * kk) * DIM + n];
    float b = W[(2 * kk + 1) * DIM + n];
    __nv_bfloat16 ha = __float2bfloat16(a);
    __nv_bfloat16 hb = __float2bfloat16(b);
    __nv_bfloat16 la = __float2bfloat16(a - __bfloat162float(ha));
    __nv_bfloat16 lb = __float2bfloat16(b - __bfloat162float(hb));
    g_wp_hi[l][n * 64 + kk] = pack_bf2(ha, hb);
    g_wp_lo[l][n * 64 + kk] = pack_bf2(la, lb);
}

// ---------------- merged CSR build (both graphs per launch) --------------------
__global__ void zero_cnt_kernel() {
    int i = blockIdx.x * blockDim.x + threadIdx.x;
    if (i <= NU) g_cnt_u[i] = 0;
    if (i <= NI) g_cnt_i[i] = 0;
}
__global__ void count_kernel(const int* __restrict__ udst, const int* __restrict__ idst) {
    int e = blockIdx.x * blockDim.x + threadIdx.x;
    if (e < EU) atomicAdd(&g_cnt_u[udst[e]], 1);
    if (e < EI) atomicAdd(&g_cnt_i[idst[e]], 1);
}
__global__ void __launch_bounds__(1024) scan_a_kernel() {
    __shared__ int sm[1024];
    int t = threadIdx.x;
    int b = blockIdx.x;
    const int* cnt;  int* offs;  int* btot;  int N;  int lb;
    if (b < NBI_SC) { cnt = g_cnt_i; offs = g_off_i; btot = g_btot_i; N = NI; lb = b; }
    else            { cnt = g_cnt_u; offs = g_off_u; btot = g_btot_u; N = NU; lb = b - NBI_SC; }
    int i = lb * 1024 + t;
    int v = (i < N) ? cnt[i] : 0;
    sm[t] = v;
    __syncthreads();
#pragma unroll
    for (int s = 1; s < 1024; s <<= 1) {
        int u = (t >= s) ? sm[t - s] : 0;
        __syncthreads();
        sm[t] += u;
        __syncthreads();
    }
    if (i < N) offs[i] = sm[t] - v;
    if (t == 1023) btot[lb] = sm[1023];
}
__global__ void __launch_bounds__(128) scan_b_kernel() {
    __shared__ int sm[128];
    int t = threadIdx.x;
    int v = (t < NBI_SC) ? g_btot_i[t] : 0;
    sm[t] = v;
    __syncthreads();
#pragma unroll
    for (int s = 1; s < 128; s <<= 1) {
        int u = (t >= s) ? sm[t - s] : 0;
        __syncthreads();
        sm[t] += u;
        __syncthreads();
    }
    if (t < NBI_SC) g_btot_i[t] = sm[t] - v;
    __syncthreads();
    v = (t < NBU_SC) ? g_btot_u[t] : 0;
    sm[t] = v;
    __syncthreads();
#pragma unroll
    for (int s = 1; s < 128; s <<= 1) {
        int u = (t >= s) ? sm[t - s] : 0;
        __syncthreads();
        sm[t] += u;
        __syncthreads();
    }
    if (t < NBU_SC) g_btot_u[t] = sm[t] - v;
}
__global__ void scan_c_kernel() {
    int i = blockIdx.x * blockDim.x + threadIdx.x;
    if (i < NI) {
        int o = g_off_i[i] + g_btot_i[i >> 10];
        g_off_i[i] = o;  g_work_i[i] = o;
    }
    if (i < NU) {
        int o = g_off_u[i] + g_btot_u[i >> 10];
        g_off_u[i] = o;  g_work_u[i] = o;
    }
    if (i == 0) { g_off_i[NI] = EI; g_off_u[NU] = EU; }
}
__global__ void scatter_kernel(const int* __restrict__ uedg, const float* __restrict__ uev,
                               const int* __restrict__ iedg, const float* __restrict__ iev) {
    int e = blockIdx.x * blockDim.x + threadIdx.x;
    if (e < EU) {
        int p = atomicAdd(&g_work_u[uedg[EU + e]], 1);
        g_ced_u[p] = make_int2(uedg[e], __float_as_int(uev[e]));
    }
    if (e < EI) {
        int p = atomicAdd(&g_work_i[iedg[EI + e]], 1);
        g_ced_i[p] = make_int2(iedg[e], __float_as_int(iev[e]));
    }
}

// ---------------- merged BF16 3-term HMMA GEMM + attention scalars -------------
struct GemmArgs {
    const float* x;
    const uint32_t *wh, *wl;
    const float *as, *ad;
    __half* h;
    float *ssrc, *sdst;
    int N;
};

// smem (bytes): B hi/lo [128n][68 u32], A hi/lo [128r][68 u32], red buf
#define SB_BH   0
#define SB_BL   34816
#define SB_AH   69632
#define SB_AL   104448
#define SB_RED  139264
#define SMEM_TOT 143360

template <int ACT>
__global__ void __launch_bounds__(256, 1) gemm_mma_kernel(GemmArgs gi, GemmArgs gu)
{
    extern __shared__ char smem[];
    uint32_t* Bh = (uint32_t*)(smem + SB_BH);
    uint32_t* Bl = (uint32_t*)(smem + SB_BL);
    uint32_t* Ah = (uint32_t*)(smem + SB_AH);
    uint32_t* Al = (uint32_t*)(smem + SB_AL);
    float* red_s = (float*)(smem + SB_RED);
    float* red_d = red_s + 128 * 4;

    const GemmArgs& g = (blockIdx.x < NBI_G) ? gi : gu;
    const int blk = (blockIdx.x < NBI_G) ? blockIdx.x : (blockIdx.x - NBI_G);
    const float* __restrict__ x = g.x;
    const int N = g.N;

    const int tid = threadIdx.x;
    const int lane = tid & 31;
    const int wid = tid >> 5;
    const int wm = wid & 1;
    const int wn = wid >> 1;
    const int r0 = blk * 128;

    // stage B (both hi and lo), uint4 copies into stride-68 layout
    for (int i = tid; i < 2048; i += 256) {
        int n = i >> 4, k4 = (i & 15) * 4;
        *(uint4*)&Bh[n * 68 + k4] = *(const uint4*)&g.wh[n * 64 + k4];
        *(uint4*)&Bl[n * 68 + k4] = *(const uint4*)&g.wl[n * 64 + k4];
    }

    // stage full A tile (128 rows x 128 k): ELU + cheap truncation-based bf16 split
    {
        const int r = tid >> 1;
        const int half = tid & 1;
        const bool ok = (r0 + r < N);
        const float* xr = x + (size_t)(r0 + r) * DIM + half * 64;
#pragma unroll
        for (int q = 0; q < 16; ++q) {
            float4 v = ok ? *(const float4*)(xr + q * 4) : make_float4(0.f, 0.f, 0.f, 0.f);
            if (ACT) { v.x = elu_f(v.x); v.y = elu_f(v.y); v.z = elu_f(v.z); v.w = elu_f(v.w); }
            uint32_t ix = __float_as_uint(v.x), iy = __float_as_uint(v.y);
            uint32_t iz = __float_as_uint(v.z), iw = __float_as_uint(v.w);
            uint32_t hi01 = __byte_perm(ix, iy, 0x7632);
            uint32_t hi23 = __byte_perm(iz, iw, 0x7632);
            float l0 = v.x - __uint_as_float(ix & 0xFFFF0000u);
            float l1 = v.y - __uint_as_float(iy & 0xFFFF0000u);
            float l2 = v.z - __uint_as_float(iz & 0xFFFF0000u);
            float l3 = v.w - __uint_as_float(iw & 0xFFFF0000u);
            int o = r * 68 + half * 32 + q * 2;
            Ah[o] = hi01;  Ah[o + 1] = hi23;
            Al[o] = cvt_bf2(l0, l1);  Al[o + 1] = cvt_bf2(l2, l3);
        }
    }
    __syncthreads();

    float acc[4][4][4];
#pragma unroll
    for (int mt = 0; mt < 4; ++mt)
#pragma unroll
        for (int nt = 0; nt < 4; ++nt)
#pragma unroll
            for (int q = 0; q < 4; ++q) acc[mt][nt][q] = 0.f;

#pragma unroll
    for (int ks = 0; ks < 8; ++ks) {
        const int kk0 = ks * 8;
        uint32_t bh[4][2], bl[4][2];
#pragma unroll
        for (int nt = 0; nt < 4; ++nt) {
            int bn = wn * 32 + nt * 8 + (lane >> 2);
            bh[nt][0] = Bh[bn * 68 + kk0 + (lane & 3)];
            bh[nt][1] = Bh[bn * 68 + kk0 + 4 + (lane & 3)];
            bl[nt][0] = Bl[bn * 68 + kk0 + (lane & 3)];
            bl[nt][1] = Bl[bn * 68 + kk0 + 4 + (lane & 3)];
        }
        uint32_t ah[4][4], al[4][4];
#pragma unroll
        for (int mt = 0; mt < 4; ++mt) {
            int ar = wm * 64 + mt * 16 + (lane >> 2);
            ah[mt][0] = Ah[ar * 68 + kk0 + (lane & 3)];
            ah[mt][1] = Ah[(ar + 8) * 68 + kk0 + (lane & 3)];
            ah[mt][2] = Ah[ar * 68 + kk0 + 4 + (lane & 3)];
            ah[mt][3] = Ah[(ar + 8) * 68 + kk0 + 4 + (lane & 3)];
            al[mt][0] = Al[ar * 68 + kk0 + (lane & 3)];
            al[mt][1] = Al[(ar + 8) * 68 + kk0 + (lane & 3)];
            al[mt][2] = Al[ar * 68 + kk0 + 4 + (lane & 3)];
            al[mt][3] = Al[(ar + 8) * 68 + kk0 + 4 + (lane & 3)];
        }
#pragma unroll
        for (int mt = 0; mt < 4; ++mt)
#pragma unroll
            for (int nt = 0; nt < 4; ++nt) {
                mma_bf16(acc[mt][nt], ah[mt], bh[nt]);
                mma_bf16(acc[mt][nt], ah[mt], bl[nt]);
                mma_bf16(acc[mt][nt], al[mt], bh[nt]);
            }
    }

    // ---------------- epilogue: store h (fp16) + attention scalar dots ---------
    float asv[4][2], adv[4][2];
#pragma unroll
    for (int nt = 0; nt < 4; ++nt) {
        int c0 = wn * 32 + nt * 8 + 2 * (lane & 3);
        asv[nt][0] = g.as[c0];   asv[nt][1] = g.as[c0 + 1];
        adv[nt][0] = g.ad[c0];   adv[nt][1] = g.ad[c0 + 1];
    }

    float ps[8], pd[8];
#pragma unroll
    for (int q = 0; q < 8; ++q) { ps[q] = 0.f; pd[q] = 0.f; }

    __half* __restrict__ h = g.h;
#pragma unroll
    for (int mt = 0; mt < 4; ++mt) {
        int ar = r0 + wm * 64 + mt * 16 + (lane >> 2);
#pragma unroll
        for (int nt = 0; nt < 4; ++nt) {
            int c0 = wn * 32 + nt * 8 + 2 * (lane & 3);
            if (ar < N) {
                __half2 hv = __floats2half2_rn(acc[mt][nt][0], acc[mt][nt][1]);
                *(__half2*)(h + (size_t)ar * DIM + c0) = hv;
            }
            if (ar + 8 < N) {
                __half2 hv = __floats2half2_rn(acc[mt][nt][2], acc[mt][nt][3]);
                *(__half2*)(h + (size_t)(ar + 8) * DIM + c0) = hv;
            }
            ps[mt * 2 + 0] += acc[mt][nt][0] * asv[nt][0] + acc[mt][nt][1] * asv[nt][1];
            ps[mt * 2 + 1] += acc[mt][nt][2] * asv[nt][0] + acc[mt][nt][3] * asv[nt][1];
            pd[mt * 2 + 0] += acc[mt][nt][0] * adv[nt][0] + acc[mt][nt][1] * adv[nt][1];
            pd[mt * 2 + 1] += acc[mt][nt][2] * adv[nt][0] + acc[mt][nt][3] * adv[nt][1];
        }
    }
#pragma unroll
    for (int q = 0; q < 8; ++q) {
        ps[q] += __shfl_xor_sync(0xFFFFFFFF, ps[q], 1);
        ps[q] += __shfl_xor_sync(0xFFFFFFFF, ps[q], 2);
        pd[q] += __shfl_xor_sync(0xFFFFFFFF, pd[q], 1);
        pd[q] += __shfl_xor_sync(0xFFFFFFFF, pd[q], 2);
    }
    __syncthreads();
    if ((lane & 3) == 0) {
#pragma unroll
        for (int mt = 0; mt < 4; ++mt) {
            int rl0 = wm * 64 + mt * 16 + (lane >> 2);
            red_s[rl0 * 4 + wn] = ps[mt * 2 + 0];
            red_s[(rl0 + 8) * 4 + wn] = ps[mt * 2 + 1];
            red_d[rl0 * 4 + wn] = pd[mt * 2 + 0];
            red_d[(rl0 + 8) * 4 + wn] = pd[mt * 2 + 1];
        }
    }
    __syncthreads();
    if (tid < 128) {
        int row = r0 + tid;
        if (row < N) {
            float s = red_s[tid * 4] + red_s[tid * 4 + 1] + red_s[tid * 4 + 2] + red_s[tid * 4 + 3];
            float d = red_d[tid * 4] + red_d[tid * 4 + 1] + red_d[tid * 4 + 2] + red_d[tid * 4 + 3];
            g.ssrc[row] = s;
            g.sdst[row] = d;
        }
    }
}

// ---------------- merged CSR aggregate (both graphs per launch) ----------------
struct AggArgs {
    const int* off;
    const int2* ced;
    const float *ssrc, *sdst;
    const __half* h;
    float* out;
    int N;
};

__global__ void agg_csr_kernel(AggArgs ai, AggArgs au)
{
    const AggArgs& a = (blockIdx.x < AB_I) ? ai : au;
    const int blk = (blockIdx.x < AB_I) ? blockIdx.x : (blockIdx.x - AB_I);
    int lane = threadIdx.x & 31;
    int d = blk * 8 + (threadIdx.x >> 5);
    if (d >= a.N) return;
    const int o0 = a.off[d], o1 = a.off[d + 1];
    const float sd = a.sdst[d];
    const __half* __restrict__ h = a.h;

    float4 acc = make_float4(0.f, 0.f, 0.f, 0.f);
    float denom = 0.f;

    for (int base = o0; base < o1; base += 32) {
        int idx = base + lane;
        float e = 0.f;
        int s = 0;
        if (idx < o1) {
            int2 se = a.ced[idx];
            s = se.x;
            float l = a.ssrc[s] + sd;
            l = l > 0.f ? l : 0.2f * l;
            e = __expf(l) * __int_as_float(se.y);
        }
        float esum = e;
#pragma unroll
        for (int m = 16; m; m >>= 1) esum += __shfl_xor_sync(0xFFFFFFFF, esum, m);
        denom += esum;

        int cnt = min(32, o1 - base);
        int k = 0;
        // MLP batch of 4: issue 4 independent row loads before accumulating
        for (; k + 4 <= cnt; k += 4) {
            float c0 = __shfl_sync(0xFFFFFFFF, e, k);
            float c1 = __shfl_sync(0xFFFFFFFF, e, k + 1);
            float c2 = __shfl_sync(0xFFFFFFFF, e, k + 2);
            float c3 = __shfl_sync(0xFFFFFFFF, e, k + 3);
            int s0 = __shfl_sync(0xFFFFFFFF, s, k);
            int s1 = __shfl_sync(0xFFFFFFFF, s, k + 1);
            int s2 = __shfl_sync(0xFFFFFFFF, s, k + 2);
            int s3 = __shfl_sync(0xFFFFFFFF, s, k + 3);
            float4 v0 = load_h4(h + (size_t)s0 * DIM + lane * 4);
            float4 v1 = load_h4(h + (size_t)s1 * DIM + lane * 4);
            float4 v2 = load_h4(h + (size_t)s2 * DIM + lane * 4);
            float4 v3 = load_h4(h + (size_t)s3 * DIM + lane * 4);
            acc.x += c0 * v0.x + c1 * v1.x + c2 * v2.x + c3 * v3.x;
            acc.y += c0 * v0.y + c1 * v1.y + c2 * v2.y + c3 * v3.y;
            acc.z += c0 * v0.z + c1 * v1.z + c2 * v2.z + c3 * v3.z;
            acc.w += c0 * v0.w + c1 * v1.w + c2 * v2.w + c3 * v3.w;
        }
        for (; k < cnt; ++k) {
            float coef = __shfl_sync(0xFFFFFFFF, e, k);
            int sk = __shfl_sync(0xFFFFFFFF, s, k);
            float4 v = load_h4(h + (size_t)sk * DIM + lane * 4);
            acc.x += coef * v.x; acc.y += coef * v.y;
            acc.z += coef * v.z; acc.w += coef * v.w;
        }
    }
    float inv = 1.f / (denom + 1e-16f);
    acc.x *= inv; acc.y *= inv; acc.z *= inv; acc.w *= inv;
    *(float4*)(a.out + (size_t)d * DIM + lane * 4) = acc;
}

// ---------------- final gather (deferred elu applied here) ----------------------
__global__ void gather_kernel(const float* __restrict__ uo, const float* __restrict__ io,
                              const int* __restrict__ uid, const int* __restrict__ iid,
                              float* __restrict__ out)
{
    int t = blockIdx.x * blockDim.x + threadIdx.x;
    int b = t >> 7, c = t & 127;
    if (b < BATCH)          out[t] = elu_f(uo[(size_t)uid[b] * DIM + c]);
    else if (b < 2 * BATCH) out[t] = elu_f(io[(size_t)iid[b - BATCH] * DIM + c]);
}

// ---------------- host orchestration -------------------------------------------
extern "C" void kernel_launch(void* const* d_in, const int* in_sizes, int n_in,
                              void* d_out, int out_size)
{
    const int*   uedg = (const int*)d_in[0];
    const int*   iedg = (const int*)d_in[1];
    const int*   user_id = (const int*)d_in[2];
    const int*   item_id = (const int*)d_in[3];
    const float* uval = (const float*)d_in[4];
    const float* ival = (const float*)d_in[5];
    const float* umat = (const float*)d_in[6];
    const float* imat = (const float*)d_in[7];
    const float* W_u1 = (const float*)d_in[8];
    const float* as_u1 = (const float*)d_in[9];
    const float* ad_u1 = (const float*)d_in[10];
    const float* W_u2 = (const float*)d_in[11];
    const float* as_u2 = (const float*)d_in[12];
    const float* ad_u2 = (const float*)d_in[13];
    const float* W_i1 = (const float*)d_in[14];
    const float* as_i1 = (const float*)d_in[15];
    const float* ad_i1 = (const float*)d_in[16];
    const float* W_i2 = (const float*)d_in[17];
    const float* as_i2 = (const float*)d_in[18];
    const float* ad_i2 = (const float*)d_in[19];

    __half *h_u, *h_i;
    float *out1_u, *out1_i, *uout2, *iout2;
    float *ssrc_u, *sdst_u, *ssrc_i, *sdst_i;
    uint32_t *wph, *wpl;
    int *off_u, *off_i;
    int2 *ced_u, *ced_i;
    cudaGetSymbolAddress((void**)&h_u, g_h_u);
    cudaGetSymbolAddress((void**)&h_i, g_h_i);
    cudaGetSymbolAddress((void**)&out1_u, g_out1_u);
    cudaGetSymbolAddress((void**)&out1_i, g_out1_i);
    cudaGetSymbolAddress((void**)&uout2, g_uout2);
    cudaGetSymbolAddress((void**)&iout2, g_iout2);
    cudaGetSymbolAddress((void**)&ssrc_u, g_ssrc_u);
    cudaGetSymbolAddress((void**)&sdst_u, g_sdst_u);
    cudaGetSymbolAddress((void**)&ssrc_i, g_ssrc_i);
    cudaGetSymbolAddress((void**)&sdst_i, g_sdst_i);
    cudaGetSymbolAddress((void**)&wph, g_wp_hi);
    cudaGetSymbolAddress((void**)&wpl, g_wp_lo);
    cudaGetSymbolAddress((void**)&off_u, g_off_u);
    cudaGetSymbolAddress((void**)&off_i, g_off_i);
    cudaGetSymbolAddress((void**)&ced_u, g_ced_u);
    cudaGetSymbolAddress((void**)&ced_i, g_ced_i);

    cudaFuncSetAttribute(gemm_mma_kernel<0>, cudaFuncAttributeMaxDynamicSharedMemorySize, SMEM_TOT);
    cudaFuncSetAttribute(gemm_mma_kernel<1>, cudaFuncAttributeMaxDynamicSharedMemorySize, SMEM_TOT);

    // one-time side-stream + events (resources only; per-call work is identical)
    static cudaStream_t s2 = nullptr;
    static cudaEvent_t evF = nullptr, evC = nullptr;
    if (!s2) {
        cudaStreamCreateWithFlags(&s2, cudaStreamNonBlocking);
        cudaEventCreateWithFlags(&evF, cudaEventDisableTiming);
        cudaEventCreateWithFlags(&evC, cudaEventDisableTiming);
    }

    const int TB = 256;
    const int WSTRIDE = DIM * 64;

    // fork: CSR build on side stream, overlapped with prep + GEMM1
    cudaEventRecord(evF, 0);
    cudaStreamWaitEvent(s2, evF, 0);

    zero_cnt_kernel<<<(NU + TB) / TB, TB, 0, s2>>>();
    count_kernel<<<(EU + TB - 1) / TB, TB, 0, s2>>>(uedg + EU, iedg + EI);
    scan_a_kernel<<<NBI_SC + NBU_SC, 1024, 0, s2>>>();
    scan_b_kernel<<<1, 128, 0, s2>>>();
    scan_c_kernel<<<(NU + TB - 1) / TB, TB, 0, s2>>>();
    scatter_kernel<<<(EU + TB - 1) / TB, TB, 0, s2>>>(uedg, uval, iedg, ival);
    cudaEventRecord(evC, s2);

    // main stream: weight prep + layer-1 GEMM (independent of CSR)
    prep_w_kernel<<<4 * DIM * 64 / TB, TB>>>(W_i1, W_i2, W_u1, W_u2);

    GemmArgs gi1 = { imat, wph + 0 * WSTRIDE, wpl + 0 * WSTRIDE, as_i1, ad_i1,
                     h_i, ssrc_i, sdst_i, NI };
    GemmArgs gu1 = { umat, wph + 2 * WSTRIDE, wpl + 2 * WSTRIDE, as_u1, ad_u1,
                     h_u, ssrc_u, sdst_u, NU };
    gemm_mma_kernel<0><<<NBI_G + NBU_G, 256, SMEM_TOT>>>(gi1, gu1);

    // join: agg needs the CSR
    cudaStreamWaitEvent(0, evC, 0);

    AggArgs ai1 = { off_i, ced_i, ssrc_i, sdst_i, h_i, out1_i, NI };
    AggArgs au1 = { off_u, ced_u, ssrc_u, sdst_u, h_u, out1_u, NU };
    agg_csr_kernel<<<AB_I + AB_U, 256>>>(ai1, au1);

    // ---- layer 2 (both graphs merged) ----
    GemmArgs gi2 = { out1_i, wph + 1 * WSTRIDE, wpl + 1 * WSTRIDE, as_i2, ad_i2,
                     h_i, ssrc_i, sdst_i, NI };
    GemmArgs gu2 = { out1_u, wph + 3 * WSTRIDE, wpl + 3 * WSTRIDE, as_u2, ad_u2,
                     h_u, ssrc_u, sdst_u, NU };
    gemm_mma_kernel<1><<<NBI_G + NBU_G, 256, SMEM_TOT>>>(gi2, gu2);

    AggArgs ai2 = { off_i, ced_i, ssrc_i, sdst_i, h_i, iout2, NI };
    AggArgs au2 = { off_u, ced_u, ssrc_u, sdst_u, h_u, uout2, NU };
    agg_csr_kernel<<<AB_I + AB_U, 256>>>(ai2, au2);

    gather_kernel<<<(2 * BATCH * DIM) / TB, TB>>>(uout2, iout2, user_id, item_id, (float*)d_out);
}

// round 12
// speedup vs baseline: 1.5899x; 1.0638x over previous
#include <cuda_runtime.h>
#include <cuda_bf16.h>
#include <cuda_fp16.h>
#include <cstdint>
#include <cfloat>

#define NU 100000
#define NI 50000
#define DIM 128
#define EU 400000
#define EI 200000
#define BATCH 4096

#define GB_U ((NU + 127) / 128)        // 782 gemm blocks (user)
#define GB_I ((NI + 127) / 128)        // 391 gemm blocks (item)
#define NBI_SC ((NI + 1023) / 1024)    // 49 scan blocks (item)
#define NBU_SC ((NU + 1023) / 1024)    // 98 scan blocks (user)
#define AGB_U ((NU + 7) / 8)           // agg blocks (user)
#define AGB_I ((NI + 7) / 8)           // agg blocks (item)

// ---------------- scratch (static device memory) ------------------------------
__device__ __half g_h_u[NU * DIM];          // h fp16 (agg is sole consumer)
__device__ __half g_h_i[NI * DIM];
__device__ __half g_out1_u[NU * DIM];       // layer-1 out fp16 (GEMM2 sole consumer)
__device__ __half g_out1_i[NI * DIM];
__device__ float g_uout2[NU * DIM];
__device__ float g_iout2[NI * DIM];
__device__ float g_ssrc_u[NU], g_sdst_u[NU];
__device__ float g_ssrc_i[NI], g_sdst_i[NI];
__device__ uint32_t g_wp_hi[4][DIM * 64];   // W^T [n][k-pair] bf16x2, hi part
__device__ uint32_t g_wp_lo[4][DIM * 64];   // residual lo part
// CSR (both graphs persist)
__device__ int   g_cnt_u[NU + 1], g_cnt_i[NI + 1];
__device__ int   g_off_u[NU + 1], g_off_i[NI + 1];
__device__ int   g_btot_u[NBU_SC], g_btot_i[NBI_SC];
__device__ int   g_work_u[NU], g_work_i[NI];
__device__ int2  g_ced_u[EU], g_ced_i[EI];  // packed (src, ev bits)

// ---------------- helpers ------------------------------------------------------
__device__ __forceinline__ float elu_f(float x) {
    return x > 0.f ? x : __expf(x) - 1.f;
}
__device__ __forceinline__ uint32_t pack_bf2(__nv_bfloat16 a, __nv_bfloat16 b) {
    return ((uint32_t)__bfloat16_as_ushort(b) << 16) | (uint32_t)__bfloat16_as_ushort(a);
}
__device__ __forceinline__ uint32_t cvt_bf2(float lo0, float lo1) {
    uint32_t r;
    asm("cvt.rn.bf16x2.f32 %0, %1, %2;" : "=r"(r) : "f"(lo1), "f"(lo0));
    return r;
}
__device__ __forceinline__ void mma_bf16(float* d, const uint32_t* a, const uint32_t* b) {
    asm volatile(
        "mma.sync.aligned.m16n8k16.row.col.f32.bf16.bf16.f32 "
        "{%0,%1,%2,%3}, {%4,%5,%6,%7}, {%8,%9}, {%0,%1,%2,%3};"
        : "+f"(d[0]), "+f"(d[1]), "+f"(d[2]), "+f"(d[3])
        : "r"(a[0]), "r"(a[1]), "r"(a[2]), "r"(a[3]), "r"(b[0]), "r"(b[1]));
}
__device__ __forceinline__ float4 load_h4(const __half* p) {
    uint2 raw = *(const uint2*)p;
    float2 f0 = __half22float2(*(__half2*)&raw.x);
    float2 f1 = __half22float2(*(__half2*)&raw.y);
    return make_float4(f0.x, f0.y, f1.x, f1.y);
}

// ---------------- W^T hi/lo prep (bf16 split, packed pairs) --------------------
__global__ void prep_w_kernel(const float* __restrict__ w0, const float* __restrict__ w1,
                              const float* __restrict__ w2, const float* __restrict__ w3) {
    int i = blockIdx.x * blockDim.x + threadIdx.x;     // 4*128*64
    int l = i >> 13;
    int j = i & 8191;
    int n = j >> 6, kk = j & 63;
    const float* W = (l == 0) ? w0 : (l == 1) ? w1 : (l == 2) ? w2 : w3;
    float a = W[(2 * kk) * DIM + n];
    float b = W[(2 * kk + 1) * DIM + n];
    __nv_bfloat16 ha = __float2bfloat16(a);
    __nv_bfloat16 hb = __float2bfloat16(b);
    __nv_bfloat16 la = __float2bfloat16(a - __bfloat162float(ha));
    __nv_bfloat16 lb = __float2bfloat16(b - __bfloat162float(hb));
    g_wp_hi[l][n * 64 + kk] = pack_bf2(ha, hb);
    g_wp_lo[l][n * 64 + kk] = pack_bf2(la, lb);
}

// ---------------- merged CSR build (both graphs per launch) --------------------
__global__ void zero_cnt_kernel() {
    int i = blockIdx.x * blockDim.x + threadIdx.x;
    if (i <= NU) g_cnt_u[i] = 0;
    if (i <= NI) g_cnt_i[i] = 0;
}
__global__ void count_kernel(const int* __restrict__ udst, const int* __restrict__ idst) {
    int e = blockIdx.x * blockDim.x + threadIdx.x;
    if (e < EU) atomicAdd(&g_cnt_u[udst[e]], 1);
    if (e < EI) atomicAdd(&g_cnt_i[idst[e]], 1);
}
__global__ void __launch_bounds__(1024) scan_a_kernel() {
    __shared__ int sm[1024];
    int t = threadIdx.x;
    int b = blockIdx.x;
    const int* cnt;  int* offs;  int* btot;  int N;  int lb;
    if (b < NBI_SC) { cnt = g_cnt_i; offs = g_off_i; btot = g_btot_i; N = NI; lb = b; }
    else            { cnt = g_cnt_u; offs = g_off_u; btot = g_btot_u; N = NU; lb = b - NBI_SC; }
    int i = lb * 1024 + t;
    int v = (i < N) ? cnt[i] : 0;
    sm[t] = v;
    __syncthreads();
#pragma unroll
    for (int s = 1; s < 1024; s <<= 1) {
        int u = (t >= s) ? sm[t - s] : 0;
        __syncthreads();
        sm[t] += u;
        __syncthreads();
    }
    if (i < N) offs[i] = sm[t] - v;
    if (t == 1023) btot[lb] = sm[1023];
}
__global__ void __launch_bounds__(128) scan_b_kernel() {
    __shared__ int sm[128];
    int t = threadIdx.x;
    int v = (t < NBI_SC) ? g_btot_i[t] : 0;
    sm[t] = v;
    __syncthreads();
#pragma unroll
    for (int s = 1; s < 128; s <<= 1) {
        int u = (t >= s) ? sm[t - s] : 0;
        __syncthreads();
        sm[t] += u;
        __syncthreads();
    }
    if (t < NBI_SC) g_btot_i[t] = sm[t] - v;
    __syncthreads();
    v = (t < NBU_SC) ? g_btot_u[t] : 0;
    sm[t] = v;
    __syncthreads();
#pragma unroll
    for (int s = 1; s < 128; s <<= 1) {
        int u = (t >= s) ? sm[t - s] : 0;
        __syncthreads();
        sm[t] += u;
        __syncthreads();
    }
    if (t < NBU_SC) g_btot_u[t] = sm[t] - v;
}
__global__ void scan_c_kernel() {
    int i = blockIdx.x * blockDim.x + threadIdx.x;
    if (i < NI) {
        int o = g_off_i[i] + g_btot_i[i >> 10];
        g_off_i[i] = o;  g_work_i[i] = o;
    }
    if (i < NU) {
        int o = g_off_u[i] + g_btot_u[i >> 10];
        g_off_u[i] = o;  g_work_u[i] = o;
    }
    if (i == 0) { g_off_i[NI] = EI; g_off_u[NU] = EU; }
}
__global__ void scatter_kernel(const int* __restrict__ uedg, const float* __restrict__ uev,
                               const int* __restrict__ iedg, const float* __restrict__ iev) {
    int e = blockIdx.x * blockDim.x + threadIdx.x;
    if (e < EU) {
        int p = atomicAdd(&g_work_u[uedg[EU + e]], 1);
        g_ced_u[p] = make_int2(uedg[e], __float_as_int(uev[e]));
    }
    if (e < EI) {
        int p = atomicAdd(&g_work_i[iedg[EI + e]], 1);
        g_ced_i[p] = make_int2(iedg[e], __float_as_int(iev[e]));
    }
}

// ---------------- BF16 3-term HMMA GEMM + attention scalars (per-graph) --------
struct GemmArgs {
    const void* x;                 // fp32 (layer1) or fp16 (layer2)
    const uint32_t *wh, *wl;
    const float *as, *ad;
    __half* h;
    float *ssrc, *sdst;
    int N;
};

// smem (bytes): B hi/lo [128n][68 u32], A hi/lo [128r][68 u32], red buf
#define SB_BH   0
#define SB_BL   34816
#define SB_AH   69632
#define SB_AL   104448
#define SB_RED  139264
#define SMEM_TOT 143360

template <int ACT, int INH>
__global__ void __launch_bounds__(256, 1) gemm_mma_kernel(GemmArgs g)
{
    extern __shared__ char smem[];
    uint32_t* Bh = (uint32_t*)(smem + SB_BH);
    uint32_t* Bl = (uint32_t*)(smem + SB_BL);
    uint32_t* Ah = (uint32_t*)(smem + SB_AH);
    uint32_t* Al = (uint32_t*)(smem + SB_AL);
    float* red_s = (float*)(smem + SB_RED);
    float* red_d = red_s + 128 * 4;

    const int N = g.N;
    const int tid = threadIdx.x;
    const int lane = tid & 31;
    const int wid = tid >> 5;
    const int wm = wid & 1;
    const int wn = wid >> 1;
    const int r0 = blockIdx.x * 128;

    // stage B (both hi and lo), uint4 copies into stride-68 layout
    for (int i = tid; i < 2048; i += 256) {
        int n = i >> 4, k4 = (i & 15) * 4;
        *(uint4*)&Bh[n * 68 + k4] = *(const uint4*)&g.wh[n * 64 + k4];
        *(uint4*)&Bl[n * 68 + k4] = *(const uint4*)&g.wl[n * 64 + k4];
    }

    // stage full A tile (128 rows x 128 k): ELU + truncation-based bf16 split
    {
        const int r = tid >> 1;
        const int half = tid & 1;
        const bool ok = (r0 + r < N);
        const size_t roff = (size_t)(r0 + r) * DIM + half * 64;
        const float* xf = (const float*)g.x + roff;
        const __half* xh = (const __half*)g.x + roff;
#pragma unroll
        for (int q = 0; q < 16; ++q) {
            float4 v = make_float4(0.f, 0.f, 0.f, 0.f);
            if (ok) v = INH ? load_h4(xh + q * 4) : *(const float4*)(xf + q * 4);
            if (ACT) { v.x = elu_f(v.x); v.y = elu_f(v.y); v.z = elu_f(v.z); v.w = elu_f(v.w); }
            uint32_t ix = __float_as_uint(v.x), iy = __float_as_uint(v.y);
            uint32_t iz = __float_as_uint(v.z), iw = __float_as_uint(v.w);
            uint32_t hi01 = __byte_perm(ix, iy, 0x7632);
            uint32_t hi23 = __byte_perm(iz, iw, 0x7632);
            float l0 = v.x - __uint_as_float(ix & 0xFFFF0000u);
            float l1 = v.y - __uint_as_float(iy & 0xFFFF0000u);
            float l2 = v.z - __uint_as_float(iz & 0xFFFF0000u);
            float l3 = v.w - __uint_as_float(iw & 0xFFFF0000u);
            int o = r * 68 + half * 32 + q * 2;
            Ah[o] = hi01;  Ah[o + 1] = hi23;
            Al[o] = cvt_bf2(l0, l1);  Al[o + 1] = cvt_bf2(l2, l3);
        }
    }
    __syncthreads();

    float acc[4][4][4];
#pragma unroll
    for (int mt = 0; mt < 4; ++mt)
#pragma unroll
        for (int nt = 0; nt < 4; ++nt)
#pragma unroll
            for (int q = 0; q < 4; ++q) acc[mt][nt][q] = 0.f;

#pragma unroll
    for (int ks = 0; ks < 8; ++ks) {
        const int kk0 = ks * 8;
        uint32_t bh[4][2], bl[4][2];
#pragma unroll
        for (int nt = 0; nt < 4; ++nt) {
            int bn = wn * 32 + nt * 8 + (lane >> 2);
            bh[nt][0] = Bh[bn * 68 + kk0 + (lane & 3)];
            bh[nt][1] = Bh[bn * 68 + kk0 + 4 + (lane & 3)];
            bl[nt][0] = Bl[bn * 68 + kk0 + (lane & 3)];
            bl[nt][1] = Bl[bn * 68 + kk0 + 4 + (lane & 3)];
        }
        uint32_t ah[4][4], al[4][4];
#pragma unroll
        for (int mt = 0; mt < 4; ++mt) {
            int ar = wm * 64 + mt * 16 + (lane >> 2);
            ah[mt][0] = Ah[ar * 68 + kk0 + (lane & 3)];
            ah[mt][1] = Ah[(ar + 8) * 68 + kk0 + (lane & 3)];
            ah[mt][2] = Ah[ar * 68 + kk0 + 4 + (lane & 3)];
            ah[mt][3] = Ah[(ar + 8) * 68 + kk0 + 4 + (lane & 3)];
            al[mt][0] = Al[ar * 68 + kk0 + (lane & 3)];
            al[mt][1] = Al[(ar + 8) * 68 + kk0 + (lane & 3)];
            al[mt][2] = Al[ar * 68 + kk0 + 4 + (lane & 3)];
            al[mt][3] = Al[(ar + 8) * 68 + kk0 + 4 + (lane & 3)];
        }
#pragma unroll
        for (int mt = 0; mt < 4; ++mt)
#pragma unroll
            for (int nt = 0; nt < 4; ++nt) {
                mma_bf16(acc[mt][nt], ah[mt], bh[nt]);
                mma_bf16(acc[mt][nt], ah[mt], bl[nt]);
                mma_bf16(acc[mt][nt], al[mt], bh[nt]);
            }
    }

    // ---------------- epilogue: store h (fp16) + attention scalar dots ---------
    float asv[4][2], adv[4][2];
#pragma unroll
    for (int nt = 0; nt < 4; ++nt) {
        int c0 = wn * 32 + nt * 8 + 2 * (lane & 3);
        asv[nt][0] = g.as[c0];   asv[nt][1] = g.as[c0 + 1];
        adv[nt][0] = g.ad[c0];   adv[nt][1] = g.ad[c0 + 1];
    }

    float ps[8], pd[8];
#pragma unroll
    for (int q = 0; q < 8; ++q) { ps[q] = 0.f; pd[q] = 0.f; }

    __half* __restrict__ h = g.h;
#pragma unroll
    for (int mt = 0; mt < 4; ++mt) {
        int ar = r0 + wm * 64 + mt * 16 + (lane >> 2);
#pragma unroll
        for (int nt = 0; nt < 4; ++nt) {
            int c0 = wn * 32 + nt * 8 + 2 * (lane & 3);
            if (ar < N) {
                __half2 hv = __floats2half2_rn(acc[mt][nt][0], acc[mt][nt][1]);
                *(__half2*)(h + (size_t)ar * DIM + c0) = hv;
            }
            if (ar + 8 < N) {
                __half2 hv = __floats2half2_rn(acc[mt][nt][2], acc[mt][nt][3]);
                *(__half2*)(h + (size_t)(ar + 8) * DIM + c0) = hv;
            }
            ps[mt * 2 + 0] += acc[mt][nt][0] * asv[nt][0] + acc[mt][nt][1] * asv[nt][1];
            ps[mt * 2 + 1] += acc[mt][nt][2] * asv[nt][0] + acc[mt][nt][3] * asv[nt][1];
            pd[mt * 2 + 0] += acc[mt][nt][0] * adv[nt][0] + acc[mt][nt][1] * adv[nt][1];
            pd[mt * 2 + 1] += acc[mt][nt][2] * adv[nt][0] + acc[mt][nt][3] * adv[nt][1];
        }
    }
#pragma unroll
    for (int q = 0; q < 8; ++q) {
        ps[q] += __shfl_xor_sync(0xFFFFFFFF, ps[q], 1);
        ps[q] += __shfl_xor_sync(0xFFFFFFFF, ps[q], 2);
        pd[q] += __shfl_xor_sync(0xFFFFFFFF, pd[q], 1);
        pd[q] += __shfl_xor_sync(0xFFFFFFFF, pd[q], 2);
    }
    __syncthreads();
    if ((lane & 3) == 0) {
#pragma unroll
        for (int mt = 0; mt < 4; ++mt) {
            int rl0 = wm * 64 + mt * 16 + (lane >> 2);
            red_s[rl0 * 4 + wn] = ps[mt * 2 + 0];
            red_s[(rl0 + 8) * 4 + wn] = ps[mt * 2 + 1];
            red_d[rl0 * 4 + wn] = pd[mt * 2 + 0];
            red_d[(rl0 + 8) * 4 + wn] = pd[mt * 2 + 1];
        }
    }
    __syncthreads();
    if (tid < 128) {
        int row = r0 + tid;
        if (row < N) {
            float s = red_s[tid * 4] + red_s[tid * 4 + 1] + red_s[tid * 4 + 2] + red_s[tid * 4 + 3];
            float d = red_d[tid * 4] + red_d[tid * 4 + 1] + red_d[tid * 4 + 2] + red_d[tid * 4 + 3];
            g.ssrc[row] = s;
            g.sdst[row] = d;
        }
    }
}

// ---------------- CSR aggregate (per-graph) ------------------------------------
struct AggArgs {
    const int* off;
    const int2* ced;
    const float *ssrc, *sdst;
    const __half* h;
    void* out;                     // fp16 (layer1) or fp32 (layer2)
    int N;
};

template <int OUTH>
__global__ void agg_csr_kernel(AggArgs a)
{
    int lane = threadIdx.x & 31;
    int d = blockIdx.x * 8 + (threadIdx.x >> 5);
    if (d >= a.N) return;
    const int o0 = a.off[d], o1 = a.off[d + 1];
    const float sd = a.sdst[d];
    const __half* __restrict__ h = a.h;

    float4 acc = make_float4(0.f, 0.f, 0.f, 0.f);
    float denom = 0.f;

    for (int base = o0; base < o1; base += 32) {
        int idx = base + lane;
        float e = 0.f;
        int s = 0;
        if (idx < o1) {
            int2 se = a.ced[idx];
            s = se.x;
            float l = a.ssrc[s] + sd;
            l = l > 0.f ? l : 0.2f * l;
            e = __expf(l) * __int_as_float(se.y);
        }
        float esum = e;
#pragma unroll
        for (int m = 16; m; m >>= 1) esum += __shfl_xor_sync(0xFFFFFFFF, esum, m);
        denom += esum;

        int cnt = min(32, o1 - base);
        int k = 0;
        for (; k + 4 <= cnt; k += 4) {
            float c0 = __shfl_sync(0xFFFFFFFF, e, k);
            float c1 = __shfl_sync(0xFFFFFFFF, e, k + 1);
            float c2 = __shfl_sync(0xFFFFFFFF, e, k + 2);
            float c3 = __shfl_sync(0xFFFFFFFF, e, k + 3);
            int s0 = __shfl_sync(0xFFFFFFFF, s, k);
            int s1 = __shfl_sync(0xFFFFFFFF, s, k + 1);
            int s2 = __shfl_sync(0xFFFFFFFF, s, k + 2);
            int s3 = __shfl_sync(0xFFFFFFFF, s, k + 3);
            float4 v0 = load_h4(h + (size_t)s0 * DIM + lane * 4);
            float4 v1 = load_h4(h + (size_t)s1 * DIM + lane * 4);
            float4 v2 = load_h4(h + (size_t)s2 * DIM + lane * 4);
            float4 v3 = load_h4(h + (size_t)s3 * DIM + lane * 4);
            acc.x += c0 * v0.x + c1 * v1.x + c2 * v2.x + c3 * v3.x;
            acc.y += c0 * v0.y + c1 * v1.y + c2 * v2.y + c3 * v3.y;
            acc.z += c0 * v0.z + c1 * v1.z + c2 * v2.z + c3 * v3.z;
            acc.w += c0 * v0.w + c1 * v1.w + c2 * v2.w + c3 * v3.w;
        }
        for (; k < cnt; ++k) {
            float coef = __shfl_sync(0xFFFFFFFF, e, k);
            int sk = __shfl_sync(0xFFFFFFFF, s, k);
            float4 v = load_h4(h + (size_t)sk * DIM + lane * 4);
            acc.x += coef * v.x; acc.y += coef * v.y;
            acc.z += coef * v.z; acc.w += coef * v.w;
        }
    }
    float inv = 1.f / (denom + 1e-16f);
    acc.x *= inv; acc.y *= inv; acc.z *= inv; acc.w *= inv;
    if (OUTH) {
        __half2 p0 = __floats2half2_rn(acc.x, acc.y);
        __half2 p1 = __floats2half2_rn(acc.z, acc.w);
        uint2 pk;
        pk.x = *(uint32_t*)&p0;  pk.y = *(uint32_t*)&p1;
        *(uint2*)((__half*)a.out + (size_t)d * DIM + lane * 4) = pk;
    } else {
        *(float4*)((float*)a.out + (size_t)d * DIM + lane * 4) = acc;
    }
}

// ---------------- final gather (deferred elu applied here) ----------------------
__global__ void gather_kernel(const float* __restrict__ uo, const float* __restrict__ io,
                              const int* __restrict__ uid, const int* __restrict__ iid,
                              float* __restrict__ out)
{
    int t = blockIdx.x * blockDim.x + threadIdx.x;
    int b = t >> 7, c = t & 127;
    if (b < BATCH)          out[t] = elu_f(uo[(size_t)uid[b] * DIM + c]);
    else if (b < 2 * BATCH) out[t] = elu_f(io[(size_t)iid[b - BATCH] * DIM + c]);
}

// ---------------- host orchestration -------------------------------------------
extern "C" void kernel_launch(void* const* d_in, const int* in_sizes, int n_in,
                              void* d_out, int out_size)
{
    const int*   uedg = (const int*)d_in[0];
    const int*   iedg = (const int*)d_in[1];
    const int*   user_id = (const int*)d_in[2];
    const int*   item_id = (const int*)d_in[3];
    const float* uval = (const float*)d_in[4];
    const float* ival = (const float*)d_in[5];
    const float* umat = (const float*)d_in[6];
    const float* imat = (const float*)d_in[7];
    const float* W_u1 = (const float*)d_in[8];
    const float* as_u1 = (const float*)d_in[9];
    const float* ad_u1 = (const float*)d_in[10];
    const float* W_u2 = (const float*)d_in[11];
    const float* as_u2 = (const float*)d_in[12];
    const float* ad_u2 = (const float*)d_in[13];
    const float* W_i1 = (const float*)d_in[14];
    const float* as_i1 = (const float*)d_in[15];
    const float* ad_i1 = (const float*)d_in[16];
    const float* W_i2 = (const float*)d_in[17];
    const float* as_i2 = (const float*)d_in[18];
    const float* ad_i2 = (const float*)d_in[19];

    __half *h_u, *h_i, *out1_u, *out1_i;
    float *uout2, *iout2;
    float *ssrc_u, *sdst_u, *ssrc_i, *sdst_i;
    uint32_t *wph, *wpl;
    int *off_u, *off_i;
    int2 *ced_u, *ced_i;
    cudaGetSymbolAddress((void**)&h_u, g_h_u);
    cudaGetSymbolAddress((void**)&h_i, g_h_i);
    cudaGetSymbolAddress((void**)&out1_u, g_out1_u);
    cudaGetSymbolAddress((void**)&out1_i, g_out1_i);
    cudaGetSymbolAddress((void**)&uout2, g_uout2);
    cudaGetSymbolAddress((void**)&iout2, g_iout2);
    cudaGetSymbolAddress((void**)&ssrc_u, g_ssrc_u);
    cudaGetSymbolAddress((void**)&sdst_u, g_sdst_u);
    cudaGetSymbolAddress((void**)&ssrc_i, g_ssrc_i);
    cudaGetSymbolAddress((void**)&sdst_i, g_sdst_i);
    cudaGetSymbolAddress((void**)&wph, g_wp_hi);
    cudaGetSymbolAddress((void**)&wpl, g_wp_lo);
    cudaGetSymbolAddress((void**)&off_u, g_off_u);
    cudaGetSymbolAddress((void**)&off_i, g_off_i);
    cudaGetSymbolAddress((void**)&ced_u, g_ced_u);
    cudaGetSymbolAddress((void**)&ced_i, g_ced_i);

    cudaFuncSetAttribute(gemm_mma_kernel<0, 0>, cudaFuncAttributeMaxDynamicSharedMemorySize, SMEM_TOT);
    cudaFuncSetAttribute(gemm_mma_kernel<1, 1>, cudaFuncAttributeMaxDynamicSharedMemorySize, SMEM_TOT);

    // one-time side streams + events
    static cudaStream_t s2 = nullptr, s3 = nullptr;
    static cudaEvent_t evF = nullptr, evC = nullptr, evP = nullptr, evI = nullptr;
    if (!s2) {
        cudaStreamCreateWithFlags(&s2, cudaStreamNonBlocking);
        cudaStreamCreateWithFlags(&s3, cudaStreamNonBlocking);
        cudaEventCreateWithFlags(&evF, cudaEventDisableTiming);
        cudaEventCreateWithFlags(&evC, cudaEventDisableTiming);
        cudaEventCreateWithFlags(&evP, cudaEventDisableTiming);
        cudaEventCreateWithFlags(&evI, cudaEventDisableTiming);
    }

    const int TB = 256;
    const int WSTRIDE = DIM * 64;

    // fork: CSR build on s2, overlapped with prep + GEMM1s
    cudaEventRecord(evF, 0);
    cudaStreamWaitEvent(s2, evF, 0);

    zero_cnt_kernel<<<(NU + TB) / TB, TB, 0, s2>>>();
    count_kernel<<<(EU + TB - 1) / TB, TB, 0, s2>>>(uedg + EU, iedg + EI);
    scan_a_kernel<<<NBI_SC + NBU_SC, 1024, 0, s2>>>();
    scan_b_kernel<<<1, 128, 0, s2>>>();
    scan_c_kernel<<<(NU + TB - 1) / TB, TB, 0, s2>>>();
    scatter_kernel<<<(EU + TB - 1) / TB, TB, 0, s2>>>(uedg, uval, iedg, ival);
    cudaEventRecord(evC, s2);

    // main stream: weight prep
    prep_w_kernel<<<4 * DIM * 64 / TB, TB>>>(W_i1, W_i2, W_u1, W_u2);
    cudaEventRecord(evP, 0);

    // --- item chain on s3 ---
    cudaStreamWaitEvent(s3, evP, 0);
    GemmArgs gi1 = { imat, wph + 0 * WSTRIDE, wpl + 0 * WSTRIDE, as_i1, ad_i1,
                     h_i, ssrc_i, sdst_i, NI };
    gemm_mma_kernel<0, 0><<<GB_I, 256, SMEM_TOT, s3>>>(gi1);
    cudaStreamWaitEvent(s3, evC, 0);
    AggArgs ai1 = { off_i, ced_i, ssrc_i, sdst_i, h_i, out1_i, NI };
    agg_csr_kernel<1><<<AGB_I, 256, 0, s3>>>(ai1);
    GemmArgs gi2 = { out1_i, wph + 1 * WSTRIDE, wpl + 1 * WSTRIDE, as_i2, ad_i2,
                     h_i, ssrc_i, sdst_i, NI };
    gemm_mma_kernel<1, 1><<<GB_I, 256, SMEM_TOT, s3>>>(gi2);
    AggArgs ai2 = { off_i, ced_i, ssrc_i, sdst_i, h_i, iout2, NI };
    agg_csr_kernel<0><<<AGB_I, 256, 0, s3>>>(ai2);
    cudaEventRecord(evI, s3);

    // --- user chain on main stream ---
    GemmArgs gu1 = { umat, wph + 2 * WSTRIDE, wpl + 2 * WSTRIDE, as_u1, ad_u1,
                     h_u, ssrc_u, sdst_u, NU };
    gemm_mma_kernel<0, 0><<<GB_U, 256, SMEM_TOT>>>(gu1);
    cudaStreamWaitEvent(0, evC, 0);
    AggArgs au1 = { off_u, ced_u, ssrc_u, sdst_u, h_u, out1_u, NU };
    agg_csr_kernel<1><<<AGB_U, 256>>>(au1);
    GemmArgs gu2 = { out1_u, wph + 3 * WSTRIDE, wpl + 3 * WSTRIDE, as_u2, ad_u2,
                     h_u, ssrc_u, sdst_u, NU };
    gemm_mma_kernel<1, 1><<<GB_U, 256, SMEM_TOT>>>(gu2);
    AggArgs au2 = { off_u, ced_u, ssrc_u, sdst_u, h_u, uout2, NU };
    agg_csr_kernel<0><<<AGB_U, 256>>>(au2);

    // join item chain, then gather
    cudaStreamWaitEvent(0, evI, 0);
    gather_kernel<<<(2 * BATCH * DIM) / TB, TB>>>(uout2, iout2, user_id, item_id, (float*)d_out);
}

// round 13
// speedup vs baseline: 1.9638x; 1.2352x over previous
#include <cuda_runtime.h>
#include <cuda_bf16.h>
#include <cuda_fp16.h>
#include <cstdint>
#include <cfloat>

#define NU 100000
#define NI 50000
#define DIM 128
#define EU 400000
#define EI 200000
#define BATCH 4096

#define GB_U ((NU + 127) / 128)        // 782 gemm blocks (user)
#define GB_I ((NI + 127) / 128)        // 391 gemm blocks (item)
#define NBI_SC ((NI + 1023) / 1024)    // 49 scan blocks (item)
#define NBU_SC ((NU + 1023) / 1024)    // 98 scan blocks (user)
#define AGB_U ((NU + 7) / 8)           // agg blocks (user)
#define AGB_I ((NI + 7) / 8)           // agg blocks (item)

// ---------------- scratch (static device memory) ------------------------------
__device__ __half g_h_u[NU * DIM];          // h fp16 (agg is sole consumer)
__device__ __half g_h_i[NI * DIM];
__device__ __half g_out1_u[NU * DIM];       // layer-1 out fp16 (GEMM2 sole consumer)
__device__ __half g_out1_i[NI * DIM];
__device__ float g_ssrc_u[NU], g_sdst_u[NU];
__device__ float g_ssrc_i[NI], g_sdst_i[NI];
__device__ uint32_t g_wp_hi[4][DIM * 64];   // W^T [n][k-pair] bf16x2, hi part
__device__ uint32_t g_wp_lo[4][DIM * 64];   // residual lo part
// CSR (both graphs persist)
__device__ int   g_cnt_u[NU + 1], g_cnt_i[NI + 1];
__device__ int   g_off_u[NU + 1], g_off_i[NI + 1];
__device__ int   g_btot_u[NBU_SC], g_btot_i[NBI_SC];
__device__ int   g_work_u[NU], g_work_i[NI];
__device__ int2  g_ced_u[EU], g_ced_i[EI];  // packed (src, ev bits)

// ---------------- helpers ------------------------------------------------------
__device__ __forceinline__ float elu_f(float x) {
    return x > 0.f ? x : __expf(x) - 1.f;
}
__device__ __forceinline__ uint32_t pack_bf2(__nv_bfloat16 a, __nv_bfloat16 b) {
    return ((uint32_t)__bfloat16_as_ushort(b) << 16) | (uint32_t)__bfloat16_as_ushort(a);
}
__device__ __forceinline__ uint32_t cvt_bf2(float lo0, float lo1) {
    uint32_t r;
    asm("cvt.rn.bf16x2.f32 %0, %1, %2;" : "=r"(r) : "f"(lo1), "f"(lo0));
    return r;
}
__device__ __forceinline__ void mma_bf16(float* d, const uint32_t* a, const uint32_t* b) {
    asm volatile(
        "mma.sync.aligned.m16n8k16.row.col.f32.bf16.bf16.f32 "
        "{%0,%1,%2,%3}, {%4,%5,%6,%7}, {%8,%9}, {%0,%1,%2,%3};"
        : "+f"(d[0]), "+f"(d[1]), "+f"(d[2]), "+f"(d[3])
        : "r"(a[0]), "r"(a[1]), "r"(a[2]), "r"(a[3]), "r"(b[0]), "r"(b[1]));
}
__device__ __forceinline__ float4 load_h4(const __half* p) {
    uint2 raw = *(const uint2*)p;
    float2 f0 = __half22float2(*(__half2*)&raw.x);
    float2 f1 = __half22float2(*(__half2*)&raw.y);
    return make_float4(f0.x, f0.y, f1.x, f1.y);
}

// ---------------- W^T hi/lo prep (bf16 split, packed pairs) --------------------
__global__ void prep_w_kernel(const float* __restrict__ w0, const float* __restrict__ w1,
                              const float* __restrict__ w2, const float* __restrict__ w3) {
    int i = blockIdx.x * blockDim.x + threadIdx.x;     // 4*128*64
    int l = i >> 13;
    int j = i & 8191;
    int n = j >> 6, kk = j & 63;
    const float* W = (l == 0) ? w0 : (l == 1) ? w1 : (l == 2) ? w2 : w3;
    float a = W[(2 * kk) * DIM + n];
    float b = W[(2 * kk + 1) * DIM + n];
    __nv_bfloat16 ha = __float2bfloat16(a);
    __nv_bfloat16 hb = __float2bfloat16(b);
    __nv_bfloat16 la = __float2bfloat16(a - __bfloat162float(ha));
    __nv_bfloat16 lb = __float2bfloat16(b - __bfloat162float(hb));
    g_wp_hi[l][n * 64 + kk] = pack_bf2(ha, hb);
    g_wp_lo[l][n * 64 + kk] = pack_bf2(la, lb);
}

// ---------------- merged CSR build (both graphs per launch) --------------------
__global__ void zero_cnt_kernel() {
    int i = blockIdx.x * blockDim.x + threadIdx.x;
    if (i <= NU) g_cnt_u[i] = 0;
    if (i <= NI) g_cnt_i[i] = 0;
}
__global__ void count_kernel(const int* __restrict__ udst, const int* __restrict__ idst) {
    int e = blockIdx.x * blockDim.x + threadIdx.x;
    if (e < EU) atomicAdd(&g_cnt_u[udst[e]], 1);
    if (e < EI) atomicAdd(&g_cnt_i[idst[e]], 1);
}
__global__ void __launch_bounds__(1024) scan_a_kernel() {
    __shared__ int sm[1024];
    int t = threadIdx.x;
    int b = blockIdx.x;
    const int* cnt;  int* offs;  int* btot;  int N;  int lb;
    if (b < NBI_SC) { cnt = g_cnt_i; offs = g_off_i; btot = g_btot_i; N = NI; lb = b; }
    else            { cnt = g_cnt_u; offs = g_off_u; btot = g_btot_u; N = NU; lb = b - NBI_SC; }
    int i = lb * 1024 + t;
    int v = (i < N) ? cnt[i] : 0;
    sm[t] = v;
    __syncthreads();
#pragma unroll
    for (int s = 1; s < 1024; s <<= 1) {
        int u = (t >= s) ? sm[t - s] : 0;
        __syncthreads();
        sm[t] += u;
        __syncthreads();
    }
    if (i < N) offs[i] = sm[t] - v;
    if (t == 1023) btot[lb] = sm[1023];
}
__global__ void __launch_bounds__(128) scan_b_kernel() {
    __shared__ int sm[128];
    int t = threadIdx.x;
    int v = (t < NBI_SC) ? g_btot_i[t] : 0;
    sm[t] = v;
    __syncthreads();
#pragma unroll
    for (int s = 1; s < 128; s <<= 1) {
        int u = (t >= s) ? sm[t - s] : 0;
        __syncthreads();
        sm[t] += u;
        __syncthreads();
    }
    if (t < NBI_SC) g_btot_i[t] = sm[t] - v;
    __syncthreads();
    v = (t < NBU_SC) ? g_btot_u[t] : 0;
    sm[t] = v;
    __syncthreads();
#pragma unroll
    for (int s = 1; s < 128; s <<= 1) {
        int u = (t >= s) ? sm[t - s] : 0;
        __syncthreads();
        sm[t] += u;
        __syncthreads();
    }
    if (t < NBU_SC) g_btot_u[t] = sm[t] - v;
}
__global__ void scan_c_kernel() {
    int i = blockIdx.x * blockDim.x + threadIdx.x;
    if (i < NI) {
        int o = g_off_i[i] + g_btot_i[i >> 10];
        g_off_i[i] = o;  g_work_i[i] = o;
    }
    if (i < NU) {
        int o = g_off_u[i] + g_btot_u[i >> 10];
        g_off_u[i] = o;  g_work_u[i] = o;
    }
    if (i == 0) { g_off_i[NI] = EI; g_off_u[NU] = EU; }
}
__global__ void scatter_kernel(const int* __restrict__ uedg, const float* __restrict__ uev,
                               const int* __restrict__ iedg, const float* __restrict__ iev) {
    int e = blockIdx.x * blockDim.x + threadIdx.x;
    if (e < EU) {
        int p = atomicAdd(&g_work_u[uedg[EU + e]], 1);
        g_ced_u[p] = make_int2(uedg[e], __float_as_int(uev[e]));
    }
    if (e < EI) {
        int p = atomicAdd(&g_work_i[iedg[EI + e]], 1);
        g_ced_i[p] = make_int2(iedg[e], __float_as_int(iev[e]));
    }
}

// ---------------- BF16 3-term HMMA GEMM + attention scalars (per-graph) --------
struct GemmArgs {
    const void* x;                 // fp32 (layer1) or fp16 (layer2)
    const uint32_t *wh, *wl;
    const float *as, *ad;
    __half* h;
    float *ssrc, *sdst;
    int N;
};

// smem (bytes): B hi/lo [128n][68 u32], A hi/lo [128r][68 u32], red buf
#define SB_BH   0
#define SB_BL   34816
#define SB_AH   69632
#define SB_AL   104448
#define SB_RED  139264
#define SMEM_TOT 143360

template <int ACT, int INH>
__global__ void __launch_bounds__(256, 1) gemm_mma_kernel(GemmArgs g)
{
    extern __shared__ char smem[];
    uint32_t* Bh = (uint32_t*)(smem + SB_BH);
    uint32_t* Bl = (uint32_t*)(smem + SB_BL);
    uint32_t* Ah = (uint32_t*)(smem + SB_AH);
    uint32_t* Al = (uint32_t*)(smem + SB_AL);
    float* red_s = (float*)(smem + SB_RED);
    float* red_d = red_s + 128 * 4;

    const int N = g.N;
    const int tid = threadIdx.x;
    const int lane = tid & 31;
    const int wid = tid >> 5;
    const int wm = wid & 1;
    const int wn = wid >> 1;
    const int r0 = blockIdx.x * 128;

    // stage B (both hi and lo), uint4 copies into stride-68 layout
    for (int i = tid; i < 2048; i += 256) {
        int n = i >> 4, k4 = (i & 15) * 4;
        *(uint4*)&Bh[n * 68 + k4] = *(const uint4*)&g.wh[n * 64 + k4];
        *(uint4*)&Bl[n * 68 + k4] = *(const uint4*)&g.wl[n * 64 + k4];
    }

    // stage full A tile (128 rows x 128 k): ELU + truncation-based bf16 split
    {
        const int r = tid >> 1;
        const int half = tid & 1;
        const bool ok = (r0 + r < N);
        const size_t roff = (size_t)(r0 + r) * DIM + half * 64;
        const float* xf = (const float*)g.x + roff;
        const __half* xh = (const __half*)g.x + roff;
#pragma unroll
        for (int q = 0; q < 16; ++q) {
            float4 v = make_float4(0.f, 0.f, 0.f, 0.f);
            if (ok) v = INH ? load_h4(xh + q * 4) : *(const float4*)(xf + q * 4);
            if (ACT) { v.x = elu_f(v.x); v.y = elu_f(v.y); v.z = elu_f(v.z); v.w = elu_f(v.w); }
            uint32_t ix = __float_as_uint(v.x), iy = __float_as_uint(v.y);
            uint32_t iz = __float_as_uint(v.z), iw = __float_as_uint(v.w);
            uint32_t hi01 = __byte_perm(ix, iy, 0x7632);
            uint32_t hi23 = __byte_perm(iz, iw, 0x7632);
            float l0 = v.x - __uint_as_float(ix & 0xFFFF0000u);
            float l1 = v.y - __uint_as_float(iy & 0xFFFF0000u);
            float l2 = v.z - __uint_as_float(iz & 0xFFFF0000u);
            float l3 = v.w - __uint_as_float(iw & 0xFFFF0000u);
            int o = r * 68 + half * 32 + q * 2;
            Ah[o] = hi01;  Ah[o + 1] = hi23;
            Al[o] = cvt_bf2(l0, l1);  Al[o + 1] = cvt_bf2(l2, l3);
        }
    }
    __syncthreads();

    float acc[4][4][4];
#pragma unroll
    for (int mt = 0; mt < 4; ++mt)
#pragma unroll
        for (int nt = 0; nt < 4; ++nt)
#pragma unroll
            for (int q = 0; q < 4; ++q) acc[mt][nt][q] = 0.f;

#pragma unroll
    for (int ks = 0; ks < 8; ++ks) {
        const int kk0 = ks * 8;
        uint32_t bh[4][2], bl[4][2];
#pragma unroll
        for (int nt = 0; nt < 4; ++nt) {
            int bn = wn * 32 + nt * 8 + (lane >> 2);
            bh[nt][0] = Bh[bn * 68 + kk0 + (lane & 3)];
            bh[nt][1] = Bh[bn * 68 + kk0 + 4 + (lane & 3)];
            bl[nt][0] = Bl[bn * 68 + kk0 + (lane & 3)];
            bl[nt][1] = Bl[bn * 68 + kk0 + 4 + (lane & 3)];
        }
        uint32_t ah[4][4], al[4][4];
#pragma unroll
        for (int mt = 0; mt < 4; ++mt) {
            int ar = wm * 64 + mt * 16 + (lane >> 2);
            ah[mt][0] = Ah[ar * 68 + kk0 + (lane & 3)];
            ah[mt][1] = Ah[(ar + 8) * 68 + kk0 + (lane & 3)];
            ah[mt][2] = Ah[ar * 68 + kk0 + 4 + (lane & 3)];
            ah[mt][3] = Ah[(ar + 8) * 68 + kk0 + 4 + (lane & 3)];
            al[mt][0] = Al[ar * 68 + kk0 + (lane & 3)];
            al[mt][1] = Al[(ar + 8) * 68 + kk0 + (lane & 3)];
            al[mt][2] = Al[ar * 68 + kk0 + 4 + (lane & 3)];
            al[mt][3] = Al[(ar + 8) * 68 + kk0 + 4 + (lane & 3)];
        }
#pragma unroll
        for (int mt = 0; mt < 4; ++mt)
#pragma unroll
            for (int nt = 0; nt < 4; ++nt) {
                mma_bf16(acc[mt][nt], ah[mt], bh[nt]);
                mma_bf16(acc[mt][nt], ah[mt], bl[nt]);
                mma_bf16(acc[mt][nt], al[mt], bh[nt]);
            }
    }

    // ---------------- epilogue: store h (fp16) + attention scalar dots ---------
    float asv[4][2], adv[4][2];
#pragma unroll
    for (int nt = 0; nt < 4; ++nt) {
        int c0 = wn * 32 + nt * 8 + 2 * (lane & 3);
        asv[nt][0] = g.as[c0];   asv[nt][1] = g.as[c0 + 1];
        adv[nt][0] = g.ad[c0];   adv[nt][1] = g.ad[c0 + 1];
    }

    float ps[8], pd[8];
#pragma unroll
    for (int q = 0; q < 8; ++q) { ps[q] = 0.f; pd[q] = 0.f; }

    __half* __restrict__ h = g.h;
#pragma unroll
    for (int mt = 0; mt < 4; ++mt) {
        int ar = r0 + wm * 64 + mt * 16 + (lane >> 2);
#pragma unroll
        for (int nt = 0; nt < 4; ++nt) {
            int c0 = wn * 32 + nt * 8 + 2 * (lane & 3);
            if (ar < N) {
                __half2 hv = __floats2half2_rn(acc[mt][nt][0], acc[mt][nt][1]);
                *(__half2*)(h + (size_t)ar * DIM + c0) = hv;
            }
            if (ar + 8 < N) {
                __half2 hv = __floats2half2_rn(acc[mt][nt][2], acc[mt][nt][3]);
                *(__half2*)(h + (size_t)(ar + 8) * DIM + c0) = hv;
            }
            ps[mt * 2 + 0] += acc[mt][nt][0] * asv[nt][0] + acc[mt][nt][1] * asv[nt][1];
            ps[mt * 2 + 1] += acc[mt][nt][2] * asv[nt][0] + acc[mt][nt][3] * asv[nt][1];
            pd[mt * 2 + 0] += acc[mt][nt][0] * adv[nt][0] + acc[mt][nt][1] * adv[nt][1];
            pd[mt * 2 + 1] += acc[mt][nt][2] * adv[nt][0] + acc[mt][nt][3] * adv[nt][1];
        }
    }
#pragma unroll
    for (int q = 0; q < 8; ++q) {
        ps[q] += __shfl_xor_sync(0xFFFFFFFF, ps[q], 1);
        ps[q] += __shfl_xor_sync(0xFFFFFFFF, ps[q], 2);
        pd[q] += __shfl_xor_sync(0xFFFFFFFF, pd[q], 1);
        pd[q] += __shfl_xor_sync(0xFFFFFFFF, pd[q], 2);
    }
    __syncthreads();
    if ((lane & 3) == 0) {
#pragma unroll
        for (int mt = 0; mt < 4; ++mt) {
            int rl0 = wm * 64 + mt * 16 + (lane >> 2);
            red_s[rl0 * 4 + wn] = ps[mt * 2 + 0];
            red_s[(rl0 + 8) * 4 + wn] = ps[mt * 2 + 1];
            red_d[rl0 * 4 + wn] = pd[mt * 2 + 0];
            red_d[(rl0 + 8) * 4 + wn] = pd[mt * 2 + 1];
        }
    }
    __syncthreads();
    if (tid < 128) {
        int row = r0 + tid;
        if (row < N) {
            float s = red_s[tid * 4] + red_s[tid * 4 + 1] + red_s[tid * 4 + 2] + red_s[tid * 4 + 3];
            float d = red_d[tid * 4] + red_d[tid * 4 + 1] + red_d[tid * 4 + 2] + red_d[tid * 4 + 3];
            g.ssrc[row] = s;
            g.sdst[row] = d;
        }
    }
}

// ---------------- shared agg core (one warp, one dst node) ---------------------
struct AggView {
    const int* off;
    const int2* ced;
    const float *ssrc, *sdst;
    const __half* h;
};

__device__ __forceinline__ float4 agg_node(const AggView& a, int d, int lane)
{
    const int o0 = a.off[d], o1 = a.off[d + 1];
    const float sd = a.sdst[d];
    const __half* __restrict__ h = a.h;

    float4 acc = make_float4(0.f, 0.f, 0.f, 0.f);
    float denom = 0.f;

    for (int base = o0; base < o1; base += 32) {
        int idx = base + lane;
        float e = 0.f;
        int s = 0;
        if (idx < o1) {
            int2 se = a.ced[idx];
            s = se.x;
            float l = a.ssrc[s] + sd;
            l = l > 0.f ? l : 0.2f * l;
            e = __expf(l) * __int_as_float(se.y);
        }
        float esum = e;
#pragma unroll
        for (int m = 16; m; m >>= 1) esum += __shfl_xor_sync(0xFFFFFFFF, esum, m);
        denom += esum;

        int cnt = min(32, o1 - base);
        int k = 0;
        for (; k + 4 <= cnt; k += 4) {
            float c0 = __shfl_sync(0xFFFFFFFF, e, k);
            float c1 = __shfl_sync(0xFFFFFFFF, e, k + 1);
            float c2 = __shfl_sync(0xFFFFFFFF, e, k + 2);
            float c3 = __shfl_sync(0xFFFFFFFF, e, k + 3);
            int s0 = __shfl_sync(0xFFFFFFFF, s, k);
            int s1 = __shfl_sync(0xFFFFFFFF, s, k + 1);
            int s2 = __shfl_sync(0xFFFFFFFF, s, k + 2);
            int s3 = __shfl_sync(0xFFFFFFFF, s, k + 3);
            float4 v0 = load_h4(h + (size_t)s0 * DIM + lane * 4);
            float4 v1 = load_h4(h + (size_t)s1 * DIM + lane * 4);
            float4 v2 = load_h4(h + (size_t)s2 * DIM + lane * 4);
            float4 v3 = load_h4(h + (size_t)s3 * DIM + lane * 4);
            acc.x += c0 * v0.x + c1 * v1.x + c2 * v2.x + c3 * v3.x;
            acc.y += c0 * v0.y + c1 * v1.y + c2 * v2.y + c3 * v3.y;
            acc.z += c0 * v0.z + c1 * v1.z + c2 * v2.z + c3 * v3.z;
            acc.w += c0 * v0.w + c1 * v1.w + c2 * v2.w + c3 * v3.w;
        }
        for (; k < cnt; ++k) {
            float coef = __shfl_sync(0xFFFFFFFF, e, k);
            int sk = __shfl_sync(0xFFFFFFFF, s, k);
            float4 v = load_h4(h + (size_t)sk * DIM + lane * 4);
            acc.x += coef * v.x; acc.y += coef * v.y;
            acc.z += coef * v.z; acc.w += coef * v.w;
        }
    }
    float inv = 1.f / (denom + 1e-16f);
    acc.x *= inv; acc.y *= inv; acc.z *= inv; acc.w *= inv;
    return acc;
}

// ---------------- layer-1 aggregate over all nodes (fp16 out) ------------------
__global__ void agg_csr_kernel(AggView a, __half* __restrict__ out, int N)
{
    int lane = threadIdx.x & 31;
    int d = blockIdx.x * 8 + (threadIdx.x >> 5);
    if (d >= N) return;
    float4 acc = agg_node(a, d, lane);
    __half2 p0 = __floats2half2_rn(acc.x, acc.y);
    __half2 p1 = __floats2half2_rn(acc.z, acc.w);
    uint2 pk;
    pk.x = *(uint32_t*)&p0;  pk.y = *(uint32_t*)&p1;
    *(uint2*)(out + (size_t)d * DIM + lane * 4) = pk;
}

// ---------------- fused layer-2 batch aggregate + elu + output -----------------
// one warp per batch element; only the 8192 needed dst rows are aggregated.
__global__ void batch_agg_kernel(AggView au, AggView ai,
                                 const int* __restrict__ uid, const int* __restrict__ iid,
                                 float* __restrict__ out)
{
    int lane = threadIdx.x & 31;
    int b = blockIdx.x * 8 + (threadIdx.x >> 5);
    if (b >= 2 * BATCH) return;
    const bool isU = b < BATCH;
    const AggView& a = isU ? au : ai;
    int d = isU ? uid[b] : iid[b - BATCH];
    float4 acc = agg_node(a, d, lane);
    acc.x = elu_f(acc.x);  acc.y = elu_f(acc.y);
    acc.z = elu_f(acc.z);  acc.w = elu_f(acc.w);
    *(float4*)(out + (size_t)b * DIM + lane * 4) = acc;
}

// ---------------- host orchestration -------------------------------------------
extern "C" void kernel_launch(void* const* d_in, const int* in_sizes, int n_in,
                              void* d_out, int out_size)
{
    const int*   uedg = (const int*)d_in[0];
    const int*   iedg = (const int*)d_in[1];
    const int*   user_id = (const int*)d_in[2];
    const int*   item_id = (const int*)d_in[3];
    const float* uval = (const float*)d_in[4];
    const float* ival = (const float*)d_in[5];
    const float* umat = (const float*)d_in[6];
    const float* imat = (const float*)d_in[7];
    const float* W_u1 = (const float*)d_in[8];
    const float* as_u1 = (const float*)d_in[9];
    const float* ad_u1 = (const float*)d_in[10];
    const float* W_u2 = (const float*)d_in[11];
    const float* as_u2 = (const float*)d_in[12];
    const float* ad_u2 = (const float*)d_in[13];
    const float* W_i1 = (const float*)d_in[14];
    const float* as_i1 = (const float*)d_in[15];
    const float* ad_i1 = (const float*)d_in[16];
    const float* W_i2 = (const float*)d_in[17];
    const float* as_i2 = (const float*)d_in[18];
    const float* ad_i2 = (const float*)d_in[19];

    __half *h_u, *h_i, *out1_u, *out1_i;
    float *ssrc_u, *sdst_u, *ssrc_i, *sdst_i;
    uint32_t *wph, *wpl;
    int *off_u, *off_i;
    int2 *ced_u, *ced_i;
    cudaGetSymbolAddress((void**)&h_u, g_h_u);
    cudaGetSymbolAddress((void**)&h_i, g_h_i);
    cudaGetSymbolAddress((void**)&out1_u, g_out1_u);
    cudaGetSymbolAddress((void**)&out1_i, g_out1_i);
    cudaGetSymbolAddress((void**)&ssrc_u, g_ssrc_u);
    cudaGetSymbolAddress((void**)&sdst_u, g_sdst_u);
    cudaGetSymbolAddress((void**)&ssrc_i, g_ssrc_i);
    cudaGetSymbolAddress((void**)&sdst_i, g_sdst_i);
    cudaGetSymbolAddress((void**)&wph, g_wp_hi);
    cudaGetSymbolAddress((void**)&wpl, g_wp_lo);
    cudaGetSymbolAddress((void**)&off_u, g_off_u);
    cudaGetSymbolAddress((void**)&off_i, g_off_i);
    cudaGetSymbolAddress((void**)&ced_u, g_ced_u);
    cudaGetSymbolAddress((void**)&ced_i, g_ced_i);

    cudaFuncSetAttribute(gemm_mma_kernel<0, 0>, cudaFuncAttributeMaxDynamicSharedMemorySize, SMEM_TOT);
    cudaFuncSetAttribute(gemm_mma_kernel<1, 1>, cudaFuncAttributeMaxDynamicSharedMemorySize, SMEM_TOT);

    // one-time side streams + events
    static cudaStream_t s2 = nullptr, s3 = nullptr;
    static cudaEvent_t evF = nullptr, evC = nullptr, evP = nullptr, evI = nullptr;
    if (!s2) {
        cudaStreamCreateWithFlags(&s2, cudaStreamNonBlocking);
        cudaStreamCreateWithFlags(&s3, cudaStreamNonBlocking);
        cudaEventCreateWithFlags(&evF, cudaEventDisableTiming);
        cudaEventCreateWithFlags(&evC, cudaEventDisableTiming);
        cudaEventCreateWithFlags(&evP, cudaEventDisableTiming);
        cudaEventCreateWithFlags(&evI, cudaEventDisableTiming);
    }

    const int TB = 256;
    const int WSTRIDE = DIM * 64;

    // fork: CSR build on s2, overlapped with prep + GEMM1s
    cudaEventRecord(evF, 0);
    cudaStreamWaitEvent(s2, evF, 0);

    zero_cnt_kernel<<<(NU + TB) / TB, TB, 0, s2>>>();
    count_kernel<<<(EU + TB - 1) / TB, TB, 0, s2>>>(uedg + EU, iedg + EI);
    scan_a_kernel<<<NBI_SC + NBU_SC, 1024, 0, s2>>>();
    scan_b_kernel<<<1, 128, 0, s2>>>();
    scan_c_kernel<<<(NU + TB - 1) / TB, TB, 0, s2>>>();
    scatter_kernel<<<(EU + TB - 1) / TB, TB, 0, s2>>>(uedg, uval, iedg, ival);
    cudaEventRecord(evC, s2);

    // main stream: weight prep
    prep_w_kernel<<<4 * DIM * 64 / TB, TB>>>(W_i1, W_i2, W_u1, W_u2);
    cudaEventRecord(evP, 0);

    AggView vu = { off_u, ced_u, ssrc_u, sdst_u, h_u };
    AggView vi = { off_i, ced_i, ssrc_i, sdst_i, h_i };

    // --- item chain on s3 ---
    cudaStreamWaitEvent(s3, evP, 0);
    GemmArgs gi1 = { imat, wph + 0 * WSTRIDE, wpl + 0 * WSTRIDE, as_i1, ad_i1,
                     h_i, ssrc_i, sdst_i, NI };
    gemm_mma_kernel<0, 0><<<GB_I, 256, SMEM_TOT, s3>>>(gi1);
    cudaStreamWaitEvent(s3, evC, 0);
    agg_csr_kernel<<<AGB_I, 256, 0, s3>>>(vi, out1_i, NI);
    GemmArgs gi2 = { out1_i, wph + 1 * WSTRIDE, wpl + 1 * WSTRIDE, as_i2, ad_i2,
                     h_i, ssrc_i, sdst_i, NI };
    gemm_mma_kernel<1, 1><<<GB_I, 256, SMEM_TOT, s3>>>(gi2);
    cudaEventRecord(evI, s3);

    // --- user chain on main stream ---
    GemmArgs gu1 = { umat, wph + 2 * WSTRIDE, wpl + 2 * WSTRIDE, as_u1, ad_u1,
                     h_u, ssrc_u, sdst_u, NU };
    gemm_mma_kernel<0, 0><<<GB_U, 256, SMEM_TOT>>>(gu1);
    cudaStreamWaitEvent(0, evC, 0);
    agg_csr_kernel<<<AGB_U, 256>>>(vu, out1_u, NU);
    GemmArgs gu2 = { out1_u, wph + 3 * WSTRIDE, wpl + 3 * WSTRIDE, as_u2, ad_u2,
                     h_u, ssrc_u, sdst_u, NU };
    gemm_mma_kernel<1, 1><<<GB_U, 256, SMEM_TOT>>>(gu2);

    // join item chain, then fused batch aggregate (layer-2 only for needed rows)
    cudaStreamWaitEvent(0, evI, 0);
    batch_agg_kernel<<<(2 * BATCH) / 8, 256>>>(vu, vi, user_id, item_id, (float*)d_out);
}

// round 14
// speedup vs baseline: 2.8636x; 1.4582x over previous
#include <cuda_runtime.h>
#include <cuda_bf16.h>
#include <cuda_fp16.h>
#include <cstdint>
#include <cfloat>

#define NU 100000
#define NI 50000
#define DIM 128
#define EU 400000
#define EI 200000
#define BATCH 4096

#define GB_U ((NU + 127) / 128)        // 782 gemm blocks (user)
#define GB_I ((NI + 127) / 128)        // 391 gemm blocks (item)
#define NBI_SC ((NI + 1023) / 1024)    // 49 scan blocks (item)
#define NBU_SC ((NU + 1023) / 1024)    // 98 scan blocks (user)
#define AGB_U ((NU + 7) / 8)           // agg blocks (user)
#define AGB_I ((NI + 7) / 8)           // agg blocks (item)

// ---------------- scratch (static device memory) ------------------------------
__device__ __half g_h_u[NU * DIM];          // h fp16 (agg is sole consumer)
__device__ __half g_h_i[NI * DIM];
__device__ __half g_out1_u[NU * DIM];       // layer-1 out fp16 (GEMM2 sole consumer)
__device__ __half g_out1_i[NI * DIM];
__device__ float g_ssrc_u[NU], g_sdst_u[NU];
__device__ float g_ssrc_i[NI], g_sdst_i[NI];
__device__ uint32_t g_wp_hi[4][DIM * 64];   // W^T [n][k-pair] bf16x2, hi part
__device__ uint32_t g_wp_lo[4][DIM * 64];   // residual lo part
// CSR (both graphs persist)
__device__ int   g_cnt_u[NU + 1], g_cnt_i[NI + 1];
__device__ int   g_off_u[NU + 1], g_off_i[NI + 1];
__device__ int   g_btot_u[NBU_SC], g_btot_i[NBI_SC];
__device__ int   g_work_u[NU], g_work_i[NI];
__device__ int2  g_ced_u[EU], g_ced_i[EI];  // packed (src, ev bits)
// demand set (layer-2 pruning)
__device__ int   g_mark_u[NU], g_mark_i[NI];
__device__ int   g_list_u[NU], g_list_i[NI];
__device__ int   g_nlist[2];                 // [0]=user count, [1]=item count

// ---------------- helpers ------------------------------------------------------
__device__ __forceinline__ float elu_f(float x) {
    return x > 0.f ? x : __expf(x) - 1.f;
}
__device__ __forceinline__ uint32_t pack_bf2(__nv_bfloat16 a, __nv_bfloat16 b) {
    return ((uint32_t)__bfloat16_as_ushort(b) << 16) | (uint32_t)__bfloat16_as_ushort(a);
}
__device__ __forceinline__ uint32_t cvt_bf2(float lo0, float lo1) {
    uint32_t r;
    asm("cvt.rn.bf16x2.f32 %0, %1, %2;" : "=r"(r) : "f"(lo1), "f"(lo0));
    return r;
}
__device__ __forceinline__ void mma_bf16(float* d, const uint32_t* a, const uint32_t* b) {
    asm volatile(
        "mma.sync.aligned.m16n8k16.row.col.f32.bf16.bf16.f32 "
        "{%0,%1,%2,%3}, {%4,%5,%6,%7}, {%8,%9}, {%0,%1,%2,%3};"
        : "+f"(d[0]), "+f"(d[1]), "+f"(d[2]), "+f"(d[3])
        : "r"(a[0]), "r"(a[1]), "r"(a[2]), "r"(a[3]), "r"(b[0]), "r"(b[1]));
}
__device__ __forceinline__ float4 load_h4(const __half* p) {
    uint2 raw = *(const uint2*)p;
    float2 f0 = __half22float2(*(__half2*)&raw.x);
    float2 f1 = __half22float2(*(__half2*)&raw.y);
    return make_float4(f0.x, f0.y, f1.x, f1.y);
}

// ---------------- W^T hi/lo prep (bf16 split, packed pairs) --------------------
__global__ void prep_w_kernel(const float* __restrict__ w0, const float* __restrict__ w1,
                              const float* __restrict__ w2, const float* __restrict__ w3) {
    int i = blockIdx.x * blockDim.x + threadIdx.x;     // 4*128*64
    int l = i >> 13;
    int j = i & 8191;
    int n = j >> 6, kk = j & 63;
    const float* W = (l == 0) ? w0 : (l == 1) ? w1 : (l == 2) ? w2 : w3;
    float a = W[(2 * kk) * DIM + n];
    float b = W[(2 * kk + 1) * DIM + n];
    __nv_bfloat16 ha = __float2bfloat16(a);
    __nv_bfloat16 hb = __float2bfloat16(b);
    __nv_bfloat16 la = __float2bfloat16(a - __bfloat162float(ha));
    __nv_bfloat16 lb = __float2bfloat16(b - __bfloat162float(hb));
    g_wp_hi[l][n * 64 + kk] = pack_bf2(ha, hb);
    g_wp_lo[l][n * 64 + kk] = pack_bf2(la, lb);
}

// ---------------- merged CSR build (both graphs per launch) --------------------
__global__ void zero_cnt_kernel() {
    int i = blockIdx.x * blockDim.x + threadIdx.x;
    if (i <= NU) g_cnt_u[i] = 0;
    if (i <= NI) g_cnt_i[i] = 0;
    if (i < NU) g_mark_u[i] = 0;
    if (i < NI) g_mark_i[i] = 0;
    if (i == 0) { g_nlist[0] = 0; g_nlist[1] = 0; }
}
__global__ void count_kernel(const int* __restrict__ udst, const int* __restrict__ idst) {
    int e = blockIdx.x * blockDim.x + threadIdx.x;
    if (e < EU) atomicAdd(&g_cnt_u[udst[e]], 1);
    if (e < EI) atomicAdd(&g_cnt_i[idst[e]], 1);
}
__global__ void __launch_bounds__(1024) scan_a_kernel() {
    __shared__ int sm[1024];
    int t = threadIdx.x;
    int b = blockIdx.x;
    const int* cnt;  int* offs;  int* btot;  int N;  int lb;
    if (b < NBI_SC) { cnt = g_cnt_i; offs = g_off_i; btot = g_btot_i; N = NI; lb = b; }
    else            { cnt = g_cnt_u; offs = g_off_u; btot = g_btot_u; N = NU; lb = b - NBI_SC; }
    int i = lb * 1024 + t;
    int v = (i < N) ? cnt[i] : 0;
    sm[t] = v;
    __syncthreads();
#pragma unroll
    for (int s = 1; s < 1024; s <<= 1) {
        int u = (t >= s) ? sm[t - s] : 0;
        __syncthreads();
        sm[t] += u;
        __syncthreads();
    }
    if (i < N) offs[i] = sm[t] - v;
    if (t == 1023) btot[lb] = sm[1023];
}
__global__ void __launch_bounds__(128) scan_b_kernel() {
    __shared__ int sm[128];
    int t = threadIdx.x;
    int v = (t < NBI_SC) ? g_btot_i[t] : 0;
    sm[t] = v;
    __syncthreads();
#pragma unroll
    for (int s = 1; s < 128; s <<= 1) {
        int u = (t >= s) ? sm[t - s] : 0;
        __syncthreads();
        sm[t] += u;
        __syncthreads();
    }
    if (t < NBI_SC) g_btot_i[t] = sm[t] - v;
    __syncthreads();
    v = (t < NBU_SC) ? g_btot_u[t] : 0;
    sm[t] = v;
    __syncthreads();
#pragma unroll
    for (int s = 1; s < 128; s <<= 1) {
        int u = (t >= s) ? sm[t - s] : 0;
        __syncthreads();
        sm[t] += u;
        __syncthreads();
    }
    if (t < NBU_SC) g_btot_u[t] = sm[t] - v;
}
__global__ void scan_c_kernel() {
    int i = blockIdx.x * blockDim.x + threadIdx.x;
    if (i < NI) {
        int o = g_off_i[i] + g_btot_i[i >> 10];
        g_off_i[i] = o;  g_work_i[i] = o;
    }
    if (i < NU) {
        int o = g_off_u[i] + g_btot_u[i >> 10];
        g_off_u[i] = o;  g_work_u[i] = o;
    }
    if (i == 0) { g_off_i[NI] = EI; g_off_u[NU] = EU; }
}
__global__ void scatter_kernel(const int* __restrict__ uedg, const float* __restrict__ uev,
                               const int* __restrict__ iedg, const float* __restrict__ iev) {
    int e = blockIdx.x * blockDim.x + threadIdx.x;
    if (e < EU) {
        int p = atomicAdd(&g_work_u[uedg[EU + e]], 1);
        g_ced_u[p] = make_int2(uedg[e], __float_as_int(uev[e]));
    }
    if (e < EI) {
        int p = atomicAdd(&g_work_i[iedg[EI + e]], 1);
        g_ced_i[p] = make_int2(iedg[e], __float_as_int(iev[e]));
    }
}
// mark batch dsts + their CSR sources (one warp per batch element)
__global__ void mark_kernel(const int* __restrict__ uid, const int* __restrict__ iid) {
    int w = (blockIdx.x * blockDim.x + threadIdx.x) >> 5;
    int lane = threadIdx.x & 31;
    if (w >= 2 * BATCH) return;
    const bool isU = w < BATCH;
    int d = isU ? uid[w] : iid[w - BATCH];
    int* mark = isU ? g_mark_u : g_mark_i;
    const int* off = isU ? g_off_u : g_off_i;
    const int2* ced = isU ? g_ced_u : g_ced_i;
    if (lane == 0) mark[d] = 1;
    int o0 = off[d], o1 = off[d + 1];
    for (int e = o0 + lane; e < o1; e += 32) mark[ced[e].x] = 1;
}
__global__ void compact_kernel() {
    int i = blockIdx.x * blockDim.x + threadIdx.x;
    if (i < NU && g_mark_u[i]) { int p = atomicAdd(&g_nlist[0], 1); g_list_u[p] = i; }
    if (i < NI && g_mark_i[i]) { int p = atomicAdd(&g_nlist[1], 1); g_list_i[p] = i; }
}

// ---------------- BF16 3-term HMMA GEMM + attention scalars (per-graph) --------
struct GemmArgs {
    const void* x;                 // fp32 (layer1) or fp16 (layer2)
    const uint32_t *wh, *wl;
    const float *as, *ad;
    __half* h;
    float *ssrc, *sdst;
    int N;
    const int* rows;               // IDX mode: compacted row list
    const int* cnt;                // IDX mode: list length (device)
};

// smem (bytes): B hi/lo [128n][68 u32], A hi/lo [128r][68 u32], red buf
#define SB_BH   0
#define SB_BL   34816
#define SB_AH   69632
#define SB_AL   104448
#define SB_RED  139264
#define SMEM_TOT 143360

template <int ACT, int INH, int IDX>
__global__ void __launch_bounds__(256, 1) gemm_mma_kernel(GemmArgs g)
{
    extern __shared__ char smem[];
    uint32_t* Bh = (uint32_t*)(smem + SB_BH);
    uint32_t* Bl = (uint32_t*)(smem + SB_BL);
    uint32_t* Ah = (uint32_t*)(smem + SB_AH);
    uint32_t* Al = (uint32_t*)(smem + SB_AL);
    float* red_s = (float*)(smem + SB_RED);
    float* red_d = red_s + 128 * 4;

    const int count = IDX ? *g.cnt : g.N;
    const int r0 = blockIdx.x * 128;
    if (r0 >= count) return;

    const int tid = threadIdx.x;
    const int lane = tid & 31;
    const int wid = tid >> 5;
    const int wm = wid & 1;
    const int wn = wid >> 1;

    // stage B (both hi and lo), uint4 copies into stride-68 layout
    for (int i = tid; i < 2048; i += 256) {
        int n = i >> 4, k4 = (i & 15) * 4;
        *(uint4*)&Bh[n * 68 + k4] = *(const uint4*)&g.wh[n * 64 + k4];
        *(uint4*)&Bl[n * 68 + k4] = *(const uint4*)&g.wl[n * 64 + k4];
    }

    // stage full A tile (128 rows x 128 k): ELU + truncation-based bf16 split
    {
        const int r = tid >> 1;
        const int half = tid & 1;
        const int li = r0 + r;
        const int gr = (li < count) ? (IDX ? g.rows[li] : li) : -1;
        const size_t roff = (size_t)(gr < 0 ? 0 : gr) * DIM + half * 64;
        const float* xf = (const float*)g.x + roff;
        const __half* xh = (const __half*)g.x + roff;
#pragma unroll
        for (int q = 0; q < 16; ++q) {
            float4 v = make_float4(0.f, 0.f, 0.f, 0.f);
            if (gr >= 0) v = INH ? load_h4(xh + q * 4) : *(const float4*)(xf + q * 4);
            if (ACT) { v.x = elu_f(v.x); v.y = elu_f(v.y); v.z = elu_f(v.z); v.w = elu_f(v.w); }
            uint32_t ix = __float_as_uint(v.x), iy = __float_as_uint(v.y);
            uint32_t iz = __float_as_uint(v.z), iw = __float_as_uint(v.w);
            uint32_t hi01 = __byte_perm(ix, iy, 0x7632);
            uint32_t hi23 = __byte_perm(iz, iw, 0x7632);
            float l0 = v.x - __uint_as_float(ix & 0xFFFF0000u);
            float l1 = v.y - __uint_as_float(iy & 0xFFFF0000u);
            float l2 = v.z - __uint_as_float(iz & 0xFFFF0000u);
            float l3 = v.w - __uint_as_float(iw & 0xFFFF0000u);
            int o = r * 68 + half * 32 + q * 2;
            Ah[o] = hi01;  Ah[o + 1] = hi23;
            Al[o] = cvt_bf2(l0, l1);  Al[o + 1] = cvt_bf2(l2, l3);
        }
    }
    __syncthreads();

    float acc[4][4][4];
#pragma unroll
    for (int mt = 0; mt < 4; ++mt)
#pragma unroll
        for (int nt = 0; nt < 4; ++nt)
#pragma unroll
            for (int q = 0; q < 4; ++q) acc[mt][nt][q] = 0.f;

#pragma unroll
    for (int ks = 0; ks < 8; ++ks) {
        const int kk0 = ks * 8;
        uint32_t bh[4][2], bl[4][2];
#pragma unroll
        for (int nt = 0; nt < 4; ++nt) {
            int bn = wn * 32 + nt * 8 + (lane >> 2);
            bh[nt][0] = Bh[bn * 68 + kk0 + (lane & 3)];
            bh[nt][1] = Bh[bn * 68 + kk0 + 4 + (lane & 3)];
            bl[nt][0] = Bl[bn * 68 + kk0 + (lane & 3)];
            bl[nt][1] = Bl[bn * 68 + kk0 + 4 + (lane & 3)];
        }
        uint32_t ah[4][4], al[4][4];
#pragma unroll
        for (int mt = 0; mt < 4; ++mt) {
            int ar = wm * 64 + mt * 16 + (lane >> 2);
            ah[mt][0] = Ah[ar * 68 + kk0 + (lane & 3)];
            ah[mt][1] = Ah[(ar + 8) * 68 + kk0 + (lane & 3)];
            ah[mt][2] = Ah[ar * 68 + kk0 + 4 + (lane & 3)];
            ah[mt][3] = Ah[(ar + 8) * 68 + kk0 + 4 + (lane & 3)];
            al[mt][0] = Al[ar * 68 + kk0 + (lane & 3)];
            al[mt][1] = Al[(ar + 8) * 68 + kk0 + (lane & 3)];
            al[mt][2] = Al[ar * 68 + kk0 + 4 + (lane & 3)];
            al[mt][3] = Al[(ar + 8) * 68 + kk0 + 4 + (lane & 3)];
        }
#pragma unroll
        for (int mt = 0; mt < 4; ++mt)
#pragma unroll
            for (int nt = 0; nt < 4; ++nt) {
                mma_bf16(acc[mt][nt], ah[mt], bh[nt]);
                mma_bf16(acc[mt][nt], ah[mt], bl[nt]);
                mma_bf16(acc[mt][nt], al[mt], bh[nt]);
            }
    }

    // ---------------- epilogue: store h (fp16) + attention scalar dots ---------
    float asv[4][2], adv[4][2];
#pragma unroll
    for (int nt = 0; nt < 4; ++nt) {
        int c0 = wn * 32 + nt * 8 + 2 * (lane & 3);
        asv[nt][0] = g.as[c0];   asv[nt][1] = g.as[c0 + 1];
        adv[nt][0] = g.ad[c0];   adv[nt][1] = g.ad[c0 + 1];
    }

    float ps[8], pd[8];
#pragma unroll
    for (int q = 0; q < 8; ++q) { ps[q] = 0.f; pd[q] = 0.f; }

    __half* __restrict__ h = g.h;
#pragma unroll
    for (int mt = 0; mt < 4; ++mt) {
        int li = r0 + wm * 64 + mt * 16 + (lane >> 2);
        int gr1 = (li < count) ? (IDX ? g.rows[li] : li) : -1;
        int gr2 = (li + 8 < count) ? (IDX ? g.rows[li + 8] : li + 8) : -1;
#pragma unroll
        for (int nt = 0; nt < 4; ++nt) {
            int c0 = wn * 32 + nt * 8 + 2 * (lane & 3);
            if (gr1 >= 0) {
                __half2 hv = __floats2half2_rn(acc[mt][nt][0], acc[mt][nt][1]);
                *(__half2*)(h + (size_t)gr1 * DIM + c0) = hv;
            }
            if (gr2 >= 0) {
                __half2 hv = __floats2half2_rn(acc[mt][nt][2], acc[mt][nt][3]);
                *(__half2*)(h + (size_t)gr2 * DIM + c0) = hv;
            }
            ps[mt * 2 + 0] += acc[mt][nt][0] * asv[nt][0] + acc[mt][nt][1] * asv[nt][1];
            ps[mt * 2 + 1] += acc[mt][nt][2] * asv[nt][0] + acc[mt][nt][3] * asv[nt][1];
            pd[mt * 2 + 0] += acc[mt][nt][0] * adv[nt][0] + acc[mt][nt][1] * adv[nt][1];
            pd[mt * 2 + 1] += acc[mt][nt][2] * adv[nt][0] + acc[mt][nt][3] * adv[nt][1];
        }
    }
#pragma unroll
    for (int q = 0; q < 8; ++q) {
        ps[q] += __shfl_xor_sync(0xFFFFFFFF, ps[q], 1);
        ps[q] += __shfl_xor_sync(0xFFFFFFFF, ps[q], 2);
        pd[q] += __shfl_xor_sync(0xFFFFFFFF, pd[q], 1);
        pd[q] += __shfl_xor_sync(0xFFFFFFFF, pd[q], 2);
    }
    __syncthreads();
    if ((lane & 3) == 0) {
#pragma unroll
        for (int mt = 0; mt < 4; ++mt) {
            int rl0 = wm * 64 + mt * 16 + (lane >> 2);
            red_s[rl0 * 4 + wn] = ps[mt * 2 + 0];
            red_s[(rl0 + 8) * 4 + wn] = ps[mt * 2 + 1];
            red_d[rl0 * 4 + wn] = pd[mt * 2 + 0];
            red_d[(rl0 + 8) * 4 + wn] = pd[mt * 2 + 1];
        }
    }
    __syncthreads();
    if (tid < 128) {
        int li = r0 + tid;
        if (li < count) {
            int row = IDX ? g.rows[li] : li;
            float s = red_s[tid * 4] + red_s[tid * 4 + 1] + red_s[tid * 4 + 2] + red_s[tid * 4 + 3];
            float d = red_d[tid * 4] + red_d[tid * 4 + 1] + red_d[tid * 4 + 2] + red_d[tid * 4 + 3];
            g.ssrc[row] = s;
            g.sdst[row] = d;
        }
    }
}

// ---------------- shared agg core (one warp, one dst node) ---------------------
struct AggView {
    const int* off;
    const int2* ced;
    const float *ssrc, *sdst;
    const __half* h;
};

__device__ __forceinline__ float4 agg_node(const AggView& a, int d, int lane)
{
    const int o0 = a.off[d], o1 = a.off[d + 1];
    const float sd = a.sdst[d];
    const __half* __restrict__ h = a.h;

    float4 acc = make_float4(0.f, 0.f, 0.f, 0.f);
    float denom = 0.f;

    for (int base = o0; base < o1; base += 32) {
        int idx = base + lane;
        float e = 0.f;
        int s = 0;
        if (idx < o1) {
            int2 se = a.ced[idx];
            s = se.x;
            float l = a.ssrc[s] + sd;
            l = l > 0.f ? l : 0.2f * l;
            e = __expf(l) * __int_as_float(se.y);
        }
        float esum = e;
#pragma unroll
        for (int m = 16; m; m >>= 1) esum += __shfl_xor_sync(0xFFFFFFFF, esum, m);
        denom += esum;

        int cnt = min(32, o1 - base);
        int k = 0;
        for (; k + 4 <= cnt; k += 4) {
            float c0 = __shfl_sync(0xFFFFFFFF, e, k);
            float c1 = __shfl_sync(0xFFFFFFFF, e, k + 1);
            float c2 = __shfl_sync(0xFFFFFFFF, e, k + 2);
            float c3 = __shfl_sync(0xFFFFFFFF, e, k + 3);
            int s0 = __shfl_sync(0xFFFFFFFF, s, k);
            int s1 = __shfl_sync(0xFFFFFFFF, s, k + 1);
            int s2 = __shfl_sync(0xFFFFFFFF, s, k + 2);
            int s3 = __shfl_sync(0xFFFFFFFF, s, k + 3);
            float4 v0 = load_h4(h + (size_t)s0 * DIM + lane * 4);
            float4 v1 = load_h4(h + (size_t)s1 * DIM + lane * 4);
            float4 v2 = load_h4(h + (size_t)s2 * DIM + lane * 4);
            float4 v3 = load_h4(h + (size_t)s3 * DIM + lane * 4);
            acc.x += c0 * v0.x + c1 * v1.x + c2 * v2.x + c3 * v3.x;
            acc.y += c0 * v0.y + c1 * v1.y + c2 * v2.y + c3 * v3.y;
            acc.z += c0 * v0.z + c1 * v1.z + c2 * v2.z + c3 * v3.z;
            acc.w += c0 * v0.w + c1 * v1.w + c2 * v2.w + c3 * v3.w;
        }
        for (; k < cnt; ++k) {
            float coef = __shfl_sync(0xFFFFFFFF, e, k);
            int sk = __shfl_sync(0xFFFFFFFF, s, k);
            float4 v = load_h4(h + (size_t)sk * DIM + lane * 4);
            acc.x += coef * v.x; acc.y += coef * v.y;
            acc.z += coef * v.z; acc.w += coef * v.w;
        }
    }
    float inv = 1.f / (denom + 1e-16f);
    acc.x *= inv; acc.y *= inv; acc.z *= inv; acc.w *= inv;
    return acc;
}

// ---------------- layer-1 aggregate over demanded nodes (fp16 out) -------------
__global__ void agg_csr_kernel(AggView a, __half* __restrict__ out,
                               const int* __restrict__ list, const int* __restrict__ cnt)
{
    int lane = threadIdx.x & 31;
    int li = blockIdx.x * 8 + (threadIdx.x >> 5);
    if (li >= *cnt) return;
    int d = list[li];
    float4 acc = agg_node(a, d, lane);
    __half2 p0 = __floats2half2_rn(acc.x, acc.y);
    __half2 p1 = __floats2half2_rn(acc.z, acc.w);
    uint2 pk;
    pk.x = *(uint32_t*)&p0;  pk.y = *(uint32_t*)&p1;
    *(uint2*)(out + (size_t)d * DIM + lane * 4) = pk;
}

// ---------------- fused layer-2 batch aggregate + elu + output -----------------
__global__ void batch_agg_kernel(AggView au, AggView ai,
                                 const int* __restrict__ uid, const int* __restrict__ iid,
                                 float* __restrict__ out)
{
    int lane = threadIdx.x & 31;
    int b = blockIdx.x * 8 + (threadIdx.x >> 5);
    if (b >= 2 * BATCH) return;
    const bool isU = b < BATCH;
    const AggView& a = isU ? au : ai;
    int d = isU ? uid[b] : iid[b - BATCH];
    float4 acc = agg_node(a, d, lane);
    acc.x = elu_f(acc.x);  acc.y = elu_f(acc.y);
    acc.z = elu_f(acc.z);  acc.w = elu_f(acc.w);
    *(float4*)(out + (size_t)b * DIM + lane * 4) = acc;
}

// ---------------- host orchestration -------------------------------------------
extern "C" void kernel_launch(void* const* d_in, const int* in_sizes, int n_in,
                              void* d_out, int out_size)
{
    const int*   uedg = (const int*)d_in[0];
    const int*   iedg = (const int*)d_in[1];
    const int*   user_id = (const int*)d_in[2];
    const int*   item_id = (const int*)d_in[3];
    const float* uval = (const float*)d_in[4];
    const float* ival = (const float*)d_in[5];
    const float* umat = (const float*)d_in[6];
    const float* imat = (const float*)d_in[7];
    const float* W_u1 = (const float*)d_in[8];
    const float* as_u1 = (const float*)d_in[9];
    const float* ad_u1 = (const float*)d_in[10];
    const float* W_u2 = (const float*)d_in[11];
    const float* as_u2 = (const float*)d_in[12];
    const float* ad_u2 = (const float*)d_in[13];
    const float* W_i1 = (const float*)d_in[14];
    const float* as_i1 = (const float*)d_in[15];
    const float* ad_i1 = (const float*)d_in[16];
    const float* W_i2 = (const float*)d_in[17];
    const float* as_i2 = (const float*)d_in[18];
    const float* ad_i2 = (const float*)d_in[19];

    __half *h_u, *h_i, *out1_u, *out1_i;
    float *ssrc_u, *sdst_u, *ssrc_i, *sdst_i;
    uint32_t *wph, *wpl;
    int *off_u, *off_i, *list_u, *list_i, *nlist;
    int2 *ced_u, *ced_i;
    cudaGetSymbolAddress((void**)&h_u, g_h_u);
    cudaGetSymbolAddress((void**)&h_i, g_h_i);
    cudaGetSymbolAddress((void**)&out1_u, g_out1_u);
    cudaGetSymbolAddress((void**)&out1_i, g_out1_i);
    cudaGetSymbolAddress((void**)&ssrc_u, g_ssrc_u);
    cudaGetSymbolAddress((void**)&sdst_u, g_sdst_u);
    cudaGetSymbolAddress((void**)&ssrc_i, g_ssrc_i);
    cudaGetSymbolAddress((void**)&sdst_i, g_sdst_i);
    cudaGetSymbolAddress((void**)&wph, g_wp_hi);
    cudaGetSymbolAddress((void**)&wpl, g_wp_lo);
    cudaGetSymbolAddress((void**)&off_u, g_off_u);
    cudaGetSymbolAddress((void**)&off_i, g_off_i);
    cudaGetSymbolAddress((void**)&ced_u, g_ced_u);
    cudaGetSymbolAddress((void**)&ced_i, g_ced_i);
    cudaGetSymbolAddress((void**)&list_u, g_list_u);
    cudaGetSymbolAddress((void**)&list_i, g_list_i);
    cudaGetSymbolAddress((void**)&nlist, g_nlist);

    cudaFuncSetAttribute(gemm_mma_kernel<0, 0, 0>, cudaFuncAttributeMaxDynamicSharedMemorySize, SMEM_TOT);
    cudaFuncSetAttribute(gemm_mma_kernel<1, 1, 1>, cudaFuncAttributeMaxDynamicSharedMemorySize, SMEM_TOT);

    // one-time side streams + events
    static cudaStream_t s2 = nullptr, s3 = nullptr;
    static cudaEvent_t evF = nullptr, evC = nullptr, evP = nullptr, evI = nullptr;
    if (!s2) {
        cudaStreamCreateWithFlags(&s2, cudaStreamNonBlocking);
        cudaStreamCreateWithFlags(&s3, cudaStreamNonBlocking);
        cudaEventCreateWithFlags(&evF, cudaEventDisableTiming);
        cudaEventCreateWithFlags(&evC, cudaEventDisableTiming);
        cudaEventCreateWithFlags(&evP, cudaEventDisableTiming);
        cudaEventCreateWithFlags(&evI, cudaEventDisableTiming);
    }

    const int TB = 256;
    const int WSTRIDE = DIM * 64;

    // fork: CSR build + demand-set on s2, overlapped with prep + GEMM1s
    cudaEventRecord(evF, 0);
    cudaStreamWaitEvent(s2, evF, 0);

    zero_cnt_kernel<<<(NU + TB) / TB, TB, 0, s2>>>();
    count_kernel<<<(EU + TB - 1) / TB, TB, 0, s2>>>(uedg + EU, iedg + EI);
    scan_a_kernel<<<NBI_SC + NBU_SC, 1024, 0, s2>>>();
    scan_b_kernel<<<1, 128, 0, s2>>>();
    scan_c_kernel<<<(NU + TB - 1) / TB, TB, 0, s2>>>();
    scatter_kernel<<<(EU + TB - 1) / TB, TB, 0, s2>>>(uedg, uval, iedg, ival);
    mark_kernel<<<(2 * BATCH * 32) / TB, TB, 0, s2>>>(user_id, item_id);
    compact_kernel<<<(NU + TB - 1) / TB, TB, 0, s2>>>();
    cudaEventRecord(evC, s2);

    // main stream: weight prep
    prep_w_kernel<<<4 * DIM * 64 / TB, TB>>>(W_i1, W_i2, W_u1, W_u2);
    cudaEventRecord(evP, 0);

    AggView vu = { off_u, ced_u, ssrc_u, sdst_u, h_u };
    AggView vi = { off_i, ced_i, ssrc_i, sdst_i, h_i };

    // --- item chain on s3 ---
    cudaStreamWaitEvent(s3, evP, 0);
    GemmArgs gi1 = { imat, wph + 0 * WSTRIDE, wpl + 0 * WSTRIDE, as_i1, ad_i1,
                     h_i, ssrc_i, sdst_i, NI, nullptr, nullptr };
    gemm_mma_kernel<0, 0, 0><<<GB_I, 256, SMEM_TOT, s3>>>(gi1);
    cudaStreamWaitEvent(s3, evC, 0);
    agg_csr_kernel<<<AGB_I, 256, 0, s3>>>(vi, out1_i, list_i, nlist + 1);
    GemmArgs gi2 = { out1_i, wph + 1 * WSTRIDE, wpl + 1 * WSTRIDE, as_i2, ad_i2,
                     h_i, ssrc_i, sdst_i, NI, list_i, nlist + 1 };
    gemm_mma_kernel<1, 1, 1><<<GB_I, 256, SMEM_TOT, s3>>>(gi2);
    cudaEventRecord(evI, s3);

    // --- user chain on main stream ---
    GemmArgs gu1 = { umat, wph + 2 * WSTRIDE, wpl + 2 * WSTRIDE, as_u1, ad_u1,
                     h_u, ssrc_u, sdst_u, NU, nullptr, nullptr };
    gemm_mma_kernel<0, 0, 0><<<GB_U, 256, SMEM_TOT>>>(gu1);
    cudaStreamWaitEvent(0, evC, 0);
    agg_csr_kernel<<<AGB_U, 256>>>(vu, out1_u, list_u, nlist + 0);
    GemmArgs gu2 = { out1_u, wph + 3 * WSTRIDE, wpl + 3 * WSTRIDE, as_u2, ad_u2,
                     h_u, ssrc_u, sdst_u, NU, list_u, nlist + 0 };
    gemm_mma_kernel<1, 1, 1><<<GB_U, 256, SMEM_TOT>>>(gu2);

    // join item chain, then fused batch aggregate
    cudaStreamWaitEvent(0, evI, 0);
    batch_agg_kernel<<<(2 * BATCH) / 8, 256>>>(vu, vi, user_id, item_id, (float*)d_out);
}

// round 15
// speedup vs baseline: 3.2673x; 1.1410x over previous
#include <cuda_runtime.h>
#include <cuda_bf16.h>
#include <cuda_fp16.h>
#include <cstdint>
#include <cfloat>

#define NU 100000
#define NI 50000
#define DIM 128
#define EU 400000
#define EI 200000
#define BATCH 4096

#define GB_U ((NU + 127) / 128)        // 782 gemm blocks (user)
#define GB_I ((NI + 127) / 128)        // 391 gemm blocks (item)
#define NBI_SC ((NI + 1024) / 1024)    // scan blocks (item, covers N+1)
#define NBU_SC ((NU + 1024) / 1024)    // scan blocks (user, covers N+1)
#define AGB_U ((NU + 7) / 8)           // agg blocks (user)
#define AGB_I ((NI + 7) / 8)           // agg blocks (item)

// ---------------- scratch (static device memory) ------------------------------
__device__ __half g_h_u[NU * DIM];          // h fp16 (agg is sole consumer)
__device__ __half g_h_i[NI * DIM];
__device__ __half g_out1_u[NU * DIM];       // layer-1 out fp16 (GEMM2 sole consumer)
__device__ __half g_out1_i[NI * DIM];
__device__ float g_ssrc_u[NU], g_sdst_u[NU];
__device__ float g_ssrc_i[NI], g_sdst_i[NI];
__device__ uint32_t g_wp_hi[4][DIM * 64];   // W^T [n][k-pair] bf16x2, hi part
__device__ uint32_t g_wp_lo[4][DIM * 64];   // residual lo part
// CSR (demand-pruned, both graphs persist)
__device__ int   g_cnt_u[NU + 1], g_cnt_i[NI + 1];
__device__ int   g_off_u[NU + 1], g_off_i[NI + 1];
__device__ int   g_btot_u[NBU_SC], g_btot_i[NBI_SC];
__device__ int   g_work_u[NU], g_work_i[NI];
__device__ int2  g_ced_u[EU], g_ced_i[EI];  // packed (src, ev bits)
// demand sets
__device__ int   g_mark0_u[NU], g_mark0_i[NI];   // batch dsts
__device__ int   g_markD_u[NU], g_markD_i[NI];   // dsts + 1-hop srcs (layer-2 set)
__device__ int   g_markG_u[NU], g_markG_i[NI];   // 2-hop srcs (extra layer-1 rows)
__device__ int   g_list_u[NU], g_list_i[NI];     // demand (layer-2) lists
__device__ int   g_listG_u[NU], g_listG_i[NI];   // gemm1 lists
__device__ int   g_nlist[4];   // [0]=u demand, [1]=i demand, [2]=u gemm1, [3]=i gemm1

// ---------------- helpers ------------------------------------------------------
__device__ __forceinline__ float elu_f(float x) {
    return x > 0.f ? x : __expf(x) - 1.f;
}
__device__ __forceinline__ uint32_t pack_bf2(__nv_bfloat16 a, __nv_bfloat16 b) {
    return ((uint32_t)__bfloat16_as_ushort(b) << 16) | (uint32_t)__bfloat16_as_ushort(a);
}
__device__ __forceinline__ uint32_t cvt_bf2(float lo0, float lo1) {
    uint32_t r;
    asm("cvt.rn.bf16x2.f32 %0, %1, %2;" : "=r"(r) : "f"(lo1), "f"(lo0));
    return r;
}
__device__ __forceinline__ void mma_bf16(float* d, const uint32_t* a, const uint32_t* b) {
    asm volatile(
        "mma.sync.aligned.m16n8k16.row.col.f32.bf16.bf16.f32 "
        "{%0,%1,%2,%3}, {%4,%5,%6,%7}, {%8,%9}, {%0,%1,%2,%3};"
        : "+f"(d[0]), "+f"(d[1]), "+f"(d[2]), "+f"(d[3])
        : "r"(a[0]), "r"(a[1]), "r"(a[2]), "r"(a[3]), "r"(b[0]), "r"(b[1]));
}
__device__ __forceinline__ float4 load_h4(const __half* p) {
    uint2 raw = *(const uint2*)p;
    float2 f0 = __half22float2(*(__half2*)&raw.x);
    float2 f1 = __half22float2(*(__half2*)&raw.y);
    return make_float4(f0.x, f0.y, f1.x, f1.y);
}

// ---------------- W^T hi/lo prep (bf16 split, packed pairs) --------------------
__global__ void prep_w_kernel(const float* __restrict__ w0, const float* __restrict__ w1,
                              const float* __restrict__ w2, const float* __restrict__ w3) {
    int i = blockIdx.x * blockDim.x + threadIdx.x;     // 4*128*64
    int l = i >> 13;
    int j = i & 8191;
    int n = j >> 6, kk = j & 63;
    const float* W = (l == 0) ? w0 : (l == 1) ? w1 : (l == 2) ? w2 : w3;
    float a = W[(2 * kk) * DIM + n];
    float b = W[(2 * kk + 1) * DIM + n];
    __nv_bfloat16 ha = __float2bfloat16(a);
    __nv_bfloat16 hb = __float2bfloat16(b);
    __nv_bfloat16 la = __float2bfloat16(a - __bfloat162float(ha));
    __nv_bfloat16 lb = __float2bfloat16(b - __bfloat162float(hb));
    g_wp_hi[l][n * 64 + kk] = pack_bf2(ha, hb);
    g_wp_lo[l][n * 64 + kk] = pack_bf2(la, lb);
}

// ---------------- demand marking (no CSR needed) -------------------------------
__global__ void zero_all_kernel() {
    int i = blockIdx.x * blockDim.x + threadIdx.x;
    if (i <= NU) g_cnt_u[i] = 0;
    if (i <= NI) g_cnt_i[i] = 0;
    if (i < NU) { g_mark0_u[i] = 0; g_markD_u[i] = 0; g_markG_u[i] = 0; }
    if (i < NI) { g_mark0_i[i] = 0; g_markD_i[i] = 0; g_markG_i[i] = 0; }
    if (i < 4) g_nlist[i] = 0;
}
__global__ void mark0_kernel(const int* __restrict__ uid, const int* __restrict__ iid) {
    int i = blockIdx.x * blockDim.x + threadIdx.x;
    if (i < BATCH)               { int d = uid[i];         g_mark0_u[d] = 1; g_markD_u[d] = 1; }
    else if (i < 2 * BATCH)      { int d = iid[i - BATCH]; g_mark0_i[d] = 1; g_markD_i[d] = 1; }
}
__global__ void markE1_kernel(const int* __restrict__ uedg, const int* __restrict__ iedg) {
    int e = blockIdx.x * blockDim.x + threadIdx.x;
    if (e < EU) { if (g_mark0_u[uedg[EU + e]]) g_markD_u[uedg[e]] = 1; }
    if (e < EI) { if (g_mark0_i[iedg[EI + e]]) g_markD_i[iedg[e]] = 1; }
}
__global__ void markE2_kernel(const int* __restrict__ uedg, const int* __restrict__ iedg) {
    int e = blockIdx.x * blockDim.x + threadIdx.x;
    if (e < EU) { if (g_markD_u[uedg[EU + e]]) g_markG_u[uedg[e]] = 1; }
    if (e < EI) { if (g_markD_i[iedg[EI + e]]) g_markG_i[iedg[e]] = 1; }
}
__global__ void compact_kernel() {
    int i = blockIdx.x * blockDim.x + threadIdx.x;
    if (i < NU) {
        if (g_markD_u[i]) { int p = atomicAdd(&g_nlist[0], 1); g_list_u[p] = i; }
        if (g_markD_u[i] | g_markG_u[i]) { int p = atomicAdd(&g_nlist[2], 1); g_listG_u[p] = i; }
    }
    if (i < NI) {
        if (g_markD_i[i]) { int p = atomicAdd(&g_nlist[1], 1); g_list_i[p] = i; }
        if (g_markD_i[i] | g_markG_i[i]) { int p = atomicAdd(&g_nlist[3], 1); g_listG_i[p] = i; }
    }
}

// ---------------- pruned CSR build --------------------------------------------
__global__ void count_kernel(const int* __restrict__ udst, const int* __restrict__ idst) {
    int e = blockIdx.x * blockDim.x + threadIdx.x;
    if (e < EU) { int d = udst[e]; if (g_markD_u[d]) atomicAdd(&g_cnt_u[d], 1); }
    if (e < EI) { int d = idst[e]; if (g_markD_i[d]) atomicAdd(&g_cnt_i[d], 1); }
}
__global__ void __launch_bounds__(1024) scan_a_kernel() {
    __shared__ int sm[1024];
    int t = threadIdx.x;
    int b = blockIdx.x;
    const int* cnt;  int* offs;  int* btot;  int N;  int lb;
    if (b < NBI_SC) { cnt = g_cnt_i; offs = g_off_i; btot = g_btot_i; N = NI; lb = b; }
    else            { cnt = g_cnt_u; offs = g_off_u; btot = g_btot_u; N = NU; lb = b - NBI_SC; }
    int i = lb * 1024 + t;
    int v = (i < N) ? cnt[i] : 0;
    sm[t] = v;
    __syncthreads();
#pragma unroll
    for (int s = 1; s < 1024; s <<= 1) {
        int u = (t >= s) ? sm[t - s] : 0;
        __syncthreads();
        sm[t] += u;
        __syncthreads();
    }
    if (i <= N) offs[i] = sm[t] - v;
    if (t == 1023) btot[lb] = sm[1023];
}
__global__ void __launch_bounds__(128) scan_b_kernel() {
    __shared__ int sm[128];
    int t = threadIdx.x;
    int v = (t < NBI_SC) ? g_btot_i[t] : 0;
    sm[t] = v;
    __syncthreads();
#pragma unroll
    for (int s = 1; s < 128; s <<= 1) {
        int u = (t >= s) ? sm[t - s] : 0;
        __syncthreads();
        sm[t] += u;
        __syncthreads();
    }
    if (t < NBI_SC) g_btot_i[t] = sm[t] - v;
    __syncthreads();
    v = (t < NBU_SC) ? g_btot_u[t] : 0;
    sm[t] = v;
    __syncthreads();
#pragma unroll
    for (int s = 1; s < 128; s <<= 1) {
        int u = (t >= s) ? sm[t - s] : 0;
        __syncthreads();
        sm[t] += u;
        __syncthreads();
    }
    if (t < NBU_SC) g_btot_u[t] = sm[t] - v;
}
__global__ void scan_c_kernel() {
    int i = blockIdx.x * blockDim.x + threadIdx.x;
    if (i <= NI) {
        int o = g_off_i[i] + g_btot_i[i >> 10];
        g_off_i[i] = o;
        if (i < NI) g_work_i[i] = o;
    }
    if (i <= NU) {
        int o = g_off_u[i] + g_btot_u[i >> 10];
        g_off_u[i] = o;
        if (i < NU) g_work_u[i] = o;
    }
}
__global__ void scatter_kernel(const int* __restrict__ uedg, const float* __restrict__ uev,
                               const int* __restrict__ iedg, const float* __restrict__ iev) {
    int e = blockIdx.x * blockDim.x + threadIdx.x;
    if (e < EU) {
        int d = uedg[EU + e];
        if (g_markD_u[d]) {
            int p = atomicAdd(&g_work_u[d], 1);
            g_ced_u[p] = make_int2(uedg[e], __float_as_int(uev[e]));
        }
    }
    if (e < EI) {
        int d = iedg[EI + e];
        if (g_markD_i[d]) {
            int p = atomicAdd(&g_work_i[d], 1);
            g_ced_i[p] = make_int2(iedg[e], __float_as_int(iev[e]));
        }
    }
}

// ---------------- BF16 3-term HMMA GEMM + attention scalars (per-graph) --------
struct GemmArgs {
    const void* x;                 // fp32 (layer1) or fp16 (layer2)
    const uint32_t *wh, *wl;
    const float *as, *ad;
    __half* h;
    float *ssrc, *sdst;
    int N;
    const int* rows;               // IDX mode: compacted row list
    const int* cnt;                // IDX mode: list length (device)
};

// smem (bytes): B hi/lo [128n][68 u32], A hi/lo [128r][68 u32], red buf
#define SB_BH   0
#define SB_BL   34816
#define SB_AH   69632
#define SB_AL   104448
#define SB_RED  139264
#define SMEM_TOT 143360

template <int ACT, int INH, int IDX>
__global__ void __launch_bounds__(256, 1) gemm_mma_kernel(GemmArgs g)
{
    extern __shared__ char smem[];
    uint32_t* Bh = (uint32_t*)(smem + SB_BH);
    uint32_t* Bl = (uint32_t*)(smem + SB_BL);
    uint32_t* Ah = (uint32_t*)(smem + SB_AH);
    uint32_t* Al = (uint32_t*)(smem + SB_AL);
    float* red_s = (float*)(smem + SB_RED);
    float* red_d = red_s + 128 * 4;

    const int count = IDX ? *g.cnt : g.N;
    const int r0 = blockIdx.x * 128;
    if (r0 >= count) return;

    const int tid = threadIdx.x;
    const int lane = tid & 31;
    const int wid = tid >> 5;
    const int wm = wid & 1;
    const int wn = wid >> 1;

    // stage B (both hi and lo), uint4 copies into stride-68 layout
    for (int i = tid; i < 2048; i += 256) {
        int n = i >> 4, k4 = (i & 15) * 4;
        *(uint4*)&Bh[n * 68 + k4] = *(const uint4*)&g.wh[n * 64 + k4];
        *(uint4*)&Bl[n * 68 + k4] = *(const uint4*)&g.wl[n * 64 + k4];
    }

    // stage full A tile (128 rows x 128 k): ELU + truncation-based bf16 split
    {
        const int r = tid >> 1;
        const int half = tid & 1;
        const int li = r0 + r;
        const int gr = (li < count) ? (IDX ? g.rows[li] : li) : -1;
        const size_t roff = (size_t)(gr < 0 ? 0 : gr) * DIM + half * 64;
        const float* xf = (const float*)g.x + roff;
        const __half* xh = (const __half*)g.x + roff;
#pragma unroll
        for (int q = 0; q < 16; ++q) {
            float4 v = make_float4(0.f, 0.f, 0.f, 0.f);
            if (gr >= 0) v = INH ? load_h4(xh + q * 4) : *(const float4*)(xf + q * 4);
            if (ACT) { v.x = elu_f(v.x); v.y = elu_f(v.y); v.z = elu_f(v.z); v.w = elu_f(v.w); }
            uint32_t ix = __float_as_uint(v.x), iy = __float_as_uint(v.y);
            uint32_t iz = __float_as_uint(v.z), iw = __float_as_uint(v.w);
            uint32_t hi01 = __byte_perm(ix, iy, 0x7632);
            uint32_t hi23 = __byte_perm(iz, iw, 0x7632);
            float l0 = v.x - __uint_as_float(ix & 0xFFFF0000u);
            float l1 = v.y - __uint_as_float(iy & 0xFFFF0000u);
            float l2 = v.z - __uint_as_float(iz & 0xFFFF0000u);
            float l3 = v.w - __uint_as_float(iw & 0xFFFF0000u);
            int o = r * 68 + half * 32 + q * 2;
            Ah[o] = hi01;  Ah[o + 1] = hi23;
            Al[o] = cvt_bf2(l0, l1);  Al[o + 1] = cvt_bf2(l2, l3);
        }
    }
    __syncthreads();

    float acc[4][4][4];
#pragma unroll
    for (int mt = 0; mt < 4; ++mt)
#pragma unroll
        for (int nt = 0; nt < 4; ++nt)
#pragma unroll
            for (int q = 0; q < 4; ++q) acc[mt][nt][q] = 0.f;

#pragma unroll
    for (int ks = 0; ks < 8; ++ks) {
        const int kk0 = ks * 8;
        uint32_t bh[4][2], bl[4][2];
#pragma unroll
        for (int nt = 0; nt < 4; ++nt) {
            int bn = wn * 32 + nt * 8 + (lane >> 2);
            bh[nt][0] = Bh[bn * 68 + kk0 + (lane & 3)];
            bh[nt][1] = Bh[bn * 68 + kk0 + 4 + (lane & 3)];
            bl[nt][0] = Bl[bn * 68 + kk0 + (lane & 3)];
            bl[nt][1] = Bl[bn * 68 + kk0 + 4 + (lane & 3)];
        }
        uint32_t ah[4][4], al[4][4];
#pragma unroll
        for (int mt = 0; mt < 4; ++mt) {
            int ar = wm * 64 + mt * 16 + (lane >> 2);
            ah[mt][0] = Ah[ar * 68 + kk0 + (lane & 3)];
            ah[mt][1] = Ah[(ar + 8) * 68 + kk0 + (lane & 3)];
            ah[mt][2] = Ah[ar * 68 + kk0 + 4 + (lane & 3)];
            ah[mt][3] = Ah[(ar + 8) * 68 + kk0 + 4 + (lane & 3)];
            al[mt][0] = Al[ar * 68 + kk0 + (lane & 3)];
            al[mt][1] = Al[(ar + 8) * 68 + kk0 + (lane & 3)];
            al[mt][2] = Al[ar * 68 + kk0 + 4 + (lane & 3)];
            al[mt][3] = Al[(ar + 8) * 68 + kk0 + 4 + (lane & 3)];
        }
#pragma unroll
        for (int mt = 0; mt < 4; ++mt)
#pragma unroll
            for (int nt = 0; nt < 4; ++nt) {
                mma_bf16(acc[mt][nt], ah[mt], bh[nt]);
                mma_bf16(acc[mt][nt], ah[mt], bl[nt]);
                mma_bf16(acc[mt][nt], al[mt], bh[nt]);
            }
    }

    // ---------------- epilogue: store h (fp16) + attention scalar dots ---------
    float asv[4][2], adv[4][2];
#pragma unroll
    for (int nt = 0; nt < 4; ++nt) {
        int c0 = wn * 32 + nt * 8 + 2 * (lane & 3);
        asv[nt][0] = g.as[c0];   asv[nt][1] = g.as[c0 + 1];
        adv[nt][0] = g.ad[c0];   adv[nt][1] = g.ad[c0 + 1];
    }

    float ps[8], pd[8];
#pragma unroll
    for (int q = 0; q < 8; ++q) { ps[q] = 0.f; pd[q] = 0.f; }

    __half* __restrict__ h = g.h;
#pragma unroll
    for (int mt = 0; mt < 4; ++mt) {
        int li = r0 + wm * 64 + mt * 16 + (lane >> 2);
        int gr1 = (li < count) ? (IDX ? g.rows[li] : li) : -1;
        int gr2 = (li + 8 < count) ? (IDX ? g.rows[li + 8] : li + 8) : -1;
#pragma unroll
        for (int nt = 0; nt < 4; ++nt) {
            int c0 = wn * 32 + nt * 8 + 2 * (lane & 3);
            if (gr1 >= 0) {
                __half2 hv = __floats2half2_rn(acc[mt][nt][0], acc[mt][nt][1]);
                *(__half2*)(h + (size_t)gr1 * DIM + c0) = hv;
            }
            if (gr2 >= 0) {
                __half2 hv = __floats2half2_rn(acc[mt][nt][2], acc[mt][nt][3]);
                *(__half2*)(h + (size_t)gr2 * DIM + c0) = hv;
            }
            ps[mt * 2 + 0] += acc[mt][nt][0] * asv[nt][0] + acc[mt][nt][1] * asv[nt][1];
            ps[mt * 2 + 1] += acc[mt][nt][2] * asv[nt][0] + acc[mt][nt][3] * asv[nt][1];
            pd[mt * 2 + 0] += acc[mt][nt][0] * adv[nt][0] + acc[mt][nt][1] * adv[nt][1];
            pd[mt * 2 + 1] += acc[mt][nt][2] * adv[nt][0] + acc[mt][nt][3] * adv[nt][1];
        }
    }
#pragma unroll
    for (int q = 0; q < 8; ++q) {
        ps[q] += __shfl_xor_sync(0xFFFFFFFF, ps[q], 1);
        ps[q] += __shfl_xor_sync(0xFFFFFFFF, ps[q], 2);
        pd[q] += __shfl_xor_sync(0xFFFFFFFF, pd[q], 1);
        pd[q] += __shfl_xor_sync(0xFFFFFFFF, pd[q], 2);
    }
    __syncthreads();
    if ((lane & 3) == 0) {
#pragma unroll
        for (int mt = 0; mt < 4; ++mt) {
            int rl0 = wm * 64 + mt * 16 + (lane >> 2);
            red_s[rl0 * 4 + wn] = ps[mt * 2 + 0];
            red_s[(rl0 + 8) * 4 + wn] = ps[mt * 2 + 1];
            red_d[rl0 * 4 + wn] = pd[mt * 2 + 0];
            red_d[(rl0 + 8) * 4 + wn] = pd[mt * 2 + 1];
        }
    }
    __syncthreads();
    if (tid < 128) {
        int li = r0 + tid;
        if (li < count) {
            int row = IDX ? g.rows[li] : li;
            float s = red_s[tid * 4] + red_s[tid * 4 + 1] + red_s[tid * 4 + 2] + red_s[tid * 4 + 3];
            float d = red_d[tid * 4] + red_d[tid * 4 + 1] + red_d[tid * 4 + 2] + red_d[tid * 4 + 3];
            g.ssrc[row] = s;
            g.sdst[row] = d;
        }
    }
}

// ---------------- shared agg core (one warp, one dst node) ---------------------
struct AggView {
    const int* off;
    const int2* ced;
    const float *ssrc, *sdst;
    const __half* h;
};

__device__ __forceinline__ float4 agg_node(const AggView& a, int d, int lane)
{
    const int o0 = a.off[d], o1 = a.off[d + 1];
    const float sd = a.sdst[d];
    const __half* __restrict__ h = a.h;

    float4 acc = make_float4(0.f, 0.f, 0.f, 0.f);
    float denom = 0.f;

    for (int base = o0; base < o1; base += 32) {
        int idx = base + lane;
        float e = 0.f;
        int s = 0;
        if (idx < o1) {
            int2 se = a.ced[idx];
            s = se.x;
            float l = a.ssrc[s] + sd;
            l = l > 0.f ? l : 0.2f * l;
            e = __expf(l) * __int_as_float(se.y);
        }
        float esum = e;
#pragma unroll
        for (int m = 16; m; m >>= 1) esum += __shfl_xor_sync(0xFFFFFFFF, esum, m);
        denom += esum;

        int cnt = min(32, o1 - base);
        int k = 0;
        for (; k + 4 <= cnt; k += 4) {
            float c0 = __shfl_sync(0xFFFFFFFF, e, k);
            float c1 = __shfl_sync(0xFFFFFFFF, e, k + 1);
            float c2 = __shfl_sync(0xFFFFFFFF, e, k + 2);
            float c3 = __shfl_sync(0xFFFFFFFF, e, k + 3);
            int s0 = __shfl_sync(0xFFFFFFFF, s, k);
            int s1 = __shfl_sync(0xFFFFFFFF, s, k + 1);
            int s2 = __shfl_sync(0xFFFFFFFF, s, k + 2);
            int s3 = __shfl_sync(0xFFFFFFFF, s, k + 3);
            float4 v0 = load_h4(h + (size_t)s0 * DIM + lane * 4);
            float4 v1 = load_h4(h + (size_t)s1 * DIM + lane * 4);
            float4 v2 = load_h4(h + (size_t)s2 * DIM + lane * 4);
            float4 v3 = load_h4(h + (size_t)s3 * DIM + lane * 4);
            acc.x += c0 * v0.x + c1 * v1.x + c2 * v2.x + c3 * v3.x;
            acc.y += c0 * v0.y + c1 * v1.y + c2 * v2.y + c3 * v3.y;
            acc.z += c0 * v0.z + c1 * v1.z + c2 * v2.z + c3 * v3.z;
            acc.w += c0 * v0.w + c1 * v1.w + c2 * v2.w + c3 * v3.w;
        }
        for (; k < cnt; ++k) {
            float coef = __shfl_sync(0xFFFFFFFF, e, k);
            int sk = __shfl_sync(0xFFFFFFFF, s, k);
            float4 v = load_h4(h + (size_t)sk * DIM + lane * 4);
            acc.x += coef * v.x; acc.y += coef * v.y;
            acc.z += coef * v.z; acc.w += coef * v.w;
        }
    }
    float inv = 1.f / (denom + 1e-16f);
    acc.x *= inv; acc.y *= inv; acc.z *= inv; acc.w *= inv;
    return acc;
}

// ---------------- layer-1 aggregate over demanded nodes (fp16 out) -------------
__global__ void agg_csr_kernel(AggView a, __half* __restrict__ out,
                               const int* __restrict__ list, const int* __restrict__ cnt)
{
    int lane = threadIdx.x & 31;
    int li = blockIdx.x * 8 + (threadIdx.x >> 5);
    if (li >= *cnt) return;
    int d = list[li];
    float4 acc = agg_node(a, d, lane);
    __half2 p0 = __floats2half2_rn(acc.x, acc.y);
    __half2 p1 = __floats2half2_rn(acc.z, acc.w);
    uint2 pk;
    pk.x = *(uint32_t*)&p0;  pk.y = *(uint32_t*)&p1;
    *(uint2*)(out + (size_t)d * DIM + lane * 4) = pk;
}

// ---------------- fused layer-2 batch aggregate + elu + output -----------------
__global__ void batch_agg_kernel(AggView au, AggView ai,
                                 const int* __restrict__ uid, const int* __restrict__ iid,
                                 float* __restrict__ out)
{
    int lane = threadIdx.x & 31;
    int b = blockIdx.x * 8 + (threadIdx.x >> 5);
    if (b >= 2 * BATCH) return;
    const bool isU = b < BATCH;
    const AggView& a = isU ? au : ai;
    int d = isU ? uid[b] : iid[b - BATCH];
    float4 acc = agg_node(a, d, lane);
    acc.x = elu_f(acc.x);  acc.y = elu_f(acc.y);
    acc.z = elu_f(acc.z);  acc.w = elu_f(acc.w);
    *(float4*)(out + (size_t)b * DIM + lane * 4) = acc;
}

// ---------------- host orchestration -------------------------------------------
extern "C" void kernel_launch(void* const* d_in, const int* in_sizes, int n_in,
                              void* d_out, int out_size)
{
    const int*   uedg = (const int*)d_in[0];
    const int*   iedg = (const int*)d_in[1];
    const int*   user_id = (const int*)d_in[2];
    const int*   item_id = (const int*)d_in[3];
    const float* uval = (const float*)d_in[4];
    const float* ival = (const float*)d_in[5];
    const float* umat = (const float*)d_in[6];
    const float* imat = (const float*)d_in[7];
    const float* W_u1 = (const float*)d_in[8];
    const float* as_u1 = (const float*)d_in[9];
    const float* ad_u1 = (const float*)d_in[10];
    const float* W_u2 = (const float*)d_in[11];
    const float* as_u2 = (const float*)d_in[12];
    const float* ad_u2 = (const float*)d_in[13];
    const float* W_i1 = (const float*)d_in[14];
    const float* as_i1 = (const float*)d_in[15];
    const float* ad_i1 = (const float*)d_in[16];
    const float* W_i2 = (const float*)d_in[17];
    const float* as_i2 = (const float*)d_in[18];
    const float* ad_i2 = (const float*)d_in[19];

    __half *h_u, *h_i, *out1_u, *out1_i;
    float *ssrc_u, *sdst_u, *ssrc_i, *sdst_i;
    uint32_t *wph, *wpl;
    int *off_u, *off_i, *list_u, *list_i, *listG_u, *listG_i, *nlist;
    int2 *ced_u, *ced_i;
    cudaGetSymbolAddress((void**)&h_u, g_h_u);
    cudaGetSymbolAddress((void**)&h_i, g_h_i);
    cudaGetSymbolAddress((void**)&out1_u, g_out1_u);
    cudaGetSymbolAddress((void**)&out1_i, g_out1_i);
    cudaGetSymbolAddress((void**)&ssrc_u, g_ssrc_u);
    cudaGetSymbolAddress((void**)&sdst_u, g_sdst_u);
    cudaGetSymbolAddress((void**)&ssrc_i, g_ssrc_i);
    cudaGetSymbolAddress((void**)&sdst_i, g_sdst_i);
    cudaGetSymbolAddress((void**)&wph, g_wp_hi);
    cudaGetSymbolAddress((void**)&wpl, g_wp_lo);
    cudaGetSymbolAddress((void**)&off_u, g_off_u);
    cudaGetSymbolAddress((void**)&off_i, g_off_i);
    cudaGetSymbolAddress((void**)&ced_u, g_ced_u);
    cudaGetSymbolAddress((void**)&ced_i, g_ced_i);
    cudaGetSymbolAddress((void**)&list_u, g_list_u);
    cudaGetSymbolAddress((void**)&list_i, g_list_i);
    cudaGetSymbolAddress((void**)&listG_u, g_listG_u);
    cudaGetSymbolAddress((void**)&listG_i, g_listG_i);
    cudaGetSymbolAddress((void**)&nlist, g_nlist);

    cudaFuncSetAttribute(gemm_mma_kernel<0, 0, 1>, cudaFuncAttributeMaxDynamicSharedMemorySize, SMEM_TOT);
    cudaFuncSetAttribute(gemm_mma_kernel<1, 1, 1>, cudaFuncAttributeMaxDynamicSharedMemorySize, SMEM_TOT);

    // one-time side streams + events
    static cudaStream_t s2 = nullptr, s3 = nullptr;
    static cudaEvent_t evF = nullptr, evM = nullptr, evC = nullptr, evP = nullptr, evI = nullptr;
    if (!s2) {
        cudaStreamCreateWithFlags(&s2, cudaStreamNonBlocking);
        cudaStreamCreateWithFlags(&s3, cudaStreamNonBlocking);
        cudaEventCreateWithFlags(&evF, cudaEventDisableTiming);
        cudaEventCreateWithFlags(&evM, cudaEventDisableTiming);
        cudaEventCreateWithFlags(&evC, cudaEventDisableTiming);
        cudaEventCreateWithFlags(&evP, cudaEventDisableTiming);
        cudaEventCreateWithFlags(&evI, cudaEventDisableTiming);
    }

    const int TB = 256;
    const int WSTRIDE = DIM * 64;

    // fork: mark chain then pruned CSR on s2
    cudaEventRecord(evF, 0);
    cudaStreamWaitEvent(s2, evF, 0);

    zero_all_kernel<<<(NU + TB) / TB, TB, 0, s2>>>();
    mark0_kernel<<<(2 * BATCH + TB - 1) / TB, TB, 0, s2>>>(user_id, item_id);
    markE1_kernel<<<(EU + TB - 1) / TB, TB, 0, s2>>>(uedg, iedg);
    markE2_kernel<<<(EU + TB - 1) / TB, TB, 0, s2>>>(uedg, iedg);
    compact_kernel<<<(NU + TB - 1) / TB, TB, 0, s2>>>();
    cudaEventRecord(evM, s2);
    count_kernel<<<(EU + TB - 1) / TB, TB, 0, s2>>>(uedg + EU, iedg + EI);
    scan_a_kernel<<<NBI_SC + NBU_SC, 1024, 0, s2>>>();
    scan_b_kernel<<<1, 128, 0, s2>>>();
    scan_c_kernel<<<(NU + TB) / TB, TB, 0, s2>>>();
    scatter_kernel<<<(EU + TB - 1) / TB, TB, 0, s2>>>(uedg, uval, iedg, ival);
    cudaEventRecord(evC, s2);

    // main stream: weight prep
    prep_w_kernel<<<4 * DIM * 64 / TB, TB>>>(W_i1, W_i2, W_u1, W_u2);
    cudaEventRecord(evP, 0);

    AggView vu = { off_u, ced_u, ssrc_u, sdst_u, h_u };
    AggView vi = { off_i, ced_i, ssrc_i, sdst_i, h_i };

    // --- item chain on s3 ---
    cudaStreamWaitEvent(s3, evP, 0);
    cudaStreamWaitEvent(s3, evM, 0);
    GemmArgs gi1 = { imat, wph + 0 * WSTRIDE, wpl + 0 * WSTRIDE, as_i1, ad_i1,
                     h_i, ssrc_i, sdst_i, NI, listG_i, nlist + 3 };
    gemm_mma_kernel<0, 0, 1><<<GB_I, 256, SMEM_TOT, s3>>>(gi1);
    cudaStreamWaitEvent(s3, evC, 0);
    agg_csr_kernel<<<AGB_I, 256, 0, s3>>>(vi, out1_i, list_i, nlist + 1);
    GemmArgs gi2 = { out1_i, wph + 1 * WSTRIDE, wpl + 1 * WSTRIDE, as_i2, ad_i2,
                     h_i, ssrc_i, sdst_i, NI, list_i, nlist + 1 };
    gemm_mma_kernel<1, 1, 1><<<GB_I, 256, SMEM_TOT, s3>>>(gi2);
    cudaEventRecord(evI, s3);

    // --- user chain on main stream ---
    cudaStreamWaitEvent(0, evM, 0);
    GemmArgs gu1 = { umat, wph + 2 * WSTRIDE, wpl + 2 * WSTRIDE, as_u1, ad_u1,
                     h_u, ssrc_u, sdst_u, NU, listG_u, nlist + 2 };
    gemm_mma_kernel<0, 0, 1><<<GB_U, 256, SMEM_TOT>>>(gu1);
    cudaStreamWaitEvent(0, evC, 0);
    agg_csr_kernel<<<AGB_U, 256>>>(vu, out1_u, list_u, nlist + 0);
    GemmArgs gu2 = { out1_u, wph + 3 * WSTRIDE, wpl + 3 * WSTRIDE, as_u2, ad_u2,
                     h_u, ssrc_u, sdst_u, NU, list_u, nlist + 0 };
    gemm_mma_kernel<1, 1, 1><<<GB_U, 256, SMEM_TOT>>>(gu2);

    // join item chain, then fused batch aggregate
    cudaStreamWaitEvent(0, evI, 0);
    batch_agg_kernel<<<(2 * BATCH) / 8, 256>>>(vu, vi, user_id, item_id, (float*)d_out);
}